// round 2
// baseline (speedup 1.0000x reference)
#include <cuda_runtime.h>
#include <math.h>

#define BATCH 8
#define HEADS 8
#define DIM 512
#define SEQ 197
#define NPATCH 196
#define PK 768
#define CDIM 64
#define TDIM 1576
#define NCLS 1000

// ---------------- scratch (device globals; no runtime allocation) ----------------
__device__ float g_patches[BATCH*NPATCH*PK];      // 4.8 MB
__device__ float g_xp[BATCH*NPATCH*DIM];          // 3.2 MB
__device__ float g_x[BATCH*SEQ*DIM];              // 3.2 MB
__device__ float g_q[BATCH*HEADS*SEQ*DIM];        // 25.8 MB
__device__ float g_k[BATCH*HEADS*SEQ*DIM];
__device__ float g_v[BATCH*HEADS*SEQ*DIM];
__device__ float g_sc[BATCH*HEADS*SEQ*SEQ];       // 9.9 MB
__device__ float g_o[BATCH*HEADS*SEQ*DIM];
__device__ float g_ot[BATCH*SEQ*HEADS*DIM];
__device__ float g_y[BATCH*CDIM*TDIM];
__device__ float g_tq[BATCH*CDIM*TDIM];
__device__ float g_tk[BATCH*CDIM*TDIM];
__device__ float g_tv[BATCH*CDIM*TDIM];
__device__ float g_ts[BATCH*CDIM*CDIM];
__device__ float g_fac[BATCH];
__device__ float g_cls[BATCH*DIM];

// ---------------- generic batched tiled fp32 GEMM ----------------
// C[z] = alpha * A[(z>>aShift)] @ op(B[(z>>bShift)&bMask]) (+ bias) (+ Cin[z])
template<int BM,int BN,int BK,int TM,int TN>
__global__ __launch_bounds__((BM/TM)*(BN/TN))
void sgemm_kernel(
    const float* __restrict__ A, const float* __restrict__ B,
    const float* __restrict__ bias,
    const float* __restrict__ Cin, float* __restrict__ C,
    int M, int N, int K, int lda, int ldb, int ldc,
    long long sA, int aShift,
    long long sB, int bShift, int bMask,
    long long sCin, long long sC,
    int transB, float alpha, int addC)
{
    constexpr int THREADS = (BM/TM)*(BN/TN);
    __shared__ float As[BK][BM+4];
    __shared__ float Bs[BK][BN+4];

    int z = blockIdx.z;
    A += (long long)(z >> aShift) * sA;
    B += (long long)((z >> bShift) & bMask) * sB;
    C += (long long)z * sC;
    const float* Cr = addC ? (Cin + (long long)z * sCin) : (const float*)0;

    int row0 = blockIdx.y * BM;
    int col0 = blockIdx.x * BN;
    int tid = threadIdx.x;
    int tx = tid % (BN/TN);
    int ty = tid / (BN/TN);

    float acc[TM][TN];
    #pragma unroll
    for (int i = 0; i < TM; i++)
        #pragma unroll
        for (int j = 0; j < TN; j++)
            acc[i][j] = 0.f;

    for (int k0 = 0; k0 < K; k0 += BK) {
        // load A tile (BM x BK), stored transposed in smem
        for (int e = tid; e < BM*BK; e += THREADS) {
            int kk = e % BK, mm = e / BK;
            int gm = row0 + mm, gk = k0 + kk;
            As[kk][mm] = (gm < M && gk < K) ? A[(long long)gm*lda + gk] : 0.f;
        }
        // load B tile (BK x BN)
        if (!transB) {
            for (int e = tid; e < BK*BN; e += THREADS) {
                int nn = e % BN, kk = e / BN;
                int gk = k0 + kk, gn = col0 + nn;
                Bs[kk][nn] = (gk < K && gn < N) ? B[(long long)gk*ldb + gn] : 0.f;
            }
        } else {
            for (int e = tid; e < BK*BN; e += THREADS) {
                int kk = e % BK, nn = e / BK;
                int gk = k0 + kk, gn = col0 + nn;
                Bs[kk][nn] = (gk < K && gn < N) ? B[(long long)gn*ldb + gk] : 0.f;
            }
        }
        __syncthreads();
        #pragma unroll
        for (int kk = 0; kk < BK; kk++) {
            float a[TM], b[TN];
            #pragma unroll
            for (int i = 0; i < TM; i++) a[i] = As[kk][ty*TM + i];
            #pragma unroll
            for (int j = 0; j < TN; j++) b[j] = Bs[kk][tx*TN + j];
            #pragma unroll
            for (int i = 0; i < TM; i++)
                #pragma unroll
                for (int j = 0; j < TN; j++)
                    acc[i][j] += a[i] * b[j];
        }
        __syncthreads();
    }

    #pragma unroll
    for (int i = 0; i < TM; i++) {
        int gm = row0 + ty*TM + i;
        if (gm >= M) continue;
        #pragma unroll
        for (int j = 0; j < TN; j++) {
            int gn = col0 + tx*TN + j;
            if (gn >= N) continue;
            float v = alpha * acc[i][j];
            if (bias) v += bias[gn];
            if (Cr)   v += Cr[(long long)gm*ldc + gn];
            C[(long long)gm*ldc + gn] = v;
        }
    }
}

static inline void run_gemm(const float* A, const float* B, const float* bias,
                            const float* Cin, float* C,
                            int M, int N, int K, int lda, int ldb, int ldc,
                            long long sA, int aShift,
                            long long sB, int bShift, int bMask,
                            long long sCin, long long sC,
                            int batch, int transB, float alpha, int addC)
{
    long long bigBlocks = (long long)((N+127)/128) * ((M+127)/128) * batch;
    if (M >= 96 && bigBlocks >= 96) {
        dim3 grid((N+127)/128, (M+127)/128, batch);
        sgemm_kernel<128,128,8,8,8><<<grid, 256>>>(A,B,bias,Cin,C,M,N,K,lda,ldb,ldc,
            sA,aShift,sB,bShift,bMask,sCin,sC,transB,alpha,addC);
    } else {
        dim3 grid((N+127)/128, (M+63)/64, batch);
        sgemm_kernel<64,128,8,4,8><<<grid, 256>>>(A,B,bias,Cin,C,M,N,K,lda,ldb,ldc,
            sA,aShift,sB,bShift,bMask,sCin,sC,transB,alpha,addC);
    }
}

// ---------------- elementwise kernels ----------------
__global__ void patch_gather_kernel(const float* __restrict__ img, float* __restrict__ out) {
    int idx = blockIdx.x*blockDim.x + threadIdx.x;
    int total = BATCH*NPATCH*PK;
    if (idx >= total) return;
    int k = idx % PK;
    int p = (idx / PK) % NPATCH;
    int b = idx / (PK*NPATCH);
    int c  = k % 3;
    int pj = (k/3) % 16;
    int pi = k / 48;
    int i = p / 14, j = p % 14;
    out[idx] = img[(((long long)b*3 + c)*224 + (i*16+pi))*224 + (j*16+pj)];
}

__global__ void assemble_x_kernel(const float* __restrict__ xp, const float* __restrict__ cls,
                                  float* __restrict__ x) {
    int idx = blockIdx.x*blockDim.x + threadIdx.x;
    int total = BATCH*SEQ*DIM;
    if (idx >= total) return;
    int d = idx % DIM;
    int m = (idx / DIM) % SEQ;
    int b = idx / (DIM*SEQ);
    x[idx] = (m == 0) ? cls[d] : xp[((long long)b*NPATCH + (m-1))*DIM + d];
}

__global__ void rms_factor_kernel(const float* __restrict__ x, float* __restrict__ fac, int per_batch) {
    int b = blockIdx.x;
    const float* xb = x + (long long)b*per_batch;
    float s = 0.f;
    for (int i = threadIdx.x; i < per_batch; i += blockDim.x) { float v = xb[i]; s += v*v; }
    __shared__ float red[256];
    red[threadIdx.x] = s; __syncthreads();
    for (int o = 128; o > 0; o >>= 1) { if (threadIdx.x < o) red[threadIdx.x] += red[threadIdx.x+o]; __syncthreads(); }
    if (threadIdx.x == 0) fac[b] = sqrtf((float)per_batch / red[0]);
}

__global__ void rms_apply_kernel(float* __restrict__ x, const float* __restrict__ fac,
                                 const float* __restrict__ scale, int per_batch, int total) {
    int idx = blockIdx.x*blockDim.x + threadIdx.x;
    if (idx >= total) return;
    int b = idx / per_batch;
    x[idx] = x[idx] * fac[b] * scale[idx % per_batch];
}

// RoPE (in-place) on two tensors of layout (Z, M, D); pos index = M dim.
// theta_i = 10000^(-2*(i-1)/D) = exp2(cc*(i-1)), cc = -2*log2(10000)/D
__global__ void rope_kernel(float* __restrict__ q, float* __restrict__ k,
                            int Z, int M, int D, float cc) {
    int half = D / 2;
    long long total = (long long)Z * M * half;
    long long idx = (long long)blockIdx.x*blockDim.x + threadIdx.x;
    if (idx >= total) return;
    int i = (int)(idx % half);
    int m = (int)((idx / half) % M);
    long long z = idx / ((long long)half * M);
    float theta = exp2f(cc * ((float)i - 1.f));
    float ang = (float)m * theta;
    float s, c;
    sincosf(ang, &s, &c);
    long long base = ((z*M) + m) * (long long)D + 2*i;
    float xe, xo;
    xe = q[base]; xo = q[base+1];
    q[base] = xe*c + xo*s;  q[base+1] = -xe*s + xo*c;
    xe = k[base]; xo = k[base+1];
    k[base] = xe*c + xo*s;  k[base+1] = -xe*s + xo*c;
}

__global__ void softmax_kernel(float* __restrict__ s, int rows, int L) {
    int warp = (blockIdx.x*blockDim.x + threadIdx.x) / 32;
    int lane = threadIdx.x % 32;
    if (warp >= rows) return;
    float* row = s + (long long)warp * L;
    float mx = -1e30f;
    for (int i = lane; i < L; i += 32) mx = fmaxf(mx, row[i]);
    for (int o = 16; o; o >>= 1) mx = fmaxf(mx, __shfl_xor_sync(0xffffffffu, mx, o));
    float sum = 0.f;
    for (int i = lane; i < L; i += 32) { float e = __expf(row[i]-mx); row[i] = e; sum += e; }
    for (int o = 16; o; o >>= 1) sum += __shfl_xor_sync(0xffffffffu, sum, o);
    float inv = 1.f / sum;
    for (int i = lane; i < L; i += 32) row[i] *= inv;
}

// ot[b][m][h*512+e] = o[b][h][m][e]
__global__ void concat_heads_kernel(const float* __restrict__ o, float* __restrict__ ot) {
    int idx = blockIdx.x*blockDim.x + threadIdx.x;
    int total = BATCH*SEQ*HEADS*DIM;
    if (idx >= total) return;
    int e2 = idx % (HEADS*DIM);
    int m  = (idx / (HEADS*DIM)) % SEQ;
    int b  = idx / (HEADS*DIM*SEQ);
    int h = e2 >> 9, e = e2 & 511;
    ot[idx] = o[((((long long)b*HEADS + h)*SEQ) + m)*DIM + e];
}

// y[(b*64+c)*1576 + f*197+mm] = x[(b*197+mm)*512 + c*8+f]
__global__ void x_to_y_kernel(const float* __restrict__ x, float* __restrict__ y) {
    int idx = blockIdx.x*blockDim.x + threadIdx.x;
    int total = BATCH*CDIM*TDIM;
    if (idx >= total) return;
    int t = idx % TDIM;
    int c = (idx / TDIM) % CDIM;
    int b = idx / (TDIM*CDIM);
    int f = t / SEQ, mm = t % SEQ;
    y[idx] = x[((long long)b*SEQ + mm)*DIM + c*8 + f];
}

__global__ void y_to_x_kernel(const float* __restrict__ y, float* __restrict__ x) {
    int idx = blockIdx.x*blockDim.x + threadIdx.x;
    int total = BATCH*SEQ*DIM;
    if (idx >= total) return;
    int d  = idx % DIM;
    int mm = (idx / DIM) % SEQ;
    int b  = idx / (DIM*SEQ);
    int c = d >> 3, f = d & 7;
    x[idx] = y[((long long)b*CDIM + c)*TDIM + f*SEQ + mm];
}

__global__ void cls_ln_kernel(const float* __restrict__ x, const float* __restrict__ g,
                              const float* __restrict__ be, float* __restrict__ out) {
    int b = blockIdx.x, t = threadIdx.x;
    const float* row = x + (long long)b*SEQ*DIM;   // x[b][0][:]
    __shared__ float red[256];
    float s = 0.f;
    for (int i = t; i < DIM; i += 256) s += row[i];
    red[t] = s; __syncthreads();
    for (int o = 128; o > 0; o >>= 1) { if (t < o) red[t] += red[t+o]; __syncthreads(); }
    float mu = red[0] / DIM; __syncthreads();
    float v = 0.f;
    for (int i = t; i < DIM; i += 256) { float d = row[i]-mu; v += d*d; }
    red[t] = v; __syncthreads();
    for (int o = 128; o > 0; o >>= 1) { if (t < o) red[t] += red[t+o]; __syncthreads(); }
    float inv = rsqrtf(red[0]/DIM + 1e-5f);
    for (int i = t; i < DIM; i += 256) out[b*DIM + i] = (row[i]-mu)*inv*g[i] + be[i];
}

static inline int nblk(long long n, int t) { return (int)((n + t - 1) / t); }

extern "C" void kernel_launch(void* const* d_in, const int* in_sizes, int n_in,
                              void* d_out, int out_size) {
    const float* img       = (const float*)d_in[0];
    const float* patch_W   = (const float*)d_in[1];
    const float* patch_b   = (const float*)d_in[2];
    const float* cls_token = (const float*)d_in[3];
    const float* rms_scale = (const float*)d_in[4];
    const float* Wq        = (const float*)d_in[5];
    const float* Wk        = (const float*)d_in[6];
    const float* Wv        = (const float*)d_in[7];
    const float* attn_W    = (const float*)d_in[8];
    const float* attn_b    = (const float*)d_in[9];
    const float* tWq       = (const float*)d_in[10];
    const float* tWk       = (const float*)d_in[11];
    const float* tWv       = (const float*)d_in[12];
    const float* ln_g      = (const float*)d_in[13];
    const float* ln_b      = (const float*)d_in[14];
    const float* head_W    = (const float*)d_in[15];
    const float* head_b    = (const float*)d_in[16];
    float* out = (float*)d_out;

    float *ppat,*pxp,*px,*pq,*pk,*pv,*ps,*po,*pot,*py,*ptq,*ptk,*ptv,*pts,*pf,*pcls;
    cudaGetSymbolAddress((void**)&ppat, g_patches);
    cudaGetSymbolAddress((void**)&pxp,  g_xp);
    cudaGetSymbolAddress((void**)&px,   g_x);
    cudaGetSymbolAddress((void**)&pq,   g_q);
    cudaGetSymbolAddress((void**)&pk,   g_k);
    cudaGetSymbolAddress((void**)&pv,   g_v);
    cudaGetSymbolAddress((void**)&ps,   g_sc);
    cudaGetSymbolAddress((void**)&po,   g_o);
    cudaGetSymbolAddress((void**)&pot,  g_ot);
    cudaGetSymbolAddress((void**)&py,   g_y);
    cudaGetSymbolAddress((void**)&ptq,  g_tq);
    cudaGetSymbolAddress((void**)&ptk,  g_tk);
    cudaGetSymbolAddress((void**)&ptv,  g_tv);
    cudaGetSymbolAddress((void**)&pts,  g_ts);
    cudaGetSymbolAddress((void**)&pf,   g_fac);
    cudaGetSymbolAddress((void**)&pcls, g_cls);

    const long long sXB  = (long long)SEQ*DIM;       // per-batch x stride
    const long long sQH  = (long long)SEQ*DIM;       // per-(b,h) q/k/v/o stride
    const long long sSS  = (long long)SEQ*SEQ;
    const long long sOT  = (long long)SEQ*HEADS*DIM;
    const long long sY   = (long long)CDIM*TDIM;
    const long long sTS  = (long long)CDIM*CDIM;
    const int ALLB = 0x7fffffff;
    const float scale1 = (float)(1.0/sqrt(512.0));
    const float scale2 = (float)(1.0/sqrt(1576.0));
    const float cc1 = (float)(-2.0*log2(10000.0)/512.0);
    const float cc2 = (float)(-2.0*log2(10000.0)/1576.0);

    // ---- patch embedding ----
    patch_gather_kernel<<<nblk((long long)BATCH*NPATCH*PK,256),256>>>(img, ppat);
    run_gemm(ppat, patch_W, patch_b, 0, pxp,
             BATCH*NPATCH, DIM, PK, PK, DIM, DIM,
             0,0, 0,0,0, 0,0, 1, 0, 1.f, 0);
    assemble_x_kernel<<<nblk((long long)BATCH*SEQ*DIM,256),256>>>(pxp, cls_token, px);

    for (int l = 0; l < 2; l++) {
        const float* scale_l = rms_scale + (long long)l*SEQ*DIM;

        // rmsnorm #1 (global over (m,d) per batch)
        rms_factor_kernel<<<BATCH,256>>>(px, pf, SEQ*DIM);
        rms_apply_kernel<<<nblk((long long)BATCH*SEQ*DIM,256),256>>>(px, pf, scale_l, SEQ*DIM, BATCH*SEQ*DIM);

        // QKV: z = b*8+h (64 batches), A shared across heads
        run_gemm(px, Wq + (long long)l*HEADS*DIM*DIM, 0, 0, pq,
                 SEQ, DIM, DIM, DIM, DIM, DIM,
                 sXB, 3, (long long)DIM*DIM, 0, 7, 0, sQH, BATCH*HEADS, 0, 1.f, 0);
        run_gemm(px, Wk + (long long)l*HEADS*DIM*DIM, 0, 0, pk,
                 SEQ, DIM, DIM, DIM, DIM, DIM,
                 sXB, 3, (long long)DIM*DIM, 0, 7, 0, sQH, BATCH*HEADS, 0, 1.f, 0);
        run_gemm(px, Wv + (long long)l*HEADS*DIM*DIM, 0, 0, pv,
                 SEQ, DIM, DIM, DIM, DIM, DIM,
                 sXB, 3, (long long)DIM*DIM, 0, 7, 0, sQH, BATCH*HEADS, 0, 1.f, 0);

        // RoPE on q,k
        rope_kernel<<<nblk((long long)BATCH*HEADS*SEQ*(DIM/2),256),256>>>(pq, pk, BATCH*HEADS, SEQ, DIM, cc1);

        // s = q @ k^T * scale
        run_gemm(pq, pk, 0, 0, ps,
                 SEQ, SEQ, DIM, DIM, DIM, SEQ,
                 sQH, 0, sQH, 0, ALLB, 0, sSS, BATCH*HEADS, 1, scale1, 0);
        softmax_kernel<<<nblk((long long)BATCH*HEADS*SEQ*32,256),256>>>(ps, BATCH*HEADS*SEQ, SEQ);

        // o = p @ v
        run_gemm(ps, pv, 0, 0, po,
                 SEQ, DIM, SEQ, SEQ, DIM, DIM,
                 sSS, 0, sQH, 0, ALLB, 0, sQH, BATCH*HEADS, 0, 1.f, 0);

        // concat heads + output projection with residual
        concat_heads_kernel<<<nblk((long long)BATCH*SEQ*HEADS*DIM,256),256>>>(po, pot);
        run_gemm(pot, attn_W + (long long)l*HEADS*DIM*DIM, attn_b + l*DIM, px, px,
                 SEQ, DIM, HEADS*DIM, HEADS*DIM, DIM, DIM,
                 sOT, 0, 0, 0, 0, sXB, sXB, BATCH, 0, 1.f, 1);

        // rmsnorm #2
        rms_factor_kernel<<<BATCH,256>>>(px, pf, SEQ*DIM);
        rms_apply_kernel<<<nblk((long long)BATCH*SEQ*DIM,256),256>>>(px, pf, scale_l, SEQ*DIM, BATCH*SEQ*DIM);

        // token-mixing attention on transposed view y (b, 64, 1576)
        x_to_y_kernel<<<nblk((long long)BATCH*CDIM*TDIM,256),256>>>(px, py);

        run_gemm(py, tWq + (long long)l*TDIM*TDIM, 0, 0, ptq,
                 CDIM, TDIM, TDIM, TDIM, TDIM, TDIM,
                 sY, 0, 0, 0, 0, 0, sY, BATCH, 0, 1.f, 0);
        run_gemm(py, tWk + (long long)l*TDIM*TDIM, 0, 0, ptk,
                 CDIM, TDIM, TDIM, TDIM, TDIM, TDIM,
                 sY, 0, 0, 0, 0, 0, sY, BATCH, 0, 1.f, 0);
        run_gemm(py, tWv + (long long)l*TDIM*TDIM, 0, 0, ptv,
                 CDIM, TDIM, TDIM, TDIM, TDIM, TDIM,
                 sY, 0, 0, 0, 0, 0, sY, BATCH, 0, 1.f, 0);

        rope_kernel<<<nblk((long long)BATCH*CDIM*(TDIM/2),256),256>>>(ptq, ptk, BATCH, CDIM, TDIM, cc2);

        run_gemm(ptq, ptk, 0, 0, pts,
                 CDIM, CDIM, TDIM, TDIM, TDIM, CDIM,
                 sY, 0, sY, 0, ALLB, 0, sTS, BATCH, 1, scale2, 0);
        softmax_kernel<<<nblk((long long)BATCH*CDIM*32,256),256>>>(pts, BATCH*CDIM, CDIM);

        // y += p @ tv
        run_gemm(pts, ptv, 0, py, py,
                 CDIM, TDIM, CDIM, CDIM, TDIM, TDIM,
                 sTS, 0, sY, 0, ALLB, sY, sY, BATCH, 0, 1.f, 1);

        y_to_x_kernel<<<nblk((long long)BATCH*SEQ*DIM,256),256>>>(py, px);
    }

    // ---- final: cls token layernorm + head ----
    cls_ln_kernel<<<BATCH,256>>>(px, ln_g, ln_b, pcls);
    run_gemm(pcls, head_W, head_b, 0, out,
             BATCH, NCLS, DIM, DIM, NCLS, NCLS,
             0,0, 0,0,0, 0,0, 1, 0, 1.f, 0);
}

// round 3
// speedup vs baseline: 2.9956x; 2.9956x over previous
#include <cuda_runtime.h>
#include <math.h>

#define BATCH 8
#define HEADS 8
#define DIM 512
#define SEQ 197
#define SEQP 208
#define NPATCH 196
#define PK 768
#define CDIM 64
#define TDIM 1576
#define NCLS 1000

// ---------------- scratch (device globals) ----------------
__device__ float g_patches[BATCH*NPATCH*PK];
__device__ float g_xp[BATCH*NPATCH*DIM];
__device__ float g_x[BATCH*SEQ*DIM];
__device__ float g_q[BATCH*HEADS*SEQ*DIM];
__device__ float g_k[BATCH*HEADS*SEQ*DIM];
__device__ float g_v[BATCH*HEADS*SEQ*DIM + 16*DIM];   // pad: K=SEQP over-read on last batch
__device__ float g_sc[BATCH*HEADS*SEQ*SEQP];
__device__ float g_o[BATCH*HEADS*SEQ*DIM];
__device__ float g_ot[BATCH*SEQ*HEADS*DIM];           // per-head proj partials
__device__ float g_y[BATCH*CDIM*TDIM];
__device__ float g_tq[BATCH*CDIM*TDIM];
__device__ float g_tk[BATCH*CDIM*TDIM];
__device__ float g_tv[BATCH*CDIM*TDIM];
__device__ float g_ts[BATCH*CDIM*CDIM];
__device__ float g_fac[BATCH];
__device__ float g_red[BATCH*32];
__device__ float g_cls[BATCH*DIM];

// ---------------- vectorized double-buffered batched GEMM ----------------
// C[z] = alpha * A[(z>>aShift)] @ op(B[(z>>bShift)&bMask]) (+bias) (+Cin[z])
// Requirements: K%4==0, lda%4==0, ldb%4==0 (all call sites satisfy this).
template<int BM,int BN,int TM,int TN>
__global__ __launch_bounds__((BM/TM)*(BN/TN))
void sgemm_v(const float* __restrict__ A, const float* __restrict__ B,
             const float* __restrict__ bias, const float* __restrict__ Cin,
             float* __restrict__ C,
             int M,int N,int K,int lda,int ldb,int ldc,
             long long sA,int aShift, long long sB,int bShift,int bMask,
             long long sCin,long long sC,int transB,float alpha,int addC)
{
    constexpr int BK=16;
    constexpr int THREADS=(BM/TM)*(BN/TN);
    __shared__ float As[2][BK][BM+4];
    __shared__ float Bs[2][BK][BN+4];

    int z=blockIdx.z;
    A += (long long)(z>>aShift)*sA;
    B += (long long)((z>>bShift)&bMask)*sB;
    C += (long long)z*sC;
    const float* Cr = addC ? Cin+(long long)z*sCin : (const float*)0;

    int row0=blockIdx.y*BM, col0=blockIdx.x*BN;
    int tid=threadIdx.x;
    int tx=tid%(BN/TN), ty=tid/(BN/TN);

    float acc[TM][TN];
#pragma unroll
    for(int i=0;i<TM;i++)
#pragma unroll
      for(int j=0;j<TN;j++) acc[i][j]=0.f;

    float4 ra[2], rb[2];

    auto ldAg=[&](int k0){
#pragma unroll
      for(int t=0;t<2;t++){
        int idx=tid+t*THREADS; int mm=idx>>2; int c4=idx&3;
        int gm=row0+mm, gk=k0+c4*4;
        float4 v=make_float4(0.f,0.f,0.f,0.f);
        if(gm<M && gk<K) v=*(const float4*)&A[(long long)gm*lda+gk];
        ra[t]=v;
      }
    };
    auto stAs=[&](int buf){
#pragma unroll
      for(int t=0;t<2;t++){
        int idx=tid+t*THREADS; int mm=idx>>2; int c4=idx&3;
        As[buf][c4*4+0][mm]=ra[t].x; As[buf][c4*4+1][mm]=ra[t].y;
        As[buf][c4*4+2][mm]=ra[t].z; As[buf][c4*4+3][mm]=ra[t].w;
      }
    };
    auto ldBg=[&](int k0){
      if(!transB){
#pragma unroll
        for(int t=0;t<2;t++){
          int idx=tid+t*THREADS; int kk=idx/(BN/4); int n4=idx%(BN/4);
          int gk=k0+kk, gn=col0+n4*4;
          float4 v=make_float4(0.f,0.f,0.f,0.f);
          if(gk<K){
            if(gn+3<N) v=*(const float4*)&B[(long long)gk*ldb+gn];
            else {
              const float* p=&B[(long long)gk*ldb];
              if(gn  <N)v.x=p[gn];   if(gn+1<N)v.y=p[gn+1];
              if(gn+2<N)v.z=p[gn+2]; if(gn+3<N)v.w=p[gn+3];
            }
          }
          rb[t]=v;
        }
      } else {
#pragma unroll
        for(int t=0;t<2;t++){
          int idx=tid+t*THREADS; int nn=idx>>2; int c4=idx&3;
          int gn=col0+nn, gk=k0+c4*4;
          float4 v=make_float4(0.f,0.f,0.f,0.f);
          if(gn<N && gk<K) v=*(const float4*)&B[(long long)gn*ldb+gk];
          rb[t]=v;
        }
      }
    };
    auto stBs=[&](int buf){
      if(!transB){
#pragma unroll
        for(int t=0;t<2;t++){
          int idx=tid+t*THREADS; int kk=idx/(BN/4); int n4=idx%(BN/4);
          *(float4*)&Bs[buf][kk][n4*4]=rb[t];
        }
      } else {
#pragma unroll
        for(int t=0;t<2;t++){
          int idx=tid+t*THREADS; int nn=idx>>2; int c4=idx&3;
          Bs[buf][c4*4+0][nn]=rb[t].x; Bs[buf][c4*4+1][nn]=rb[t].y;
          Bs[buf][c4*4+2][nn]=rb[t].z; Bs[buf][c4*4+3][nn]=rb[t].w;
        }
      }
    };

    ldAg(0); ldBg(0); stAs(0); stBs(0);
    __syncthreads();
    int nk=(K+BK-1)/BK;
    for(int kt=0;kt<nk;kt++){
      int cur=kt&1;
      if(kt+1<nk){ ldAg((kt+1)*BK); ldBg((kt+1)*BK); }
#pragma unroll
      for(int kk=0;kk<BK;kk++){
        float a[TM], b[TN];
        *(float4*)&a[0]=*(float4*)&As[cur][kk][ty*TM];
        if(TM>4) *(float4*)&a[4]=*(float4*)&As[cur][kk][ty*TM+4];
        *(float4*)&b[0]=*(float4*)&Bs[cur][kk][tx*TN];
        if(TN>4) *(float4*)&b[4]=*(float4*)&Bs[cur][kk][tx*TN+4];
#pragma unroll
        for(int i=0;i<TM;i++)
#pragma unroll
          for(int j=0;j<TN;j++) acc[i][j]+=a[i]*b[j];
      }
      if(kt+1<nk){ stAs(cur^1); stBs(cur^1); __syncthreads(); }
    }

#pragma unroll
    for(int i=0;i<TM;i++){
      int gm=row0+ty*TM+i;
      if(gm>=M) continue;
      long long base=(long long)gm*ldc;
#pragma unroll
      for(int j=0;j<TN;j++){
        int gn=col0+tx*TN+j;
        if(gn>=N) continue;
        float v=alpha*acc[i][j];
        if(bias) v+=bias[gn];
        if(Cr)   v+=Cr[base+gn];
        C[base+gn]=v;
      }
    }
}

static inline void run_gemm(const float* A,const float* B,const float* bias,
                            const float* Cin,float* C,
                            int M,int N,int K,int lda,int ldb,int ldc,
                            long long sA,int aShift,long long sB,int bShift,int bMask,
                            long long sCin,long long sC,int batch,int transB,float alpha,int addC)
{
    if(M<=32 || (M<=64 && N<=64)){
        dim3 grid((N+31)/32,(M+31)/32,batch);
        sgemm_v<32,32,4,4><<<grid,64>>>(A,B,bias,Cin,C,M,N,K,lda,ldb,ldc,
            sA,aShift,sB,bShift,bMask,sCin,sC,transB,alpha,addC);
        return;
    }
    long long bigBlocks=(long long)((M+127)/128)*((N+127)/128)*batch;
    if(M>=96 && bigBlocks>=120){
        dim3 grid((N+127)/128,(M+127)/128,batch);
        sgemm_v<128,128,8,8><<<grid,256>>>(A,B,bias,Cin,C,M,N,K,lda,ldb,ldc,
            sA,aShift,sB,bShift,bMask,sCin,sC,transB,alpha,addC);
    } else {
        dim3 grid((N+63)/64,(M+63)/64,batch);
        sgemm_v<64,64,4,8><<<grid,128>>>(A,B,bias,Cin,C,M,N,K,lda,ldb,ldc,
            sA,aShift,sB,bShift,bMask,sCin,sC,transB,alpha,addC);
    }
}

// ---------------- elementwise kernels ----------------
__global__ void patch_gather_kernel(const float* __restrict__ img, float* __restrict__ out) {
    int idx = blockIdx.x*blockDim.x + threadIdx.x;
    int total = BATCH*NPATCH*PK;
    if (idx >= total) return;
    int k = idx % PK;
    int p = (idx / PK) % NPATCH;
    int b = idx / (PK*NPATCH);
    int c  = k % 3;
    int pj = (k/3) % 16;
    int pi = k / 48;
    int i = p / 14, j = p % 14;
    out[idx] = img[(((long long)b*3 + c)*224 + (i*16+pi))*224 + (j*16+pj)];
}

__global__ void assemble_x_kernel(const float* __restrict__ xp, const float* __restrict__ cls,
                                  float* __restrict__ x) {
    int idx = blockIdx.x*blockDim.x + threadIdx.x;
    int total = BATCH*SEQ*DIM;
    if (idx >= total) return;
    int d = idx % DIM;
    int m = (idx / DIM) % SEQ;
    int b = idx / (DIM*SEQ);
    x[idx] = (m == 0) ? cls[d] : xp[((long long)b*NPATCH + (m-1))*DIM + d];
}

// two-stage rms factor: stage1 -> 32 partials per batch (float4 loads)
__global__ void rms_part_kernel(const float* __restrict__ x, float* __restrict__ red) {
    int b = blockIdx.y, ch = blockIdx.x;
    const int per_batch = SEQ*DIM;          // 100864
    const int chunk = per_batch/32;         // 3152 (div by 4)
    const float4* p = (const float4*)(x + (long long)b*per_batch + ch*chunk);
    float s = 0.f;
    for (int i = threadIdx.x; i < chunk/4; i += 256) {
        float4 v = p[i];
        s += v.x*v.x + v.y*v.y + v.z*v.z + v.w*v.w;
    }
    __shared__ float sm[256];
    sm[threadIdx.x] = s; __syncthreads();
    for (int o = 128; o > 0; o >>= 1) { if (threadIdx.x < o) sm[threadIdx.x] += sm[threadIdx.x+o]; __syncthreads(); }
    if (threadIdx.x == 0) red[b*32 + ch] = sm[0];
}
__global__ void rms_fin_kernel(const float* __restrict__ red, float* __restrict__ fac) {
    int b = threadIdx.x / 32, lane = threadIdx.x % 32;   // 256 threads = 8 batches
    float v = red[b*32 + lane];
    for (int o = 16; o; o >>= 1) v += __shfl_xor_sync(0xffffffffu, v, o);
    if (lane == 0) fac[b] = sqrtf((float)(SEQ*DIM) / v);
}

__global__ void rms_apply_kernel(float* __restrict__ x, const float* __restrict__ fac,
                                 const float* __restrict__ scale) {
    int idx = blockIdx.x*blockDim.x + threadIdx.x;
    const int per4 = SEQ*DIM/4;
    int total = BATCH*per4;
    if (idx >= total) return;
    int b = idx / per4, s4 = idx % per4;
    float f = fac[b];
    float4 v = ((float4*)x)[idx];
    float4 sc = ((const float4*)scale)[s4];
    v.x *= f*sc.x; v.y *= f*sc.y; v.z *= f*sc.z; v.w *= f*sc.w;
    ((float4*)x)[idx] = v;
}

// RoPE on (Z, M, D), pos index = M; theta_i = 10000^(-2(i-1)/D)
__global__ void rope_kernel(float* __restrict__ q, float* __restrict__ k,
                            int Z, int M, int D, float cc) {
    int half = D / 2;
    long long total = (long long)Z * M * half;
    long long idx = (long long)blockIdx.x*blockDim.x + threadIdx.x;
    if (idx >= total) return;
    int i = (int)(idx % half);
    int m = (int)((idx / half) % M);
    long long z = idx / ((long long)half * M);
    float theta = exp2f(cc * ((float)i - 1.f));
    float ang = (float)m * theta;
    float s, c;
    sincosf(ang, &s, &c);
    long long base = ((z*M) + m) * (long long)D + 2*i;
    float xe, xo;
    xe = q[base]; xo = q[base+1];
    q[base] = xe*c + xo*s;  q[base+1] = -xe*s + xo*c;
    xe = k[base]; xo = k[base+1];
    k[base] = xe*c + xo*s;  k[base+1] = -xe*s + xo*c;
}

// softmax on rows of leading-dim ld; zeros padding cols [L, ld)
__global__ void softmax_kernel(float* __restrict__ s, int rows, int L, int ld) {
    int warp = (blockIdx.x*blockDim.x + threadIdx.x) / 32;
    int lane = threadIdx.x % 32;
    if (warp >= rows) return;
    float* row = s + (long long)warp * ld;
    float mx = -1e30f;
    for (int i = lane; i < L; i += 32) mx = fmaxf(mx, row[i]);
    for (int o = 16; o; o >>= 1) mx = fmaxf(mx, __shfl_xor_sync(0xffffffffu, mx, o));
    float sum = 0.f;
    for (int i = lane; i < L; i += 32) { float e = __expf(row[i]-mx); row[i] = e; sum += e; }
    for (int o = 16; o; o >>= 1) sum += __shfl_xor_sync(0xffffffffu, sum, o);
    float inv = 1.f / sum;
    for (int i = lane; i < ld; i += 32) row[i] = (i < L) ? row[i]*inv : 0.f;
}

// x[b][m][:] += bias + sum_h part[b*8+h][m][:]   (float4)
__global__ void attn_reduce_kernel(const float* __restrict__ part,
                                   const float* __restrict__ bias,
                                   float* __restrict__ x) {
    int idx = blockIdx.x*blockDim.x + threadIdx.x;
    const int D4 = DIM/4;
    int total = BATCH*SEQ*D4;
    if (idx >= total) return;
    int d4 = idx % D4;
    int m  = (idx / D4) % SEQ;
    int b  = idx / (D4*SEQ);
    float4 acc = ((float4*)x)[idx];
    float4 bb = ((const float4*)bias)[d4];
    acc.x += bb.x; acc.y += bb.y; acc.z += bb.z; acc.w += bb.w;
#pragma unroll
    for (int h = 0; h < HEADS; h++) {
        float4 p = ((const float4*)part)[((long long)(b*HEADS+h)*SEQ + m)*D4 + d4];
        acc.x += p.x; acc.y += p.y; acc.z += p.z; acc.w += p.w;
    }
    ((float4*)x)[idx] = acc;
}

// y[(b*64+c)*1576 + f*197+mm] = x[(b*197+mm)*512 + c*8+f]
__global__ void x_to_y_kernel(const float* __restrict__ x, float* __restrict__ y) {
    int idx = blockIdx.x*blockDim.x + threadIdx.x;
    int total = BATCH*CDIM*TDIM;
    if (idx >= total) return;
    int t = idx % TDIM;
    int c = (idx / TDIM) % CDIM;
    int b = idx / (TDIM*CDIM);
    int f = t / SEQ, mm = t % SEQ;
    y[idx] = x[((long long)b*SEQ + mm)*DIM + c*8 + f];
}

__global__ void y_to_x_kernel(const float* __restrict__ y, float* __restrict__ x) {
    int idx = blockIdx.x*blockDim.x + threadIdx.x;
    int total = BATCH*SEQ*DIM;
    if (idx >= total) return;
    int d  = idx % DIM;
    int mm = (idx / DIM) % SEQ;
    int b  = idx / (DIM*SEQ);
    int c = d >> 3, f = d & 7;
    x[idx] = y[((long long)b*CDIM + c)*TDIM + f*SEQ + mm];
}

__global__ void cls_ln_kernel(const float* __restrict__ x, const float* __restrict__ g,
                              const float* __restrict__ be, float* __restrict__ out) {
    int b = blockIdx.x, t = threadIdx.x;
    const float* row = x + (long long)b*SEQ*DIM;
    __shared__ float red[256];
    float s = 0.f;
    for (int i = t; i < DIM; i += 256) s += row[i];
    red[t] = s; __syncthreads();
    for (int o = 128; o > 0; o >>= 1) { if (t < o) red[t] += red[t+o]; __syncthreads(); }
    float mu = red[0] / DIM; __syncthreads();
    float v = 0.f;
    for (int i = t; i < DIM; i += 256) { float d = row[i]-mu; v += d*d; }
    red[t] = v; __syncthreads();
    for (int o = 128; o > 0; o >>= 1) { if (t < o) red[t] += red[t+o]; __syncthreads(); }
    float inv = rsqrtf(red[0]/DIM + 1e-5f);
    for (int i = t; i < DIM; i += 256) out[b*DIM + i] = (row[i]-mu)*inv*g[i] + be[i];
}

static inline int nblk(long long n, int t) { return (int)((n + t - 1) / t); }

extern "C" void kernel_launch(void* const* d_in, const int* in_sizes, int n_in,
                              void* d_out, int out_size) {
    const float* img       = (const float*)d_in[0];
    const float* patch_W   = (const float*)d_in[1];
    const float* patch_b   = (const float*)d_in[2];
    const float* cls_token = (const float*)d_in[3];
    const float* rms_scale = (const float*)d_in[4];
    const float* Wq        = (const float*)d_in[5];
    const float* Wk        = (const float*)d_in[6];
    const float* Wv        = (const float*)d_in[7];
    const float* attn_W    = (const float*)d_in[8];
    const float* attn_b    = (const float*)d_in[9];
    const float* tWq       = (const float*)d_in[10];
    const float* tWk       = (const float*)d_in[11];
    const float* tWv       = (const float*)d_in[12];
    const float* ln_g      = (const float*)d_in[13];
    const float* ln_b      = (const float*)d_in[14];
    const float* head_W    = (const float*)d_in[15];
    const float* head_b    = (const float*)d_in[16];
    float* out = (float*)d_out;

    float *ppat,*pxp,*px,*pq,*pk,*pv,*ps,*po,*pot,*py,*ptq,*ptk,*ptv,*pts,*pf,*pred,*pcls;
    cudaGetSymbolAddress((void**)&ppat, g_patches);
    cudaGetSymbolAddress((void**)&pxp,  g_xp);
    cudaGetSymbolAddress((void**)&px,   g_x);
    cudaGetSymbolAddress((void**)&pq,   g_q);
    cudaGetSymbolAddress((void**)&pk,   g_k);
    cudaGetSymbolAddress((void**)&pv,   g_v);
    cudaGetSymbolAddress((void**)&ps,   g_sc);
    cudaGetSymbolAddress((void**)&po,   g_o);
    cudaGetSymbolAddress((void**)&pot,  g_ot);
    cudaGetSymbolAddress((void**)&py,   g_y);
    cudaGetSymbolAddress((void**)&ptq,  g_tq);
    cudaGetSymbolAddress((void**)&ptk,  g_tk);
    cudaGetSymbolAddress((void**)&ptv,  g_tv);
    cudaGetSymbolAddress((void**)&pts,  g_ts);
    cudaGetSymbolAddress((void**)&pf,   g_fac);
    cudaGetSymbolAddress((void**)&pred, g_red);
    cudaGetSymbolAddress((void**)&pcls, g_cls);

    const long long sXB  = (long long)SEQ*DIM;
    const long long sQH  = (long long)SEQ*DIM;
    const long long sSSp = (long long)SEQ*SEQP;
    const long long sY   = (long long)CDIM*TDIM;
    const long long sTS  = (long long)CDIM*CDIM;
    const int ALLB = 0x7fffffff;
    const float scale1 = (float)(1.0/sqrt(512.0));
    const float scale2 = (float)(1.0/sqrt(1576.0));
    const float cc1 = (float)(-2.0*log2(10000.0)/512.0);
    const float cc2 = (float)(-2.0*log2(10000.0)/1576.0);

    // ---- patch embedding ----
    patch_gather_kernel<<<nblk((long long)BATCH*NPATCH*PK,256),256>>>(img, ppat);
    run_gemm(ppat, patch_W, patch_b, 0, pxp,
             BATCH*NPATCH, DIM, PK, PK, DIM, DIM,
             0,0, 0,0,0, 0,0, 1, 0, 1.f, 0);
    assemble_x_kernel<<<nblk((long long)BATCH*SEQ*DIM,256),256>>>(pxp, cls_token, px);

    for (int l = 0; l < 2; l++) {
        const float* scale_l = rms_scale + (long long)l*SEQ*DIM;

        // rmsnorm #1
        rms_part_kernel<<<dim3(32,BATCH),256>>>(px, pred);
        rms_fin_kernel<<<1,256>>>(pred, pf);
        rms_apply_kernel<<<nblk((long long)BATCH*SEQ*DIM/4,256),256>>>(px, pf, scale_l);

        // QKV: z = b*8+h (64 batches)
        run_gemm(px, Wq + (long long)l*HEADS*DIM*DIM, 0, 0, pq,
                 SEQ, DIM, DIM, DIM, DIM, DIM,
                 sXB, 3, (long long)DIM*DIM, 0, 7, 0, sQH, BATCH*HEADS, 0, 1.f, 0);
        run_gemm(px, Wk + (long long)l*HEADS*DIM*DIM, 0, 0, pk,
                 SEQ, DIM, DIM, DIM, DIM, DIM,
                 sXB, 3, (long long)DIM*DIM, 0, 7, 0, sQH, BATCH*HEADS, 0, 1.f, 0);
        run_gemm(px, Wv + (long long)l*HEADS*DIM*DIM, 0, 0, pv,
                 SEQ, DIM, DIM, DIM, DIM, DIM,
                 sXB, 3, (long long)DIM*DIM, 0, 7, 0, sQH, BATCH*HEADS, 0, 1.f, 0);

        rope_kernel<<<nblk((long long)BATCH*HEADS*SEQ*(DIM/2),256),256>>>(pq, pk, BATCH*HEADS, SEQ, DIM, cc1);

        // s = q @ k^T * scale (ldc padded to 208)
        run_gemm(pq, pk, 0, 0, ps,
                 SEQ, SEQ, DIM, DIM, DIM, SEQP,
                 sQH, 0, sQH, 0, ALLB, 0, sSSp, BATCH*HEADS, 1, scale1, 0);
        softmax_kernel<<<nblk((long long)BATCH*HEADS*SEQ*32,256),256>>>(ps, BATCH*HEADS*SEQ, SEQ, SEQP);

        // o = p @ v  (K padded to 208; pad cols of p are zero)
        run_gemm(ps, pv, 0, 0, po,
                 SEQ, DIM, SEQP, SEQP, DIM, DIM,
                 sSSp, 0, sQH, 0, ALLB, 0, sQH, BATCH*HEADS, 0, 1.f, 0);

        // per-head output-proj partials: part[b*8+h] = o[b,h] @ attn_W[l, h*512:(h+1)*512, :]
        run_gemm(po, attn_W + (long long)l*HEADS*DIM*DIM, 0, 0, pot,
                 SEQ, DIM, DIM, DIM, DIM, DIM,
                 sQH, 0, (long long)DIM*DIM, 0, 7, 0, sQH, BATCH*HEADS, 0, 1.f, 0);
        attn_reduce_kernel<<<nblk((long long)BATCH*SEQ*DIM/4,256),256>>>(pot, attn_b + l*DIM, px);

        // rmsnorm #2
        rms_part_kernel<<<dim3(32,BATCH),256>>>(px, pred);
        rms_fin_kernel<<<1,256>>>(pred, pf);
        rms_apply_kernel<<<nblk((long long)BATCH*SEQ*DIM/4,256),256>>>(px, pf, scale_l);

        // token-mixing attention
        x_to_y_kernel<<<nblk((long long)BATCH*CDIM*TDIM,256),256>>>(px, py);

        run_gemm(py, tWq + (long long)l*TDIM*TDIM, 0, 0, ptq,
                 CDIM, TDIM, TDIM, TDIM, TDIM, TDIM,
                 sY, 0, 0, 0, 0, 0, sY, BATCH, 0, 1.f, 0);
        run_gemm(py, tWk + (long long)l*TDIM*TDIM, 0, 0, ptk,
                 CDIM, TDIM, TDIM, TDIM, TDIM, TDIM,
                 sY, 0, 0, 0, 0, 0, sY, BATCH, 0, 1.f, 0);
        run_gemm(py, tWv + (long long)l*TDIM*TDIM, 0, 0, ptv,
                 CDIM, TDIM, TDIM, TDIM, TDIM, TDIM,
                 sY, 0, 0, 0, 0, 0, sY, BATCH, 0, 1.f, 0);

        rope_kernel<<<nblk((long long)BATCH*CDIM*(TDIM/2),256),256>>>(ptq, ptk, BATCH, CDIM, TDIM, cc2);

        run_gemm(ptq, ptk, 0, 0, pts,
                 CDIM, CDIM, TDIM, TDIM, TDIM, CDIM,
                 sY, 0, sY, 0, ALLB, 0, sTS, BATCH, 1, scale2, 0);
        softmax_kernel<<<nblk((long long)BATCH*CDIM*32,256),256>>>(pts, BATCH*CDIM, CDIM, CDIM);

        // y += p @ tv
        run_gemm(pts, ptv, 0, py, py,
                 CDIM, TDIM, CDIM, CDIM, TDIM, TDIM,
                 sTS, 0, sY, 0, ALLB, sY, sY, BATCH, 0, 1.f, 1);

        y_to_x_kernel<<<nblk((long long)BATCH*SEQ*DIM,256),256>>>(py, px);
    }

    // ---- final: cls layernorm + head ----
    cls_ln_kernel<<<BATCH,256>>>(px, ln_g, ln_b, pcls);
    run_gemm(pcls, head_W, head_b, 0, out,
             BATCH, NCLS, DIM, DIM, NCLS, NCLS,
             0,0, 0,0,0, 0,0, 1, 0, 1.f, 0);
}

// round 4
// speedup vs baseline: 3.3937x; 1.1329x over previous
#include <cuda_runtime.h>
#include <cuda_bf16.h>
#include <math.h>

#define BATCH 8
#define HEADS 8
#define DIM 512
#define SEQ 197
#define SEQP 208
#define NPATCH 196
#define PK 768
#define CDIM 64
#define TDIM 1576
#define NCLS 1000

// ---------------- scratch (device globals) ----------------
__device__ float g_patches[BATCH*NPATCH*PK];
__device__ float g_xp[BATCH*NPATCH*DIM];
__device__ float g_x[BATCH*SEQ*DIM];
__device__ float g_q[BATCH*HEADS*SEQ*DIM];
__device__ float g_k[BATCH*HEADS*SEQ*DIM];
__device__ float g_v[BATCH*HEADS*SEQ*DIM + 16*DIM];   // pad: K=SEQP over-read on last batch
__device__ float g_sc[BATCH*HEADS*SEQ*SEQP];
__device__ float g_o[BATCH*HEADS*SEQ*DIM];
__device__ float g_ot[BATCH*SEQ*HEADS*DIM];
__device__ float g_y[BATCH*CDIM*TDIM];
__device__ float g_tq[BATCH*CDIM*TDIM];
__device__ float g_tk[BATCH*CDIM*TDIM];
__device__ float g_tv[BATCH*CDIM*TDIM];
__device__ float g_ts[BATCH*CDIM*CDIM];
__device__ float g_fac[BATCH];
__device__ float g_red[BATCH*32];
__device__ float g_cls[BATCH*DIM];

// ================= tensor-core GEMM (bf16 split hi/lo, fp32 acc) =================
// C[z] = alpha * A[(z>>aShift)] @ op(B[(z>>bShift)&bMask]) (+bias) (+Cin[z])
// A fp32 [M][lda] row-major; B fp32 [K][ldb] (transB=0) or [N][ldb] (transB=1).
// Requires lda%4==0, ldb%4==0, K%4==0; N%4==0 when transB==0.

__device__ __forceinline__ void ldsm4(unsigned r[4], const __nv_bfloat16* p) {
    unsigned a = (unsigned)__cvta_generic_to_shared(p);
    asm volatile("ldmatrix.sync.aligned.m8n8.x4.shared.b16 {%0,%1,%2,%3}, [%4];"
                 : "=r"(r[0]), "=r"(r[1]), "=r"(r[2]), "=r"(r[3]) : "r"(a));
}
__device__ __forceinline__ void mma16816(float c[4], const unsigned a[4],
                                         unsigned b0, unsigned b1) {
    asm volatile("mma.sync.aligned.m16n8k16.row.col.f32.bf16.bf16.f32 "
                 "{%0,%1,%2,%3}, {%4,%5,%6,%7}, {%8,%9}, {%0,%1,%2,%3};"
                 : "+f"(c[0]), "+f"(c[1]), "+f"(c[2]), "+f"(c[3])
                 : "r"(a[0]), "r"(a[1]), "r"(a[2]), "r"(a[3]), "r"(b0), "r"(b1));
}

#define LDSM 40   // smem row stride (halves): 80B -> 16B-aligned rows, conflict-free ldmatrix

template<int BM, int BN>
__global__ __launch_bounds__((BM/64)*(BN/32)*32)
void hgemm(const float* __restrict__ A, const float* __restrict__ B,
           const float* __restrict__ bias, const float* __restrict__ Cin,
           float* __restrict__ C,
           int M, int N, int K, int lda, int ldb, int ldc,
           long long sA, int aShift, long long sB, int bShift, int bMask,
           long long sCin, long long sC, int transB, float alpha, int addC)
{
    constexpr int WARPS_M = BM/64;
    constexpr int WARPS_N = BN/32;
    constexpr int THREADS = WARPS_M*WARPS_N*32;
    constexpr int A_F4 = BM*8/THREADS;   // float4 slots per thread (BM*32/4 / THREADS)
    constexpr int B_F4 = BN*8/THREADS;

    __shared__ __align__(16) __nv_bfloat16 AsH[BM][LDSM];
    __shared__ __align__(16) __nv_bfloat16 AsL[BM][LDSM];
    __shared__ __align__(16) __nv_bfloat16 BsH[BN][LDSM];
    __shared__ __align__(16) __nv_bfloat16 BsL[BN][LDSM];

    int z = blockIdx.z;
    A += (long long)(z>>aShift)*sA;
    B += (long long)((z>>bShift)&bMask)*sB;
    C += (long long)z*sC;
    const float* Cr = addC ? Cin + (long long)z*sCin : (const float*)0;

    int row0 = blockIdx.y*BM, col0 = blockIdx.x*BN;
    int tid = threadIdx.x;
    int lane = tid & 31, warp = tid >> 5;
    int wm0 = (warp % WARPS_M)*64;
    int wn0 = (warp / WARPS_M)*32;

    float acc[4][4][4];
#pragma unroll
    for (int i=0;i<4;i++)
#pragma unroll
      for (int j=0;j<4;j++)
#pragma unroll
        for (int t=0;t<4;t++) acc[i][j][t]=0.f;

    float4 stA[A_F4], stB[B_F4];

    auto ldA = [&](int k0){
#pragma unroll
      for (int t=0;t<A_F4;t++){
        int idx = tid + t*THREADS;
        int mm = idx>>3, k4 = idx&7;
        int gm = row0+mm, gk = k0+k4*4;
        float4 v = make_float4(0.f,0.f,0.f,0.f);
        if (gm<M && gk<K) v = *(const float4*)&A[(long long)gm*lda+gk];
        stA[t]=v;
      }
    };
    auto stoA = [&](){
#pragma unroll
      for (int t=0;t<A_F4;t++){
        int idx = tid + t*THREADS;
        int mm = idx>>3, k4 = idx&7;
        float4 v = stA[t];
        __nv_bfloat16 hx=__float2bfloat16_rn(v.x), hy=__float2bfloat16_rn(v.y);
        __nv_bfloat16 hz=__float2bfloat16_rn(v.z), hw=__float2bfloat16_rn(v.w);
        __nv_bfloat162* ph = (__nv_bfloat162*)&AsH[mm][k4*4];
        __nv_bfloat162* pl = (__nv_bfloat162*)&AsL[mm][k4*4];
        __nv_bfloat162 p0; p0.x=hx; p0.y=hy; ph[0]=p0;
        __nv_bfloat162 p1; p1.x=hz; p1.y=hw; ph[1]=p1;
        __nv_bfloat162 q0; q0.x=__float2bfloat16_rn(v.x-__bfloat162float(hx));
                           q0.y=__float2bfloat16_rn(v.y-__bfloat162float(hy)); pl[0]=q0;
        __nv_bfloat162 q1; q1.x=__float2bfloat16_rn(v.z-__bfloat162float(hz));
                           q1.y=__float2bfloat16_rn(v.w-__bfloat162float(hw)); pl[1]=q1;
      }
    };
    auto ldB = [&](int k0){
      if (transB){
#pragma unroll
        for (int t=0;t<B_F4;t++){
          int idx = tid + t*THREADS;
          int nn = idx>>3, k4 = idx&7;
          int gn = col0+nn, gk = k0+k4*4;
          float4 v = make_float4(0.f,0.f,0.f,0.f);
          if (gn<N && gk<K) v = *(const float4*)&B[(long long)gn*ldb+gk];
          stB[t]=v;
        }
      } else {
#pragma unroll
        for (int t=0;t<B_F4;t++){
          int idx = tid + t*THREADS;
          int kk = idx/(BN/4), n4 = idx%(BN/4);
          int gk = k0+kk, gn = col0+n4*4;
          float4 v = make_float4(0.f,0.f,0.f,0.f);
          if (gk<K && gn+4<=N) v = *(const float4*)&B[(long long)gk*ldb+gn];
          stB[t]=v;
        }
      }
    };
    auto stoB = [&](){
      if (transB){
#pragma unroll
        for (int t=0;t<B_F4;t++){
          int idx = tid + t*THREADS;
          int nn = idx>>3, k4 = idx&7;
          float4 v = stB[t];
          __nv_bfloat16 hx=__float2bfloat16_rn(v.x), hy=__float2bfloat16_rn(v.y);
          __nv_bfloat16 hz=__float2bfloat16_rn(v.z), hw=__float2bfloat16_rn(v.w);
          __nv_bfloat162* ph = (__nv_bfloat162*)&BsH[nn][k4*4];
          __nv_bfloat162* pl = (__nv_bfloat162*)&BsL[nn][k4*4];
          __nv_bfloat162 p0; p0.x=hx; p0.y=hy; ph[0]=p0;
          __nv_bfloat162 p1; p1.x=hz; p1.y=hw; ph[1]=p1;
          __nv_bfloat162 q0; q0.x=__float2bfloat16_rn(v.x-__bfloat162float(hx));
                             q0.y=__float2bfloat16_rn(v.y-__bfloat162float(hy)); pl[0]=q0;
          __nv_bfloat162 q1; q1.x=__float2bfloat16_rn(v.z-__bfloat162float(hz));
                             q1.y=__float2bfloat16_rn(v.w-__bfloat162float(hw)); pl[1]=q1;
        }
      } else {
#pragma unroll
        for (int t=0;t<B_F4;t++){
          int idx = tid + t*THREADS;
          int kk = idx/(BN/4), n4 = idx%(BN/4);
          float4 v = stB[t];
          float a4[4] = {v.x,v.y,v.z,v.w};
#pragma unroll
          for (int j=0;j<4;j++){
            __nv_bfloat16 h = __float2bfloat16_rn(a4[j]);
            BsH[n4*4+j][kk] = h;
            BsL[n4*4+j][kk] = __float2bfloat16_rn(a4[j]-__bfloat162float(h));
          }
        }
      }
    };

    int r8 = lane&7, s1 = (lane>>3)&1, s2 = lane>>4;

    auto compute = [&](int kk){
      unsigned ah[4][4], al[4][4], bh[2][4], bl[2][4];
#pragma unroll
      for (int mt=0;mt<4;mt++){
        int row = wm0 + mt*16 + r8 + s1*8;
        int col = kk + s2*8;
        ldsm4(ah[mt], &AsH[row][col]);
        ldsm4(al[mt], &AsL[row][col]);
      }
#pragma unroll
      for (int np=0;np<2;np++){
        int row = wn0 + np*16 + r8 + s2*8;
        int col = kk + s1*8;
        ldsm4(bh[np], &BsH[row][col]);
        ldsm4(bl[np], &BsL[row][col]);
      }
#pragma unroll
      for (int mt=0;mt<4;mt++)
#pragma unroll
        for (int nt=0;nt<4;nt++){
          unsigned b0h = bh[nt>>1][(nt&1)*2], b1h = bh[nt>>1][(nt&1)*2+1];
          unsigned b0l = bl[nt>>1][(nt&1)*2], b1l = bl[nt>>1][(nt&1)*2+1];
          mma16816(acc[mt][nt], ah[mt], b0h, b1h);   // hi*hi
          mma16816(acc[mt][nt], al[mt], b0h, b1h);   // lo*hi
          mma16816(acc[mt][nt], ah[mt], b0l, b1l);   // hi*lo
        }
    };

    int nk = (K+31)/32;
    ldA(0); ldB(0);
    stoA(); stoB();
    __syncthreads();
    for (int kt=0; kt<nk; kt++){
      if (kt+1<nk){ ldA((kt+1)*32); ldB((kt+1)*32); }
      compute(0);
      compute(16);
      __syncthreads();
      if (kt+1<nk){ stoA(); stoB(); __syncthreads(); }
    }

    // epilogue
    int gid = lane>>2, tq = lane&3;
#pragma unroll
    for (int mt=0;mt<4;mt++)
#pragma unroll
      for (int h=0;h<2;h++){
        int gm = row0 + wm0 + mt*16 + gid + h*8;
        if (gm>=M) continue;
        long long base = (long long)gm*ldc;
#pragma unroll
        for (int nt=0;nt<4;nt++){
          int gn = col0 + wn0 + nt*8 + tq*2;
          if (gn>=N) continue;
          float v0 = alpha*acc[mt][nt][h*2+0];
          float v1 = alpha*acc[mt][nt][h*2+1];
          if (bias){ v0 += bias[gn]; if (gn+1<N) v1 += bias[gn+1]; }
          if (Cr)  { v0 += Cr[base+gn]; if (gn+1<N) v1 += Cr[base+gn+1]; }
          if (gn+1<N){ float2 st; st.x=v0; st.y=v1; *(float2*)&C[base+gn]=st; }
          else C[base+gn]=v0;
        }
      }
}

// ---------------- fp32 fallback GEMM (small M: final head) ----------------
template<int BM,int BN,int TM,int TN>
__global__ __launch_bounds__((BM/TM)*(BN/TN))
void sgemm_v(const float* __restrict__ A, const float* __restrict__ B,
             const float* __restrict__ bias, const float* __restrict__ Cin,
             float* __restrict__ C,
             int M,int N,int K,int lda,int ldb,int ldc,
             long long sA,int aShift, long long sB,int bShift,int bMask,
             long long sCin,long long sC,int transB,float alpha,int addC)
{
    constexpr int BK=16;
    constexpr int THREADS=(BM/TM)*(BN/TN);
    __shared__ float As[2][BK][BM+4];
    __shared__ float Bs[2][BK][BN+4];

    int z=blockIdx.z;
    A += (long long)(z>>aShift)*sA;
    B += (long long)((z>>bShift)&bMask)*sB;
    C += (long long)z*sC;
    const float* Cr = addC ? Cin+(long long)z*sCin : (const float*)0;

    int row0=blockIdx.y*BM, col0=blockIdx.x*BN;
    int tid=threadIdx.x;
    int tx=tid%(BN/TN), ty=tid/(BN/TN);

    float acc[TM][TN];
#pragma unroll
    for(int i=0;i<TM;i++)
#pragma unroll
      for(int j=0;j<TN;j++) acc[i][j]=0.f;

    float4 ra[2], rb[2];
    auto ldAg=[&](int k0){
#pragma unroll
      for(int t=0;t<2;t++){
        int idx=tid+t*THREADS; int mm=idx>>2; int c4=idx&3;
        int gm=row0+mm, gk=k0+c4*4;
        float4 v=make_float4(0.f,0.f,0.f,0.f);
        if(gm<M && gk<K) v=*(const float4*)&A[(long long)gm*lda+gk];
        ra[t]=v;
      }
    };
    auto stAs=[&](int buf){
#pragma unroll
      for(int t=0;t<2;t++){
        int idx=tid+t*THREADS; int mm=idx>>2; int c4=idx&3;
        As[buf][c4*4+0][mm]=ra[t].x; As[buf][c4*4+1][mm]=ra[t].y;
        As[buf][c4*4+2][mm]=ra[t].z; As[buf][c4*4+3][mm]=ra[t].w;
      }
    };
    auto ldBg=[&](int k0){
      if(!transB){
#pragma unroll
        for(int t=0;t<2;t++){
          int idx=tid+t*THREADS; int kk=idx/(BN/4); int n4=idx%(BN/4);
          int gk=k0+kk, gn=col0+n4*4;
          float4 v=make_float4(0.f,0.f,0.f,0.f);
          if(gk<K){
            if(gn+3<N) v=*(const float4*)&B[(long long)gk*ldb+gn];
            else {
              const float* p=&B[(long long)gk*ldb];
              if(gn  <N)v.x=p[gn];   if(gn+1<N)v.y=p[gn+1];
              if(gn+2<N)v.z=p[gn+2]; if(gn+3<N)v.w=p[gn+3];
            }
          }
          rb[t]=v;
        }
      } else {
#pragma unroll
        for(int t=0;t<2;t++){
          int idx=tid+t*THREADS; int nn=idx>>2; int c4=idx&3;
          int gn=col0+nn, gk=k0+c4*4;
          float4 v=make_float4(0.f,0.f,0.f,0.f);
          if(gn<N && gk<K) v=*(const float4*)&B[(long long)gn*ldb+gk];
          rb[t]=v;
        }
      }
    };
    auto stBs=[&](int buf){
      if(!transB){
#pragma unroll
        for(int t=0;t<2;t++){
          int idx=tid+t*THREADS; int kk=idx/(BN/4); int n4=idx%(BN/4);
          *(float4*)&Bs[buf][kk][n4*4]=rb[t];
        }
      } else {
#pragma unroll
        for(int t=0;t<2;t++){
          int idx=tid+t*THREADS; int nn=idx>>2; int c4=idx&3;
          Bs[buf][c4*4+0][nn]=rb[t].x; Bs[buf][c4*4+1][nn]=rb[t].y;
          Bs[buf][c4*4+2][nn]=rb[t].z; Bs[buf][c4*4+3][nn]=rb[t].w;
        }
      }
    };

    ldAg(0); ldBg(0); stAs(0); stBs(0);
    __syncthreads();
    int nk=(K+BK-1)/BK;
    for(int kt=0;kt<nk;kt++){
      int cur=kt&1;
      if(kt+1<nk){ ldAg((kt+1)*BK); ldBg((kt+1)*BK); }
#pragma unroll
      for(int kk=0;kk<BK;kk++){
        float a[TM], b[TN];
        *(float4*)&a[0]=*(float4*)&As[cur][kk][ty*TM];
        *(float4*)&b[0]=*(float4*)&Bs[cur][kk][tx*TN];
#pragma unroll
        for(int i=0;i<TM;i++)
#pragma unroll
          for(int j=0;j<TN;j++) acc[i][j]+=a[i]*b[j];
      }
      if(kt+1<nk){ stAs(cur^1); stBs(cur^1); __syncthreads(); }
    }

#pragma unroll
    for(int i=0;i<TM;i++){
      int gm=row0+ty*TM+i;
      if(gm>=M) continue;
      long long base=(long long)gm*ldc;
#pragma unroll
      for(int j=0;j<TN;j++){
        int gn=col0+tx*TN+j;
        if(gn>=N) continue;
        float v=alpha*acc[i][j];
        if(bias) v+=bias[gn];
        if(Cr)   v+=Cr[base+gn];
        C[base+gn]=v;
      }
    }
}

static inline void run_gemm(const float* A,const float* B,const float* bias,
                            const float* Cin,float* C,
                            int M,int N,int K,int lda,int ldb,int ldc,
                            long long sA,int aShift,long long sB,int bShift,int bMask,
                            long long sCin,long long sC,int batch,int transB,float alpha,int addC)
{
    if (M < 64) {
        dim3 grid((N+31)/32,(M+31)/32,batch);
        sgemm_v<32,32,4,4><<<grid,64>>>(A,B,bias,Cin,C,M,N,K,lda,ldb,ldc,
            sA,aShift,sB,bShift,bMask,sCin,sC,transB,alpha,addC);
    } else if (M >= 96) {
        dim3 grid((N+127)/128,(M+127)/128,batch);
        hgemm<128,128><<<grid,256>>>(A,B,bias,Cin,C,M,N,K,lda,ldb,ldc,
            sA,aShift,sB,bShift,bMask,sCin,sC,transB,alpha,addC);
    } else {
        dim3 grid((N+127)/128,(M+63)/64,batch);
        hgemm<64,128><<<grid,128>>>(A,B,bias,Cin,C,M,N,K,lda,ldb,ldc,
            sA,aShift,sB,bShift,bMask,sCin,sC,transB,alpha,addC);
    }
}

// ---------------- elementwise kernels ----------------
__global__ void patch_gather_kernel(const float* __restrict__ img, float* __restrict__ out) {
    int idx = blockIdx.x*blockDim.x + threadIdx.x;
    int total = BATCH*NPATCH*PK;
    if (idx >= total) return;
    int k = idx % PK;
    int p = (idx / PK) % NPATCH;
    int b = idx / (PK*NPATCH);
    int c  = k % 3;
    int pj = (k/3) % 16;
    int pi = k / 48;
    int i = p / 14, j = p % 14;
    out[idx] = img[(((long long)b*3 + c)*224 + (i*16+pi))*224 + (j*16+pj)];
}

__global__ void assemble_x_kernel(const float* __restrict__ xp, const float* __restrict__ cls,
                                  float* __restrict__ x) {
    int idx = blockIdx.x*blockDim.x + threadIdx.x;
    int total = BATCH*SEQ*DIM;
    if (idx >= total) return;
    int d = idx % DIM;
    int m = (idx / DIM) % SEQ;
    int b = idx / (DIM*SEQ);
    x[idx] = (m == 0) ? cls[d] : xp[((long long)b*NPATCH + (m-1))*DIM + d];
}

__global__ void rms_part_kernel(const float* __restrict__ x, float* __restrict__ red) {
    int b = blockIdx.y, ch = blockIdx.x;
    const int per_batch = SEQ*DIM;
    const int chunk = per_batch/32;
    const float4* p = (const float4*)(x + (long long)b*per_batch + ch*chunk);
    float s = 0.f;
    for (int i = threadIdx.x; i < chunk/4; i += 256) {
        float4 v = p[i];
        s += v.x*v.x + v.y*v.y + v.z*v.z + v.w*v.w;
    }
    __shared__ float sm[256];
    sm[threadIdx.x] = s; __syncthreads();
    for (int o = 128; o > 0; o >>= 1) { if (threadIdx.x < o) sm[threadIdx.x] += sm[threadIdx.x+o]; __syncthreads(); }
    if (threadIdx.x == 0) red[b*32 + ch] = sm[0];
}
__global__ void rms_fin_kernel(const float* __restrict__ red, float* __restrict__ fac) {
    int b = threadIdx.x / 32, lane = threadIdx.x % 32;
    float v = red[b*32 + lane];
    for (int o = 16; o; o >>= 1) v += __shfl_xor_sync(0xffffffffu, v, o);
    if (lane == 0) fac[b] = sqrtf((float)(SEQ*DIM) / v);
}

__global__ void rms_apply_kernel(float* __restrict__ x, const float* __restrict__ fac,
                                 const float* __restrict__ scale) {
    int idx = blockIdx.x*blockDim.x + threadIdx.x;
    const int per4 = SEQ*DIM/4;
    int total = BATCH*per4;
    if (idx >= total) return;
    int b = idx / per4, s4 = idx % per4;
    float f = fac[b];
    float4 v = ((float4*)x)[idx];
    float4 sc = ((const float4*)scale)[s4];
    v.x *= f*sc.x; v.y *= f*sc.y; v.z *= f*sc.z; v.w *= f*sc.w;
    ((float4*)x)[idx] = v;
}

__global__ void rope_kernel(float* __restrict__ q, float* __restrict__ k,
                            int Z, int M, int D, float cc) {
    int half = D / 2;
    long long total = (long long)Z * M * half;
    long long idx = (long long)blockIdx.x*blockDim.x + threadIdx.x;
    if (idx >= total) return;
    int i = (int)(idx % half);
    int m = (int)((idx / half) % M);
    long long z = idx / ((long long)half * M);
    float theta = exp2f(cc * ((float)i - 1.f));
    float ang = (float)m * theta;
    float s, c;
    sincosf(ang, &s, &c);
    long long base = ((z*M) + m) * (long long)D + 2*i;
    float xe, xo;
    xe = q[base]; xo = q[base+1];
    q[base] = xe*c + xo*s;  q[base+1] = -xe*s + xo*c;
    xe = k[base]; xo = k[base+1];
    k[base] = xe*c + xo*s;  k[base+1] = -xe*s + xo*c;
}

__global__ void softmax_kernel(float* __restrict__ s, int rows, int L, int ld) {
    int warp = (blockIdx.x*blockDim.x + threadIdx.x) / 32;
    int lane = threadIdx.x % 32;
    if (warp >= rows) return;
    float* row = s + (long long)warp * ld;
    float mx = -1e30f;
    for (int i = lane; i < L; i += 32) mx = fmaxf(mx, row[i]);
    for (int o = 16; o; o >>= 1) mx = fmaxf(mx, __shfl_xor_sync(0xffffffffu, mx, o));
    float sum = 0.f;
    for (int i = lane; i < L; i += 32) { float e = __expf(row[i]-mx); row[i] = e; sum += e; }
    for (int o = 16; o; o >>= 1) sum += __shfl_xor_sync(0xffffffffu, sum, o);
    float inv = 1.f / sum;
    for (int i = lane; i < ld; i += 32) row[i] = (i < L) ? row[i]*inv : 0.f;
}

__global__ void attn_reduce_kernel(const float* __restrict__ part,
                                   const float* __restrict__ bias,
                                   float* __restrict__ x) {
    int idx = blockIdx.x*blockDim.x + threadIdx.x;
    const int D4 = DIM/4;
    int total = BATCH*SEQ*D4;
    if (idx >= total) return;
    int d4 = idx % D4;
    int m  = (idx / D4) % SEQ;
    int b  = idx / (D4*SEQ);
    float4 acc = ((float4*)x)[idx];
    float4 bb = ((const float4*)bias)[d4];
    acc.x += bb.x; acc.y += bb.y; acc.z += bb.z; acc.w += bb.w;
#pragma unroll
    for (int h = 0; h < HEADS; h++) {
        float4 p = ((const float4*)part)[((long long)(b*HEADS+h)*SEQ + m)*D4 + d4];
        acc.x += p.x; acc.y += p.y; acc.z += p.z; acc.w += p.w;
    }
    ((float4*)x)[idx] = acc;
}

__global__ void x_to_y_kernel(const float* __restrict__ x, float* __restrict__ y) {
    int idx = blockIdx.x*blockDim.x + threadIdx.x;
    int total = BATCH*CDIM*TDIM;
    if (idx >= total) return;
    int t = idx % TDIM;
    int c = (idx / TDIM) % CDIM;
    int b = idx / (TDIM*CDIM);
    int f = t / SEQ, mm = t % SEQ;
    y[idx] = x[((long long)b*SEQ + mm)*DIM + c*8 + f];
}

__global__ void y_to_x_kernel(const float* __restrict__ y, float* __restrict__ x) {
    int idx = blockIdx.x*blockDim.x + threadIdx.x;
    int total = BATCH*SEQ*DIM;
    if (idx >= total) return;
    int d  = idx % DIM;
    int mm = (idx / DIM) % SEQ;
    int b  = idx / (DIM*SEQ);
    int c = d >> 3, f = d & 7;
    x[idx] = y[((long long)b*CDIM + c)*TDIM + f*SEQ + mm];
}

__global__ void cls_ln_kernel(const float* __restrict__ x, const float* __restrict__ g,
                              const float* __restrict__ be, float* __restrict__ out) {
    int b = blockIdx.x, t = threadIdx.x;
    const float* row = x + (long long)b*SEQ*DIM;
    __shared__ float red[256];
    float s = 0.f;
    for (int i = t; i < DIM; i += 256) s += row[i];
    red[t] = s; __syncthreads();
    for (int o = 128; o > 0; o >>= 1) { if (t < o) red[t] += red[t+o]; __syncthreads(); }
    float mu = red[0] / DIM; __syncthreads();
    float v = 0.f;
    for (int i = t; i < DIM; i += 256) { float d = row[i]-mu; v += d*d; }
    red[t] = v; __syncthreads();
    for (int o = 128; o > 0; o >>= 1) { if (t < o) red[t] += red[t+o]; __syncthreads(); }
    float inv = rsqrtf(red[0]/DIM + 1e-5f);
    for (int i = t; i < DIM; i += 256) out[b*DIM + i] = (row[i]-mu)*inv*g[i] + be[i];
}

static inline int nblk(long long n, int t) { return (int)((n + t - 1) / t); }

extern "C" void kernel_launch(void* const* d_in, const int* in_sizes, int n_in,
                              void* d_out, int out_size) {
    const float* img       = (const float*)d_in[0];
    const float* patch_W   = (const float*)d_in[1];
    const float* patch_b   = (const float*)d_in[2];
    const float* cls_token = (const float*)d_in[3];
    const float* rms_scale = (const float*)d_in[4];
    const float* Wq        = (const float*)d_in[5];
    const float* Wk        = (const float*)d_in[6];
    const float* Wv        = (const float*)d_in[7];
    const float* attn_W    = (const float*)d_in[8];
    const float* attn_b    = (const float*)d_in[9];
    const float* tWq       = (const float*)d_in[10];
    const float* tWk       = (const float*)d_in[11];
    const float* tWv       = (const float*)d_in[12];
    const float* ln_g      = (const float*)d_in[13];
    const float* ln_b      = (const float*)d_in[14];
    const float* head_W    = (const float*)d_in[15];
    const float* head_b    = (const float*)d_in[16];
    float* out = (float*)d_out;

    float *ppat,*pxp,*px,*pq,*pk,*pv,*ps,*po,*pot,*py,*ptq,*ptk,*ptv,*pts,*pf,*pred,*pcls;
    cudaGetSymbolAddress((void**)&ppat, g_patches);
    cudaGetSymbolAddress((void**)&pxp,  g_xp);
    cudaGetSymbolAddress((void**)&px,   g_x);
    cudaGetSymbolAddress((void**)&pq,   g_q);
    cudaGetSymbolAddress((void**)&pk,   g_k);
    cudaGetSymbolAddress((void**)&pv,   g_v);
    cudaGetSymbolAddress((void**)&ps,   g_sc);
    cudaGetSymbolAddress((void**)&po,   g_o);
    cudaGetSymbolAddress((void**)&pot,  g_ot);
    cudaGetSymbolAddress((void**)&py,   g_y);
    cudaGetSymbolAddress((void**)&ptq,  g_tq);
    cudaGetSymbolAddress((void**)&ptk,  g_tk);
    cudaGetSymbolAddress((void**)&ptv,  g_tv);
    cudaGetSymbolAddress((void**)&pts,  g_ts);
    cudaGetSymbolAddress((void**)&pf,   g_fac);
    cudaGetSymbolAddress((void**)&pred, g_red);
    cudaGetSymbolAddress((void**)&pcls, g_cls);

    const long long sXB  = (long long)SEQ*DIM;
    const long long sQH  = (long long)SEQ*DIM;
    const long long sSSp = (long long)SEQ*SEQP;
    const long long sY   = (long long)CDIM*TDIM;
    const long long sTS  = (long long)CDIM*CDIM;
    const int ALLB = 0x7fffffff;
    const float scale1 = (float)(1.0/sqrt(512.0));
    const float scale2 = (float)(1.0/sqrt(1576.0));
    const float cc1 = (float)(-2.0*log2(10000.0)/512.0);
    const float cc2 = (float)(-2.0*log2(10000.0)/1576.0);

    // ---- patch embedding ----
    patch_gather_kernel<<<nblk((long long)BATCH*NPATCH*PK,256),256>>>(img, ppat);
    run_gemm(ppat, patch_W, patch_b, 0, pxp,
             BATCH*NPATCH, DIM, PK, PK, DIM, DIM,
             0,0, 0,0,0, 0,0, 1, 0, 1.f, 0);
    assemble_x_kernel<<<nblk((long long)BATCH*SEQ*DIM,256),256>>>(pxp, cls_token, px);

    for (int l = 0; l < 2; l++) {
        const float* scale_l = rms_scale + (long long)l*SEQ*DIM;

        // rmsnorm #1
        rms_part_kernel<<<dim3(32,BATCH),256>>>(px, pred);
        rms_fin_kernel<<<1,256>>>(pred, pf);
        rms_apply_kernel<<<nblk((long long)BATCH*SEQ*DIM/4,256),256>>>(px, pf, scale_l);

        // QKV: z = b*8+h (64 batches)
        run_gemm(px, Wq + (long long)l*HEADS*DIM*DIM, 0, 0, pq,
                 SEQ, DIM, DIM, DIM, DIM, DIM,
                 sXB, 3, (long long)DIM*DIM, 0, 7, 0, sQH, BATCH*HEADS, 0, 1.f, 0);
        run_gemm(px, Wk + (long long)l*HEADS*DIM*DIM, 0, 0, pk,
                 SEQ, DIM, DIM, DIM, DIM, DIM,
                 sXB, 3, (long long)DIM*DIM, 0, 7, 0, sQH, BATCH*HEADS, 0, 1.f, 0);
        run_gemm(px, Wv + (long long)l*HEADS*DIM*DIM, 0, 0, pv,
                 SEQ, DIM, DIM, DIM, DIM, DIM,
                 sXB, 3, (long long)DIM*DIM, 0, 7, 0, sQH, BATCH*HEADS, 0, 1.f, 0);

        rope_kernel<<<nblk((long long)BATCH*HEADS*SEQ*(DIM/2),256),256>>>(pq, pk, BATCH*HEADS, SEQ, DIM, cc1);

        // s = q @ k^T * scale (ldc padded to 208)
        run_gemm(pq, pk, 0, 0, ps,
                 SEQ, SEQ, DIM, DIM, DIM, SEQP,
                 sQH, 0, sQH, 0, ALLB, 0, sSSp, BATCH*HEADS, 1, scale1, 0);
        softmax_kernel<<<nblk((long long)BATCH*HEADS*SEQ*32,256),256>>>(ps, BATCH*HEADS*SEQ, SEQ, SEQP);

        // o = p @ v  (K padded to 208; pad cols of p are zero)
        run_gemm(ps, pv, 0, 0, po,
                 SEQ, DIM, SEQP, SEQP, DIM, DIM,
                 sSSp, 0, sQH, 0, ALLB, 0, sQH, BATCH*HEADS, 0, 1.f, 0);

        // per-head output-proj partials
        run_gemm(po, attn_W + (long long)l*HEADS*DIM*DIM, 0, 0, pot,
                 SEQ, DIM, DIM, DIM, DIM, DIM,
                 sQH, 0, (long long)DIM*DIM, 0, 7, 0, sQH, BATCH*HEADS, 0, 1.f, 0);
        attn_reduce_kernel<<<nblk((long long)BATCH*SEQ*DIM/4,256),256>>>(pot, attn_b + l*DIM, px);

        // rmsnorm #2
        rms_part_kernel<<<dim3(32,BATCH),256>>>(px, pred);
        rms_fin_kernel<<<1,256>>>(pred, pf);
        rms_apply_kernel<<<nblk((long long)BATCH*SEQ*DIM/4,256),256>>>(px, pf, scale_l);

        // token-mixing attention
        x_to_y_kernel<<<nblk((long long)BATCH*CDIM*TDIM,256),256>>>(px, py);

        run_gemm(py, tWq + (long long)l*TDIM*TDIM, 0, 0, ptq,
                 CDIM, TDIM, TDIM, TDIM, TDIM, TDIM,
                 sY, 0, 0, 0, 0, 0, sY, BATCH, 0, 1.f, 0);
        run_gemm(py, tWk + (long long)l*TDIM*TDIM, 0, 0, ptk,
                 CDIM, TDIM, TDIM, TDIM, TDIM, TDIM,
                 sY, 0, 0, 0, 0, 0, sY, BATCH, 0, 1.f, 0);
        run_gemm(py, tWv + (long long)l*TDIM*TDIM, 0, 0, ptv,
                 CDIM, TDIM, TDIM, TDIM, TDIM, TDIM,
                 sY, 0, 0, 0, 0, 0, sY, BATCH, 0, 1.f, 0);

        rope_kernel<<<nblk((long long)BATCH*CDIM*(TDIM/2),256),256>>>(ptq, ptk, BATCH, CDIM, TDIM, cc2);

        run_gemm(ptq, ptk, 0, 0, pts,
                 CDIM, CDIM, TDIM, TDIM, TDIM, CDIM,
                 sY, 0, sY, 0, ALLB, 0, sTS, BATCH, 1, scale2, 0);
        softmax_kernel<<<nblk((long long)BATCH*CDIM*32,256),256>>>(pts, BATCH*CDIM, CDIM, CDIM);

        // y += p @ tv
        run_gemm(pts, ptv, 0, py, py,
                 CDIM, TDIM, CDIM, CDIM, TDIM, TDIM,
                 sTS, 0, sY, 0, ALLB, sY, sY, BATCH, 0, 1.f, 1);

        y_to_x_kernel<<<nblk((long long)BATCH*SEQ*DIM,256),256>>>(py, px);
    }

    // ---- final: cls layernorm + head (fp32 path, M=8) ----
    cls_ln_kernel<<<BATCH,256>>>(px, ln_g, ln_b, pcls);
    run_gemm(pcls, head_W, head_b, 0, out,
             BATCH, NCLS, DIM, DIM, NCLS, NCLS,
             0,0, 0,0,0, 0,0, 1, 0, 1.f, 0);
}

// round 9
// speedup vs baseline: 6.1003x; 1.7975x over previous
#include <cuda_runtime.h>
#include <cuda_bf16.h>
#include <math.h>
#include <stdint.h>

#define BATCH 8
#define HEADS 8
#define DIM 512
#define SEQ 197
#define SEQP 208
#define NPATCH 196
#define PK 768
#define CDIM 64
#define TDIM 1576
#define NCLS 1000

// ---------------- fp32 scratch ----------------
__device__ float g_xp[BATCH*NPATCH*DIM];
__device__ float g_x[BATCH*SEQ*DIM];
__device__ float g_q[BATCH*HEADS*SEQ*DIM];
__device__ float g_k[BATCH*HEADS*SEQ*DIM];
__device__ float g_v[BATCH*HEADS*SEQ*DIM];
__device__ float g_sc[BATCH*HEADS*SEQ*SEQP];
__device__ float g_o[BATCH*HEADS*SEQ*DIM];
__device__ float g_ot[BATCH*SEQ*HEADS*DIM];
__device__ float g_y[BATCH*CDIM*TDIM];
__device__ float g_tq[BATCH*CDIM*TDIM];
__device__ float g_tk[BATCH*CDIM*TDIM];
__device__ float g_tv[BATCH*CDIM*TDIM];
__device__ float g_ts[BATCH*CDIM*CDIM];
__device__ float g_fac[BATCH];
__device__ float g_red[BATCH*32];
__device__ float g_cls[BATCH*DIM];

// ---------------- bf16 hi/lo split operands (K-major) ----------------
__device__ __nv_bfloat16 g_path_h[BATCH*NPATCH*PK],  g_path_l[BATCH*NPATCH*PK];
__device__ __nv_bfloat16 g_xh[BATCH*SEQ*DIM],        g_xl[BATCH*SEQ*DIM];
__device__ __nv_bfloat16 g_qh[BATCH*HEADS*SEQ*DIM],  g_ql[BATCH*HEADS*SEQ*DIM];
__device__ __nv_bfloat16 g_kh[BATCH*HEADS*SEQ*DIM],  g_kl[BATCH*HEADS*SEQ*DIM];
__device__ __nv_bfloat16 g_ph[BATCH*HEADS*SEQ*SEQP], g_pl[BATCH*HEADS*SEQ*SEQP];
__device__ __nv_bfloat16 g_oh[BATCH*HEADS*SEQ*DIM],  g_ol[BATCH*HEADS*SEQ*DIM];
__device__ __nv_bfloat16 g_yh[BATCH*CDIM*TDIM],      g_yl[BATCH*CDIM*TDIM];
__device__ __nv_bfloat16 g_tqh[BATCH*CDIM*TDIM],     g_tql[BATCH*CDIM*TDIM];
__device__ __nv_bfloat16 g_tkh[BATCH*CDIM*TDIM],     g_tkl[BATCH*CDIM*TDIM];
__device__ __nv_bfloat16 g_tsh[BATCH*CDIM*CDIM],     g_tsl[BATCH*CDIM*CDIM];
// weights
__device__ __nv_bfloat16 g_pwh[DIM*PK],         g_pwl[DIM*PK];
__device__ __nv_bfloat16 g_wqh[16*DIM*DIM],     g_wql[16*DIM*DIM];
__device__ __nv_bfloat16 g_wkh[16*DIM*DIM],     g_wkl[16*DIM*DIM];
__device__ __nv_bfloat16 g_wvh[16*DIM*DIM],     g_wvl[16*DIM*DIM];
__device__ __nv_bfloat16 g_awh[16*DIM*DIM],     g_awl[16*DIM*DIM];
__device__ __nv_bfloat16 g_twqh[2*TDIM*TDIM],   g_twql[2*TDIM*TDIM];
__device__ __nv_bfloat16 g_twkh[2*TDIM*TDIM],   g_twkl[2*TDIM*TDIM];
__device__ __nv_bfloat16 g_twvh[2*TDIM*TDIM],   g_twvl[2*TDIM*TDIM];
__device__ __nv_bfloat16 g_vth[64*DIM*SEQP],    g_vtl[64*DIM*SEQP];
__device__ __nv_bfloat16 g_tvth[8*TDIM*CDIM],   g_tvtl[8*TDIM*CDIM];

// ---------------- helpers ----------------
__device__ __forceinline__ void cvt4(float4 v, uint2 &h, uint2 &l){
    __nv_bfloat16 ax=__float2bfloat16_rn(v.x), ay=__float2bfloat16_rn(v.y);
    __nv_bfloat16 az=__float2bfloat16_rn(v.z), aw=__float2bfloat16_rn(v.w);
    __nv_bfloat162 h0; h0.x=ax; h0.y=ay;
    __nv_bfloat162 h1; h1.x=az; h1.y=aw;
    h.x=*(unsigned*)&h0; h.y=*(unsigned*)&h1;
    __nv_bfloat162 l0; l0.x=__float2bfloat16_rn(v.x-__bfloat162float(ax));
                       l0.y=__float2bfloat16_rn(v.y-__bfloat162float(ay));
    __nv_bfloat162 l1; l1.x=__float2bfloat16_rn(v.z-__bfloat162float(az));
                       l1.y=__float2bfloat16_rn(v.w-__bfloat162float(aw));
    l.x=*(unsigned*)&l0; l.y=*(unsigned*)&l1;
}
__device__ __forceinline__ void cvt2(float a, float b, uint32_t &h, uint32_t &l){
    __nv_bfloat16 ha=__float2bfloat16_rn(a), hb=__float2bfloat16_rn(b);
    __nv_bfloat162 H; H.x=ha; H.y=hb; h=*(uint32_t*)&H;
    __nv_bfloat162 L; L.x=__float2bfloat16_rn(a-__bfloat162float(ha));
                      L.y=__float2bfloat16_rn(b-__bfloat162float(hb)); l=*(uint32_t*)&L;
}
__device__ __forceinline__ void cvt1(float a, __nv_bfloat16 &h, __nv_bfloat16 &l){
    h=__float2bfloat16_rn(a);
    l=__float2bfloat16_rn(a-__bfloat162float(h));
}
__device__ __forceinline__ void ldsm4(unsigned r[4], const __nv_bfloat16* p) {
    unsigned a = (unsigned)__cvta_generic_to_shared(p);
    asm volatile("ldmatrix.sync.aligned.m8n8.x4.shared.b16 {%0,%1,%2,%3}, [%4];"
                 : "=r"(r[0]), "=r"(r[1]), "=r"(r[2]), "=r"(r[3]) : "r"(a));
}
__device__ __forceinline__ void mma16816(float c[4], const unsigned a[4],
                                         unsigned b0, unsigned b1) {
    asm volatile("mma.sync.aligned.m16n8k16.row.col.f32.bf16.bf16.f32 "
                 "{%0,%1,%2,%3}, {%4,%5,%6,%7}, {%8,%9}, {%0,%1,%2,%3};"
                 : "+f"(c[0]), "+f"(c[1]), "+f"(c[2]), "+f"(c[3])
                 : "r"(a[0]), "r"(a[1]), "r"(a[2]), "r"(a[3]), "r"(b0), "r"(b1));
}

// ================= bf16 split GEMM (pre-split operands, double-buffered) =================
// C[z] = alpha * A[(z>>aShift)] @ B[(z>>bShift)&bMask]^T (+bias) (+Cin[z])
// A: bf16 hi/lo [M][lda] K-major; B: bf16 hi/lo [N][ldb] K-major. lda/ldb/K % 8 == 0.
template<int BM>
__global__ __launch_bounds__(BM*2)
void hgemm2(const __nv_bfloat16* __restrict__ Ah, const __nv_bfloat16* __restrict__ Al,
            const __nv_bfloat16* __restrict__ Bh, const __nv_bfloat16* __restrict__ Bl,
            const float* __restrict__ bias, const float* __restrict__ Cin,
            float* __restrict__ C,
            int M, int N, int K, int lda, int ldb, int ldc,
            long long sA, int aShift, long long sB, int bShift, int bMask,
            long long sCin, long long sC, float alpha, int addC)
{
    constexpr int WARPS_M = BM/64;
    constexpr int THREADS = BM*2;
    constexpr int B_V = 512/THREADS;
    constexpr int SHALF = (2*BM + 256)*40;     // halves per stage
    const int OFF_AH = 0, OFF_AL = BM*40, OFF_BH = 2*BM*40, OFF_BL = 2*BM*40 + 128*40;
    extern __shared__ __align__(16) __nv_bfloat16 sm[];

    int z = blockIdx.z;
    long long ao = (long long)(z >> aShift) * sA;
    long long bo = (long long)((z >> bShift) & bMask) * sB;
    Ah += ao; Al += ao; Bh += bo; Bl += bo;
    C += (long long)z * sC;
    const float* Cr = addC ? Cin + (long long)z * sCin : (const float*)0;

    int row0 = blockIdx.y*BM, col0 = blockIdx.x*128;
    int tid = threadIdx.x, lane = tid & 31, warp = tid >> 5;
    int wm0 = (warp % WARPS_M)*64;
    int wn0 = (warp / WARPS_M)*32;

    float acc[4][4][4];
#pragma unroll
    for (int i=0;i<4;i++)
#pragma unroll
      for (int j=0;j<4;j++)
#pragma unroll
        for (int t=0;t<4;t++) acc[i][j][t]=0.f;

    uint4 rah[2], ral[2], rbh[B_V], rbl[B_V];

    auto ldA = [&](int k0){
#pragma unroll
        for (int t = 0; t < 2; t++){
            int idx = tid + t*THREADS;
            int row = idx >> 2, k8 = idx & 3;
            int gm = row0 + row, gk = k0 + k8*8;
            uint4 zz = make_uint4(0,0,0,0);
            rah[t] = zz; ral[t] = zz;
            if (gm < M && gk < K){
                rah[t] = *(const uint4*)&Ah[(long long)gm*lda + gk];
                ral[t] = *(const uint4*)&Al[(long long)gm*lda + gk];
            }
        }
    };
    auto ldB = [&](int k0){
#pragma unroll
        for (int t = 0; t < B_V; t++){
            int idx = tid + t*THREADS;
            int row = idx >> 2, k8 = idx & 3;
            int gn = col0 + row, gk = k0 + k8*8;
            uint4 zz = make_uint4(0,0,0,0);
            rbh[t] = zz; rbl[t] = zz;
            if (gn < N && gk < K){
                rbh[t] = *(const uint4*)&Bh[(long long)gn*ldb + gk];
                rbl[t] = *(const uint4*)&Bl[(long long)gn*ldb + gk];
            }
        }
    };
    auto stA = [&](int st){
#pragma unroll
        for (int t = 0; t < 2; t++){
            int idx = tid + t*THREADS;
            int row = idx >> 2, k8 = idx & 3;
            *(uint4*)&sm[st*SHALF + OFF_AH + row*40 + k8*8] = rah[t];
            *(uint4*)&sm[st*SHALF + OFF_AL + row*40 + k8*8] = ral[t];
        }
    };
    auto stB = [&](int st){
#pragma unroll
        for (int t = 0; t < B_V; t++){
            int idx = tid + t*THREADS;
            int row = idx >> 2, k8 = idx & 3;
            *(uint4*)&sm[st*SHALF + OFF_BH + row*40 + k8*8] = rbh[t];
            *(uint4*)&sm[st*SHALF + OFF_BL + row*40 + k8*8] = rbl[t];
        }
    };

    int r8 = lane&7, s1 = (lane>>3)&1, s2 = lane>>4;
    auto compute = [&](int st, int kk){
        unsigned ah[4][4], al[4][4], bh[2][4], bl[2][4];
#pragma unroll
        for (int mt=0;mt<4;mt++){
            int row = wm0 + mt*16 + r8 + s1*8;
            int col = kk + s2*8;
            ldsm4(ah[mt], &sm[st*SHALF + OFF_AH + row*40 + col]);
            ldsm4(al[mt], &sm[st*SHALF + OFF_AL + row*40 + col]);
        }
#pragma unroll
        for (int np=0;np<2;np++){
            int row = wn0 + np*16 + r8 + s2*8;
            int col = kk + s1*8;
            ldsm4(bh[np], &sm[st*SHALF + OFF_BH + row*40 + col]);
            ldsm4(bl[np], &sm[st*SHALF + OFF_BL + row*40 + col]);
        }
#pragma unroll
        for (int mt=0;mt<4;mt++)
#pragma unroll
            for (int nt=0;nt<4;nt++){
                unsigned b0h = bh[nt>>1][(nt&1)*2], b1h = bh[nt>>1][(nt&1)*2+1];
                unsigned b0l = bl[nt>>1][(nt&1)*2], b1l = bl[nt>>1][(nt&1)*2+1];
                mma16816(acc[mt][nt], ah[mt], b0h, b1h);
                mma16816(acc[mt][nt], al[mt], b0h, b1h);
                mma16816(acc[mt][nt], ah[mt], b0l, b1l);
            }
    };

    int nk = (K + 31) / 32;
    ldA(0); ldB(0);
    stA(0); stB(0);
    __syncthreads();
    for (int kt = 0; kt < nk; kt++){
        int cur = kt & 1;
        if (kt + 1 < nk){ ldA((kt+1)*32); ldB((kt+1)*32); }
        compute(cur, 0);
        compute(cur, 16);
        if (kt + 1 < nk){ stA(cur^1); stB(cur^1); }
        __syncthreads();
    }

    // epilogue (layout identical to R4-verified mapping)
    int gid = lane>>2, tq = lane&3;
#pragma unroll
    for (int mt=0;mt<4;mt++)
#pragma unroll
      for (int h=0;h<2;h++){
        int gm = row0 + wm0 + mt*16 + gid + h*8;
        if (gm>=M) continue;
        long long base = (long long)gm*ldc;
#pragma unroll
        for (int nt=0;nt<4;nt++){
          int gn = col0 + wn0 + nt*8 + tq*2;
          if (gn>=N) continue;
          float v0 = alpha*acc[mt][nt][h*2+0];
          float v1 = alpha*acc[mt][nt][h*2+1];
          if (bias){ v0 += bias[gn]; if (gn+1<N) v1 += bias[gn+1]; }
          if (Cr)  { v0 += Cr[base+gn]; if (gn+1<N) v1 += Cr[base+gn+1]; }
          if (gn+1<N){ float2 st; st.x=v0; st.y=v1; *(float2*)&C[base+gn]=st; }
          else C[base+gn]=v0;
        }
      }
}

static void run_hgemm(const __nv_bfloat16* Ah, const __nv_bfloat16* Al,
                      const __nv_bfloat16* Bh, const __nv_bfloat16* Bl,
                      const float* bias, const float* Cin, float* C,
                      int M, int N, int K, int lda, int ldb, int ldc,
                      long long sA, int aShift, long long sB, int bShift, int bMask,
                      long long sCin, long long sC, int batch, float alpha, int addC)
{
    if (M >= 96) {
        constexpr int SM = 2*(2*128+256)*40*2;   // 81920 B
        cudaFuncSetAttribute(hgemm2<128>, cudaFuncAttributeMaxDynamicSharedMemorySize, SM);
        dim3 grid((N+127)/128, (M+127)/128, batch);
        hgemm2<128><<<grid, 256, SM>>>(Ah,Al,Bh,Bl,bias,Cin,C,M,N,K,lda,ldb,ldc,
            sA,aShift,sB,bShift,bMask,sCin,sC,alpha,addC);
    } else {
        constexpr int SM = 2*(2*64+256)*40*2;    // 61440 B
        cudaFuncSetAttribute(hgemm2<64>, cudaFuncAttributeMaxDynamicSharedMemorySize, SM);
        dim3 grid((N+127)/128, (M+63)/64, batch);
        hgemm2<64><<<grid, 128, SM>>>(Ah,Al,Bh,Bl,bias,Cin,C,M,N,K,lda,ldb,ldc,
            sA,aShift,sB,bShift,bMask,sCin,sC,alpha,addC);
    }
}

// ================= transpose-convert: fp32 [K][N] -> bf16 hi/lo [N][Kp] =================
__global__ void tconv(const float* __restrict__ in, __nv_bfloat16* __restrict__ oh,
                      __nv_bfloat16* __restrict__ ol,
                      int K, int N, int Kp, long long sIn, long long sOut)
{
    __shared__ float t[32][33];
    int z = blockIdx.z;
    const float* I = in + (long long)z * sIn;
    __nv_bfloat16* OH = oh + (long long)z * sOut;
    __nv_bfloat16* OL = ol + (long long)z * sOut;
    int kb = blockIdx.y * 32, nb = blockIdx.x * 32;
    for (int i = threadIdx.y; i < 32; i += 8) {
        int k = kb + i, n = nb + threadIdx.x;
        t[i][threadIdx.x] = (k < K && n < N) ? I[(long long)k*N + n] : 0.f;
    }
    __syncthreads();
    for (int i = threadIdx.y; i < 32; i += 8) {
        int n = nb + i, k = kb + threadIdx.x;
        if (n < N && k < Kp) {
            __nv_bfloat16 h, l; cvt1(t[threadIdx.x][i], h, l);
            OH[(long long)n*Kp + k] = h;
            OL[(long long)n*Kp + k] = l;
        }
    }
}

// ---------------- fp32 fallback GEMM (final head, M=8) ----------------
__global__ __launch_bounds__(64)
void sgemm_s(const float* __restrict__ A, const float* __restrict__ B,
             const float* __restrict__ bias, float* __restrict__ C,
             int M, int N, int K, int lda, int ldb, int ldc)
{
    constexpr int BK = 16;
    __shared__ float As[BK][36];
    __shared__ float Bs[BK][36];
    int row0 = blockIdx.y*32, col0 = blockIdx.x*32;
    int tid = threadIdx.x;
    int tx = tid % 8, ty = tid / 8;
    float acc[4][4];
#pragma unroll
    for (int i=0;i<4;i++)
#pragma unroll
      for (int j=0;j<4;j++) acc[i][j]=0.f;
    for (int k0 = 0; k0 < K; k0 += BK) {
        for (int e = tid; e < 32*BK/4; e += 64) {
            int mm = e >> 2, c4 = e & 3;
            int gm = row0+mm, gk = k0+c4*4;
            float4 v = make_float4(0.f,0.f,0.f,0.f);
            if (gm < M && gk < K) v = *(const float4*)&A[(long long)gm*lda+gk];
            As[c4*4+0][mm]=v.x; As[c4*4+1][mm]=v.y; As[c4*4+2][mm]=v.z; As[c4*4+3][mm]=v.w;
        }
        for (int e = tid; e < BK*8; e += 64) {
            int kk = e / 8, n4 = e % 8;
            int gk = k0+kk, gn = col0+n4*4;
            float4 v = make_float4(0.f,0.f,0.f,0.f);
            if (gk < K) {
                if (gn+3 < N) v = *(const float4*)&B[(long long)gk*ldb+gn];
                else {
                    const float* p = &B[(long long)gk*ldb];
                    if (gn<N)v.x=p[gn]; if (gn+1<N)v.y=p[gn+1];
                    if (gn+2<N)v.z=p[gn+2]; if (gn+3<N)v.w=p[gn+3];
                }
            }
            Bs[kk][n4*4+0]=v.x; Bs[kk][n4*4+1]=v.y; Bs[kk][n4*4+2]=v.z; Bs[kk][n4*4+3]=v.w;
        }
        __syncthreads();
#pragma unroll
        for (int kk = 0; kk < BK; kk++) {
            float a[4], b[4];
#pragma unroll
            for (int i=0;i<4;i++) a[i]=As[kk][ty*4+i];
#pragma unroll
            for (int j=0;j<4;j++) b[j]=Bs[kk][tx*4+j];
#pragma unroll
            for (int i=0;i<4;i++)
#pragma unroll
              for (int j=0;j<4;j++) acc[i][j]+=a[i]*b[j];
        }
        __syncthreads();
    }
#pragma unroll
    for (int i=0;i<4;i++){
        int gm = row0+ty*4+i;
        if (gm >= M) continue;
#pragma unroll
        for (int j=0;j<4;j++){
            int gn = col0+tx*4+j;
            if (gn >= N) continue;
            float v = acc[i][j];
            if (bias) v += bias[gn];
            C[(long long)gm*ldc+gn] = v;
        }
    }
}

// ---------------- elementwise kernels ----------------
__global__ void patch_gather2(const float* __restrict__ img,
                              __nv_bfloat16* __restrict__ oh, __nv_bfloat16* __restrict__ ol) {
    int idx = blockIdx.x*blockDim.x + threadIdx.x;
    int total = BATCH*NPATCH*PK;
    if (idx >= total) return;
    int k = idx % PK;
    int p = (idx / PK) % NPATCH;
    int b = idx / (PK*NPATCH);
    int c  = k % 3;
    int pj = (k/3) % 16;
    int pi = k / 48;
    int i = p / 14, j = p % 14;
    float v = img[(((long long)b*3 + c)*224 + (i*16+pi))*224 + (j*16+pj)];
    __nv_bfloat16 h, l; cvt1(v, h, l);
    oh[idx] = h; ol[idx] = l;
}

__global__ void assemble_x_kernel(const float* __restrict__ xp, const float* __restrict__ cls,
                                  float* __restrict__ x) {
    int idx = blockIdx.x*blockDim.x + threadIdx.x;
    int total = BATCH*SEQ*DIM;
    if (idx >= total) return;
    int d = idx % DIM;
    int m = (idx / DIM) % SEQ;
    int b = idx / (DIM*SEQ);
    x[idx] = (m == 0) ? cls[d] : xp[((long long)b*NPATCH + (m-1))*DIM + d];
}

__global__ void rms_part_kernel(const float* __restrict__ x, float* __restrict__ red) {
    int b = blockIdx.y, ch = blockIdx.x;
    const int per_batch = SEQ*DIM;
    const int chunk = per_batch/32;
    const float4* p = (const float4*)(x + (long long)b*per_batch + ch*chunk);
    float s = 0.f;
    for (int i = threadIdx.x; i < chunk/4; i += 256) {
        float4 v = p[i];
        s += v.x*v.x + v.y*v.y + v.z*v.z + v.w*v.w;
    }
    __shared__ float sm[256];
    sm[threadIdx.x] = s; __syncthreads();
    for (int o = 128; o > 0; o >>= 1) { if (threadIdx.x < o) sm[threadIdx.x] += sm[threadIdx.x+o]; __syncthreads(); }
    if (threadIdx.x == 0) red[b*32 + ch] = sm[0];
}
__global__ void rms_fin_kernel(const float* __restrict__ red, float* __restrict__ fac) {
    int b = threadIdx.x / 32, lane = threadIdx.x % 32;
    float v = red[b*32 + lane];
    for (int o = 16; o; o >>= 1) v += __shfl_xor_sync(0xffffffffu, v, o);
    if (lane == 0) fac[b] = sqrtf((float)(SEQ*DIM) / v);
}
// rms apply: x fp32 in-place AND split to xh/xl
__global__ void rms_apply2(float* __restrict__ x, const float* __restrict__ fac,
                           const float* __restrict__ scale,
                           uint2* __restrict__ xh, uint2* __restrict__ xl) {
    int idx = blockIdx.x*blockDim.x + threadIdx.x;
    const int per4 = SEQ*DIM/4;
    int total = BATCH*per4;
    if (idx >= total) return;
    int b = idx / per4, s4 = idx % per4;
    float f = fac[b];
    float4 v = ((float4*)x)[idx];
    float4 sc = ((const float4*)scale)[s4];
    v.x *= f*sc.x; v.y *= f*sc.y; v.z *= f*sc.z; v.w *= f*sc.w;
    ((float4*)x)[idx] = v;
    uint2 h, l; cvt4(v, h, l);
    xh[idx] = h; xl[idx] = l;
}

// RoPE: read fp32 q/k, emit split bf16
__global__ void rope2(const float* __restrict__ q, const float* __restrict__ k,
                      __nv_bfloat16* __restrict__ qh, __nv_bfloat16* __restrict__ ql,
                      __nv_bfloat16* __restrict__ kh, __nv_bfloat16* __restrict__ kl,
                      int Z, int M, int D, float cc) {
    int half = D / 2;
    long long total = (long long)Z * M * half;
    long long idx = (long long)blockIdx.x*blockDim.x + threadIdx.x;
    if (idx >= total) return;
    int i = (int)(idx % half);
    int m = (int)((idx / half) % M);
    long long z = idx / ((long long)half * M);
    float theta = exp2f(cc * ((float)i - 1.f));
    float ang = (float)m * theta;
    float s, c;
    sincosf(ang, &s, &c);
    long long base = ((z*M) + m) * (long long)D + 2*i;
    float xe, xo, re, ro;
    uint32_t h, l;
    xe = q[base]; xo = q[base+1];
    re = xe*c + xo*s; ro = -xe*s + xo*c;
    cvt2(re, ro, h, l);
    *(uint32_t*)&qh[base] = h; *(uint32_t*)&ql[base] = l;
    xe = k[base]; xo = k[base+1];
    re = xe*c + xo*s; ro = -xe*s + xo*c;
    cvt2(re, ro, h, l);
    *(uint32_t*)&kh[base] = h; *(uint32_t*)&kl[base] = l;
}

// softmax: fp32 scores in (scratch), split bf16 out (pad cols zeroed)
__global__ void softmax2(float* __restrict__ s,
                         __nv_bfloat16* __restrict__ ph, __nv_bfloat16* __restrict__ pl,
                         int rows, int L, int ld) {
    int warp = (blockIdx.x*blockDim.x + threadIdx.x) / 32;
    int lane = threadIdx.x % 32;
    if (warp >= rows) return;
    long long ro = (long long)warp * ld;
    float* row = s + ro;
    float mx = -1e30f;
    for (int i = lane; i < L; i += 32) mx = fmaxf(mx, row[i]);
    for (int o = 16; o; o >>= 1) mx = fmaxf(mx, __shfl_xor_sync(0xffffffffu, mx, o));
    float sum = 0.f;
    for (int i = lane; i < L; i += 32) { float e = __expf(row[i]-mx); row[i] = e; sum += e; }
    for (int o = 16; o; o >>= 1) sum += __shfl_xor_sync(0xffffffffu, sum, o);
    float inv = 1.f / sum;
    for (int i = lane; i < ld; i += 32) {
        float v = (i < L) ? row[i]*inv : 0.f;
        __nv_bfloat16 h, l; cvt1(v, h, l);
        ph[ro + i] = h; pl[ro + i] = l;
    }
}

// generic fp32 -> split
__global__ void split_kernel(const float4* __restrict__ in,
                             uint2* __restrict__ oh, uint2* __restrict__ ol, int n4) {
    int idx = blockIdx.x*blockDim.x + threadIdx.x;
    if (idx >= n4) return;
    uint2 h, l; cvt4(in[idx], h, l);
    oh[idx] = h; ol[idx] = l;
}

__global__ void attn_reduce_kernel(const float* __restrict__ part,
                                   const float* __restrict__ bias,
                                   float* __restrict__ x) {
    int idx = blockIdx.x*blockDim.x + threadIdx.x;
    const int D4 = DIM/4;
    int total = BATCH*SEQ*D4;
    if (idx >= total) return;
    int d4 = idx % D4;
    int m  = (idx / D4) % SEQ;
    int b  = idx / (D4*SEQ);
    float4 acc = ((float4*)x)[idx];
    float4 bb = ((const float4*)bias)[d4];
    acc.x += bb.x; acc.y += bb.y; acc.z += bb.z; acc.w += bb.w;
#pragma unroll
    for (int h = 0; h < HEADS; h++) {
        float4 p = ((const float4*)part)[((long long)(b*HEADS+h)*SEQ + m)*D4 + d4];
        acc.x += p.x; acc.y += p.y; acc.z += p.z; acc.w += p.w;
    }
    ((float4*)x)[idx] = acc;
}

// y fp32 + split
__global__ void x_to_y2(const float* __restrict__ x, float* __restrict__ y,
                        __nv_bfloat16* __restrict__ yh, __nv_bfloat16* __restrict__ yl) {
    int idx = blockIdx.x*blockDim.x + threadIdx.x;
    int total = BATCH*CDIM*TDIM;
    if (idx >= total) return;
    int t = idx % TDIM;
    int c = (idx / TDIM) % CDIM;
    int b = idx / (TDIM*CDIM);
    int f = t / SEQ, mm = t % SEQ;
    float v = x[((long long)b*SEQ + mm)*DIM + c*8 + f];
    y[idx] = v;
    __nv_bfloat16 h, l; cvt1(v, h, l);
    yh[idx] = h; yl[idx] = l;
}

__global__ void y_to_x_kernel(const float* __restrict__ y, float* __restrict__ x) {
    int idx = blockIdx.x*blockDim.x + threadIdx.x;
    int total = BATCH*SEQ*DIM;
    if (idx >= total) return;
    int d  = idx % DIM;
    int mm = (idx / DIM) % SEQ;
    int b  = idx / (DIM*SEQ);
    int c = d >> 3, f = d & 7;
    x[idx] = y[((long long)b*CDIM + c)*TDIM + f*SEQ + mm];
}

__global__ void cls_ln_kernel(const float* __restrict__ x, const float* __restrict__ g,
                              const float* __restrict__ be, float* __restrict__ out) {
    int b = blockIdx.x, t = threadIdx.x;
    const float* row = x + (long long)b*SEQ*DIM;
    __shared__ float red[256];
    float s = 0.f;
    for (int i = t; i < DIM; i += 256) s += row[i];
    red[t] = s; __syncthreads();
    for (int o = 128; o > 0; o >>= 1) { if (t < o) red[t] += red[t+o]; __syncthreads(); }
    float mu = red[0] / DIM; __syncthreads();
    float v = 0.f;
    for (int i = t; i < DIM; i += 256) { float d = row[i]-mu; v += d*d; }
    red[t] = v; __syncthreads();
    for (int o = 128; o > 0; o >>= 1) { if (t < o) red[t] += red[t+o]; __syncthreads(); }
    float inv = rsqrtf(red[0]/DIM + 1e-5f);
    for (int i = t; i < DIM; i += 256) out[b*DIM + i] = (row[i]-mu)*inv*g[i] + be[i];
}

static inline int nblk(long long n, int t) { return (int)((n + t - 1) / t); }

extern "C" void kernel_launch(void* const* d_in, const int* in_sizes, int n_in,
                              void* d_out, int out_size) {
    const float* img       = (const float*)d_in[0];
    const float* patch_W   = (const float*)d_in[1];
    const float* patch_b   = (const float*)d_in[2];
    const float* cls_token = (const float*)d_in[3];
    const float* rms_scale = (const float*)d_in[4];
    const float* Wq        = (const float*)d_in[5];
    const float* Wk        = (const float*)d_in[6];
    const float* Wv        = (const float*)d_in[7];
    const float* attn_W    = (const float*)d_in[8];
    const float* attn_b    = (const float*)d_in[9];
    const float* tWq       = (const float*)d_in[10];
    const float* tWk       = (const float*)d_in[11];
    const float* tWv       = (const float*)d_in[12];
    const float* ln_g      = (const float*)d_in[13];
    const float* ln_b      = (const float*)d_in[14];
    const float* head_W    = (const float*)d_in[15];
    const float* head_b    = (const float*)d_in[16];
    float* out = (float*)d_out;

    float *pxp,*px,*pq,*pk,*pv,*ps,*po,*pot,*py,*ptq,*ptk,*ptv,*pts,*pf,*pred,*pcls;
    cudaGetSymbolAddress((void**)&pxp,  g_xp);
    cudaGetSymbolAddress((void**)&px,   g_x);
    cudaGetSymbolAddress((void**)&pq,   g_q);
    cudaGetSymbolAddress((void**)&pk,   g_k);
    cudaGetSymbolAddress((void**)&pv,   g_v);
    cudaGetSymbolAddress((void**)&ps,   g_sc);
    cudaGetSymbolAddress((void**)&po,   g_o);
    cudaGetSymbolAddress((void**)&pot,  g_ot);
    cudaGetSymbolAddress((void**)&py,   g_y);
    cudaGetSymbolAddress((void**)&ptq,  g_tq);
    cudaGetSymbolAddress((void**)&ptk,  g_tk);
    cudaGetSymbolAddress((void**)&ptv,  g_tv);
    cudaGetSymbolAddress((void**)&pts,  g_ts);
    cudaGetSymbolAddress((void**)&pf,   g_fac);
    cudaGetSymbolAddress((void**)&pred, g_red);
    cudaGetSymbolAddress((void**)&pcls, g_cls);

    __nv_bfloat16 *path_h,*path_l,*xh,*xl,*qh,*ql,*kh,*kl,*ph,*pl,*oh,*ol;
    __nv_bfloat16 *yh,*yl,*tqh,*tql,*tkh,*tkl,*tsh,*tsl;
    __nv_bfloat16 *pwh,*pwl,*wqh,*wql,*wkh,*wkl,*wvh,*wvl,*awh,*awl;
    __nv_bfloat16 *twqh,*twql,*twkh,*twkl,*twvh,*twvl,*vth,*vtl,*tvth,*tvtl;
    cudaGetSymbolAddress((void**)&path_h, g_path_h); cudaGetSymbolAddress((void**)&path_l, g_path_l);
    cudaGetSymbolAddress((void**)&xh,  g_xh);  cudaGetSymbolAddress((void**)&xl,  g_xl);
    cudaGetSymbolAddress((void**)&qh,  g_qh);  cudaGetSymbolAddress((void**)&ql,  g_ql);
    cudaGetSymbolAddress((void**)&kh,  g_kh);  cudaGetSymbolAddress((void**)&kl,  g_kl);
    cudaGetSymbolAddress((void**)&ph,  g_ph);  cudaGetSymbolAddress((void**)&pl,  g_pl);
    cudaGetSymbolAddress((void**)&oh,  g_oh);  cudaGetSymbolAddress((void**)&ol,  g_ol);
    cudaGetSymbolAddress((void**)&yh,  g_yh);  cudaGetSymbolAddress((void**)&yl,  g_yl);
    cudaGetSymbolAddress((void**)&tqh, g_tqh); cudaGetSymbolAddress((void**)&tql, g_tql);
    cudaGetSymbolAddress((void**)&tkh, g_tkh); cudaGetSymbolAddress((void**)&tkl, g_tkl);
    cudaGetSymbolAddress((void**)&tsh, g_tsh); cudaGetSymbolAddress((void**)&tsl, g_tsl);
    cudaGetSymbolAddress((void**)&pwh,  g_pwh);  cudaGetSymbolAddress((void**)&pwl,  g_pwl);
    cudaGetSymbolAddress((void**)&wqh,  g_wqh);  cudaGetSymbolAddress((void**)&wql,  g_wql);
    cudaGetSymbolAddress((void**)&wkh,  g_wkh);  cudaGetSymbolAddress((void**)&wkl,  g_wkl);
    cudaGetSymbolAddress((void**)&wvh,  g_wvh);  cudaGetSymbolAddress((void**)&wvl,  g_wvl);
    cudaGetSymbolAddress((void**)&awh,  g_awh);  cudaGetSymbolAddress((void**)&awl,  g_awl);
    cudaGetSymbolAddress((void**)&twqh, g_twqh); cudaGetSymbolAddress((void**)&twql, g_twql);
    cudaGetSymbolAddress((void**)&twkh, g_twkh); cudaGetSymbolAddress((void**)&twkl, g_twkl);
    cudaGetSymbolAddress((void**)&twvh, g_twvh); cudaGetSymbolAddress((void**)&twvl, g_twvl);
    cudaGetSymbolAddress((void**)&vth,  g_vth);  cudaGetSymbolAddress((void**)&vtl,  g_vtl);
    cudaGetSymbolAddress((void**)&tvth, g_tvth); cudaGetSymbolAddress((void**)&tvtl, g_tvtl);

    const long long sXB  = (long long)SEQ*DIM;
    const long long sQH  = (long long)SEQ*DIM;
    const long long sSSp = (long long)SEQ*SEQP;
    const long long sY   = (long long)CDIM*TDIM;
    const long long sTS  = (long long)CDIM*CDIM;
    const long long sW   = (long long)DIM*DIM;
    const long long sVT  = (long long)DIM*SEQP;
    const long long sTVT = (long long)TDIM*CDIM;
    const long long sTW  = (long long)TDIM*TDIM;
    const int ALLB = 0x7fffffff;
    const float scale1 = (float)(1.0/sqrt(512.0));
    const float scale2 = (float)(1.0/sqrt(1576.0));
    const float cc1 = (float)(-2.0*log2(10000.0)/512.0);
    const float cc2 = (float)(-2.0*log2(10000.0)/1576.0);
    dim3 tcb(32, 8);

    // ---- weight pre-conversion ----
    tconv<<<dim3(DIM/32, PK/32, 1), tcb>>>(patch_W, pwh, pwl, PK, DIM, PK, 0, 0);
    tconv<<<dim3(16, 16, 16), tcb>>>(Wq, wqh, wql, DIM, DIM, DIM, sW, sW);
    tconv<<<dim3(16, 16, 16), tcb>>>(Wk, wkh, wkl, DIM, DIM, DIM, sW, sW);
    tconv<<<dim3(16, 16, 16), tcb>>>(Wv, wvh, wvl, DIM, DIM, DIM, sW, sW);
    tconv<<<dim3(16, 16, 16), tcb>>>(attn_W, awh, awl, DIM, DIM, DIM, sW, sW);
    tconv<<<dim3(50, 50, 2), tcb>>>(tWq, twqh, twql, TDIM, TDIM, TDIM, sTW, sTW);
    tconv<<<dim3(50, 50, 2), tcb>>>(tWk, twkh, twkl, TDIM, TDIM, TDIM, sTW, sTW);
    tconv<<<dim3(50, 50, 2), tcb>>>(tWv, twvh, twvl, TDIM, TDIM, TDIM, sTW, sTW);

    // ---- patch embedding ----
    patch_gather2<<<nblk((long long)BATCH*NPATCH*PK,256),256>>>(img, path_h, path_l);
    run_hgemm(path_h, path_l, pwh, pwl, patch_b, 0, pxp,
              BATCH*NPATCH, DIM, PK, PK, PK, DIM,
              0,0, 0,0,0, 0,0, 1, 1.f, 0);
    assemble_x_kernel<<<nblk((long long)BATCH*SEQ*DIM,256),256>>>(pxp, cls_token, px);

    for (int l = 0; l < 2; l++) {
        const float* scale_l = rms_scale + (long long)l*SEQ*DIM;
        long long wOff = (long long)l*8*sW;
        long long twOff = (long long)l*sTW;

        // rmsnorm #1 (+split)
        rms_part_kernel<<<dim3(32,BATCH),256>>>(px, pred);
        rms_fin_kernel<<<1,256>>>(pred, pf);
        rms_apply2<<<nblk((long long)BATCH*SEQ*DIM/4,256),256>>>(px, pf, scale_l,
                                                                 (uint2*)xh, (uint2*)xl);

        // QKV (z = b*8+h)
        run_hgemm(xh, xl, wqh+wOff, wql+wOff, 0, 0, pq,
                  SEQ, DIM, DIM, DIM, DIM, DIM,
                  sXB, 3, sW, 0, 7, 0, sQH, BATCH*HEADS, 1.f, 0);
        run_hgemm(xh, xl, wkh+wOff, wkl+wOff, 0, 0, pk,
                  SEQ, DIM, DIM, DIM, DIM, DIM,
                  sXB, 3, sW, 0, 7, 0, sQH, BATCH*HEADS, 1.f, 0);
        run_hgemm(xh, xl, wvh+wOff, wvl+wOff, 0, 0, pv,
                  SEQ, DIM, DIM, DIM, DIM, DIM,
                  sXB, 3, sW, 0, 7, 0, sQH, BATCH*HEADS, 1.f, 0);

        // v -> vT split [DIM][SEQP] (zero-padded)
        tconv<<<dim3(16, 7, 64), tcb>>>(pv, vth, vtl, SEQ, DIM, SEQP, sQH, sVT);

        // RoPE -> split q,k
        rope2<<<nblk((long long)BATCH*HEADS*SEQ*(DIM/2),256),256>>>(pq, pk, qh, ql, kh, kl,
                                                                     BATCH*HEADS, SEQ, DIM, cc1);

        // scores
        run_hgemm(qh, ql, kh, kl, 0, 0, ps,
                  SEQ, SEQ, DIM, DIM, DIM, SEQP,
                  sQH, 0, sQH, 0, ALLB, 0, sSSp, BATCH*HEADS, scale1, 0);
        softmax2<<<nblk((long long)BATCH*HEADS*SEQ*32,256),256>>>(ps, ph, pl,
                                                                  BATCH*HEADS*SEQ, SEQ, SEQP);

        // o = p @ v
        run_hgemm(ph, pl, vth, vtl, 0, 0, po,
                  SEQ, DIM, SEQP, SEQP, SEQP, DIM,
                  sSSp, 0, sVT, 0, ALLB, 0, sQH, BATCH*HEADS, 1.f, 0);
        split_kernel<<<nblk((long long)BATCH*HEADS*SEQ*DIM/4,256),256>>>(
            (const float4*)po, (uint2*)oh, (uint2*)ol, BATCH*HEADS*SEQ*DIM/4);

        // per-head proj partials + reduce
        run_hgemm(oh, ol, awh+wOff, awl+wOff, 0, 0, pot,
                  SEQ, DIM, DIM, DIM, DIM, DIM,
                  sQH, 0, sW, 0, 7, 0, sQH, BATCH*HEADS, 1.f, 0);
        attn_reduce_kernel<<<nblk((long long)BATCH*SEQ*DIM/4,256),256>>>(pot, attn_b + l*DIM, px);

        // rmsnorm #2 (+split, xh/xl reused)
        rms_part_kernel<<<dim3(32,BATCH),256>>>(px, pred);
        rms_fin_kernel<<<1,256>>>(pred, pf);
        rms_apply2<<<nblk((long long)BATCH*SEQ*DIM/4,256),256>>>(px, pf, scale_l,
                                                                 (uint2*)xh, (uint2*)xl);

        // token-mixing
        x_to_y2<<<nblk((long long)BATCH*CDIM*TDIM,256),256>>>(px, py, yh, yl);

        run_hgemm(yh, yl, twqh+twOff, twql+twOff, 0, 0, ptq,
                  CDIM, TDIM, TDIM, TDIM, TDIM, TDIM,
                  sY, 0, 0, 0, 0, 0, sY, BATCH, 1.f, 0);
        run_hgemm(yh, yl, twkh+twOff, twkl+twOff, 0, 0, ptk,
                  CDIM, TDIM, TDIM, TDIM, TDIM, TDIM,
                  sY, 0, 0, 0, 0, 0, sY, BATCH, 1.f, 0);
        run_hgemm(yh, yl, twvh+twOff, twvl+twOff, 0, 0, ptv,
                  CDIM, TDIM, TDIM, TDIM, TDIM, TDIM,
                  sY, 0, 0, 0, 0, 0, sY, BATCH, 1.f, 0);

        tconv<<<dim3(50, 2, 8), tcb>>>(ptv, tvth, tvtl, CDIM, TDIM, CDIM, sY, sTVT);

        rope2<<<nblk((long long)BATCH*CDIM*(TDIM/2),256),256>>>(ptq, ptk, tqh, tql, tkh, tkl,
                                                                 BATCH, CDIM, TDIM, cc2);

        run_hgemm(tqh, tql, tkh, tkl, 0, 0, pts,
                  CDIM, CDIM, TDIM, TDIM, TDIM, CDIM,
                  sY, 0, sY, 0, ALLB, 0, sTS, BATCH, scale2, 0);
        softmax2<<<nblk((long long)BATCH*CDIM*32,256),256>>>(pts, tsh, tsl,
                                                             BATCH*CDIM, CDIM, CDIM);

        // y += p @ tv
        run_hgemm(tsh, tsl, tvth, tvtl, 0, py, py,
                  CDIM, TDIM, CDIM, CDIM, CDIM, TDIM,
                  sTS, 0, sTVT, 0, ALLB, sY, sY, BATCH, 1.f, 1);

        y_to_x_kernel<<<nblk((long long)BATCH*SEQ*DIM,256),256>>>(py, px);
    }

    // ---- final: cls layernorm + head ----
    cls_ln_kernel<<<BATCH,256>>>(px, ln_g, ln_b, pcls);
    {
        dim3 grid((NCLS+31)/32, 1, 1);
        sgemm_s<<<grid, 64>>>(pcls, head_W, head_b, out, BATCH, NCLS, DIM, DIM, NCLS, NCLS);
    }
}

// round 10
// speedup vs baseline: 6.6599x; 1.0917x over previous
#include <cuda_runtime.h>
#include <cuda_bf16.h>
#include <math.h>
#include <stdint.h>

#define BATCH 8
#define HEADS 8
#define DIM 512
#define SEQ 197
#define SEQP 208
#define NPATCH 196
#define PK 768
#define CDIM 64
#define TDIM 1576
#define NCLS 1000

// ---------------- fp32 scratch ----------------
__device__ float g_xp[BATCH*NPATCH*DIM];
__device__ float g_x[BATCH*SEQ*DIM];
__device__ float g_qkv[192*SEQ*DIM];          // [w][b*8+h][SEQ][DIM], w=0:q 1:k 2:v
__device__ float g_sc[BATCH*HEADS*SEQ*SEQP];
__device__ float g_o[BATCH*HEADS*SEQ*DIM];
__device__ float g_ot[BATCH*SEQ*HEADS*DIM];
__device__ float g_y[BATCH*CDIM*TDIM];
__device__ float g_tqkv[24*CDIM*TDIM];        // [w][b][CDIM][TDIM]
__device__ float g_ts[BATCH*CDIM*CDIM];
__device__ float g_fac[BATCH];
__device__ float g_red[BATCH*32];
__device__ float g_cls[BATCH*DIM];

// ---------------- bf16 hi/lo split operands (K-major) ----------------
__device__ __nv_bfloat16 g_path_h[BATCH*NPATCH*PK],  g_path_l[BATCH*NPATCH*PK];
__device__ __nv_bfloat16 g_xh[BATCH*SEQ*DIM],        g_xl[BATCH*SEQ*DIM];
__device__ __nv_bfloat16 g_qh[BATCH*HEADS*SEQ*DIM],  g_ql[BATCH*HEADS*SEQ*DIM];
__device__ __nv_bfloat16 g_kh[BATCH*HEADS*SEQ*DIM],  g_kl[BATCH*HEADS*SEQ*DIM];
__device__ __nv_bfloat16 g_ph[BATCH*HEADS*SEQ*SEQP], g_pl[BATCH*HEADS*SEQ*SEQP];
__device__ __nv_bfloat16 g_oh[BATCH*HEADS*SEQ*DIM],  g_ol[BATCH*HEADS*SEQ*DIM];
__device__ __nv_bfloat16 g_yh[BATCH*CDIM*TDIM],      g_yl[BATCH*CDIM*TDIM];
__device__ __nv_bfloat16 g_tqh[BATCH*CDIM*TDIM],     g_tql[BATCH*CDIM*TDIM];
__device__ __nv_bfloat16 g_tkh[BATCH*CDIM*TDIM],     g_tkl[BATCH*CDIM*TDIM];
__device__ __nv_bfloat16 g_tsh[BATCH*CDIM*CDIM],     g_tsl[BATCH*CDIM*CDIM];
// weights
__device__ __nv_bfloat16 g_pwh[DIM*PK],            g_pwl[DIM*PK];
__device__ __nv_bfloat16 g_wAh[2*3*8*DIM*DIM],     g_wAl[2*3*8*DIM*DIM];   // [l][w][h]
__device__ __nv_bfloat16 g_awh[16*DIM*DIM],        g_awl[16*DIM*DIM];
__device__ __nv_bfloat16 g_twAh[2*3*TDIM*TDIM],    g_twAl[2*3*TDIM*TDIM]; // [l][w]
__device__ __nv_bfloat16 g_vth[64*DIM*SEQP],       g_vtl[64*DIM*SEQP];
__device__ __nv_bfloat16 g_tvth[8*TDIM*CDIM],      g_tvtl[8*TDIM*CDIM];

// ---------------- helpers ----------------
__device__ __forceinline__ void cvt4(float4 v, uint2 &h, uint2 &l){
    __nv_bfloat16 ax=__float2bfloat16_rn(v.x), ay=__float2bfloat16_rn(v.y);
    __nv_bfloat16 az=__float2bfloat16_rn(v.z), aw=__float2bfloat16_rn(v.w);
    __nv_bfloat162 h0; h0.x=ax; h0.y=ay;
    __nv_bfloat162 h1; h1.x=az; h1.y=aw;
    h.x=*(unsigned*)&h0; h.y=*(unsigned*)&h1;
    __nv_bfloat162 l0; l0.x=__float2bfloat16_rn(v.x-__bfloat162float(ax));
                       l0.y=__float2bfloat16_rn(v.y-__bfloat162float(ay));
    __nv_bfloat162 l1; l1.x=__float2bfloat16_rn(v.z-__bfloat162float(az));
                       l1.y=__float2bfloat16_rn(v.w-__bfloat162float(aw));
    l.x=*(unsigned*)&l0; l.y=*(unsigned*)&l1;
}
__device__ __forceinline__ void cvt2(float a, float b, uint32_t &h, uint32_t &l){
    __nv_bfloat16 ha=__float2bfloat16_rn(a), hb=__float2bfloat16_rn(b);
    __nv_bfloat162 H; H.x=ha; H.y=hb; h=*(uint32_t*)&H;
    __nv_bfloat162 L; L.x=__float2bfloat16_rn(a-__bfloat162float(ha));
                      L.y=__float2bfloat16_rn(b-__bfloat162float(hb)); l=*(uint32_t*)&L;
}
__device__ __forceinline__ void cvt1(float a, __nv_bfloat16 &h, __nv_bfloat16 &l){
    h=__float2bfloat16_rn(a);
    l=__float2bfloat16_rn(a-__bfloat162float(h));
}
__device__ __forceinline__ void ldsm4(unsigned r[4], const __nv_bfloat16* p) {
    unsigned a = (unsigned)__cvta_generic_to_shared(p);
    asm volatile("ldmatrix.sync.aligned.m8n8.x4.shared.b16 {%0,%1,%2,%3}, [%4];"
                 : "=r"(r[0]), "=r"(r[1]), "=r"(r[2]), "=r"(r[3]) : "r"(a));
}
__device__ __forceinline__ void mma16816(float c[4], const unsigned a[4],
                                         unsigned b0, unsigned b1) {
    asm volatile("mma.sync.aligned.m16n8k16.row.col.f32.bf16.bf16.f32 "
                 "{%0,%1,%2,%3}, {%4,%5,%6,%7}, {%8,%9}, {%0,%1,%2,%3};"
                 : "+f"(c[0]), "+f"(c[1]), "+f"(c[2]), "+f"(c[3])
                 : "r"(a[0]), "r"(a[1]), "r"(a[2]), "r"(a[3]), "r"(b0), "r"(b1));
}

// ================= bf16 split GEMM (pre-split, double-buffered, generic batching) ===========
// off(z) = (z/D1)*S1 + ((z%D1)/D2)*S2 + (z%D2)*S3  for A and B independently.
// C (+Cin) indexed plain z. Optional split bf16 outputs Ch/Cl.
template<int BM>
__global__ __launch_bounds__(BM*2)
void hgemm2(const __nv_bfloat16* __restrict__ Ah, const __nv_bfloat16* __restrict__ Al,
            const __nv_bfloat16* __restrict__ Bh, const __nv_bfloat16* __restrict__ Bl,
            const float* __restrict__ bias, const float* __restrict__ Cin,
            float* __restrict__ C,
            __nv_bfloat16* __restrict__ Ch, __nv_bfloat16* __restrict__ Cl,
            int M, int N, int K, int lda, int ldb, int ldc,
            int aD1, long long aS1, int aD2, long long aS2, long long aS3,
            int bD1, long long bS1, int bD2, long long bS2, long long bS3,
            long long sCin, long long sC, float alpha, int addC)
{
    constexpr int WARPS_M = BM/64;
    constexpr int THREADS = BM*2;
    constexpr int B_V = 512/THREADS;
    constexpr int SHALF = (2*BM + 256)*40;
    const int OFF_AH = 0, OFF_AL = BM*40, OFF_BH = 2*BM*40, OFF_BL = 2*BM*40 + 128*40;
    extern __shared__ __align__(16) __nv_bfloat16 sm[];

    int z = blockIdx.z;
    long long ao = (long long)(z / aD1)*aS1 + (long long)((z % aD1) / aD2)*aS2
                 + (long long)(z % aD2)*aS3;
    long long bo = (long long)(z / bD1)*bS1 + (long long)((z % bD1) / bD2)*bS2
                 + (long long)(z % bD2)*bS3;
    Ah += ao; Al += ao; Bh += bo; Bl += bo;
    long long co = (long long)z * sC;
    C += co;
    if (Ch){ Ch += co; Cl += co; }
    const float* Cr = addC ? Cin + (long long)z * sCin : (const float*)0;

    int row0 = blockIdx.y*BM, col0 = blockIdx.x*128;
    int tid = threadIdx.x, lane = tid & 31, warp = tid >> 5;
    int wm0 = (warp % WARPS_M)*64;
    int wn0 = (warp / WARPS_M)*32;

    float acc[4][4][4];
#pragma unroll
    for (int i=0;i<4;i++)
#pragma unroll
      for (int j=0;j<4;j++)
#pragma unroll
        for (int t=0;t<4;t++) acc[i][j][t]=0.f;

    uint4 rah[2], ral[2], rbh[B_V], rbl[B_V];

    auto ldA = [&](int k0){
#pragma unroll
        for (int t = 0; t < 2; t++){
            int idx = tid + t*THREADS;
            int row = idx >> 2, k8 = idx & 3;
            int gm = row0 + row, gk = k0 + k8*8;
            uint4 zz = make_uint4(0,0,0,0);
            rah[t] = zz; ral[t] = zz;
            if (gm < M && gk < K){
                rah[t] = *(const uint4*)&Ah[(long long)gm*lda + gk];
                ral[t] = *(const uint4*)&Al[(long long)gm*lda + gk];
            }
        }
    };
    auto ldB = [&](int k0){
#pragma unroll
        for (int t = 0; t < B_V; t++){
            int idx = tid + t*THREADS;
            int row = idx >> 2, k8 = idx & 3;
            int gn = col0 + row, gk = k0 + k8*8;
            uint4 zz = make_uint4(0,0,0,0);
            rbh[t] = zz; rbl[t] = zz;
            if (gn < N && gk < K){
                rbh[t] = *(const uint4*)&Bh[(long long)gn*ldb + gk];
                rbl[t] = *(const uint4*)&Bl[(long long)gn*ldb + gk];
            }
        }
    };
    auto stA = [&](int st){
#pragma unroll
        for (int t = 0; t < 2; t++){
            int idx = tid + t*THREADS;
            int row = idx >> 2, k8 = idx & 3;
            *(uint4*)&sm[st*SHALF + OFF_AH + row*40 + k8*8] = rah[t];
            *(uint4*)&sm[st*SHALF + OFF_AL + row*40 + k8*8] = ral[t];
        }
    };
    auto stB = [&](int st){
#pragma unroll
        for (int t = 0; t < B_V; t++){
            int idx = tid + t*THREADS;
            int row = idx >> 2, k8 = idx & 3;
            *(uint4*)&sm[st*SHALF + OFF_BH + row*40 + k8*8] = rbh[t];
            *(uint4*)&sm[st*SHALF + OFF_BL + row*40 + k8*8] = rbl[t];
        }
    };

    int r8 = lane&7, s1 = (lane>>3)&1, s2 = lane>>4;
    auto compute = [&](int st, int kk){
        unsigned ah[4][4], al[4][4], bh[2][4], bl[2][4];
#pragma unroll
        for (int mt=0;mt<4;mt++){
            int row = wm0 + mt*16 + r8 + s1*8;
            int col = kk + s2*8;
            ldsm4(ah[mt], &sm[st*SHALF + OFF_AH + row*40 + col]);
            ldsm4(al[mt], &sm[st*SHALF + OFF_AL + row*40 + col]);
        }
#pragma unroll
        for (int np=0;np<2;np++){
            int row = wn0 + np*16 + r8 + s2*8;
            int col = kk + s1*8;
            ldsm4(bh[np], &sm[st*SHALF + OFF_BH + row*40 + col]);
            ldsm4(bl[np], &sm[st*SHALF + OFF_BL + row*40 + col]);
        }
#pragma unroll
        for (int mt=0;mt<4;mt++)
#pragma unroll
            for (int nt=0;nt<4;nt++){
                unsigned b0h = bh[nt>>1][(nt&1)*2], b1h = bh[nt>>1][(nt&1)*2+1];
                unsigned b0l = bl[nt>>1][(nt&1)*2], b1l = bl[nt>>1][(nt&1)*2+1];
                mma16816(acc[mt][nt], ah[mt], b0h, b1h);
                mma16816(acc[mt][nt], al[mt], b0h, b1h);
                mma16816(acc[mt][nt], ah[mt], b0l, b1l);
            }
    };

    int nk = (K + 31) / 32;
    ldA(0); ldB(0);
    stA(0); stB(0);
    __syncthreads();
    for (int kt = 0; kt < nk; kt++){
        int cur = kt & 1;
        if (kt + 1 < nk){ ldA((kt+1)*32); ldB((kt+1)*32); }
        compute(cur, 0);
        compute(cur, 16);
        if (kt + 1 < nk){ stA(cur^1); stB(cur^1); }
        __syncthreads();
    }

    // epilogue
    int gid = lane>>2, tq = lane&3;
#pragma unroll
    for (int mt=0;mt<4;mt++)
#pragma unroll
      for (int h=0;h<2;h++){
        int gm = row0 + wm0 + mt*16 + gid + h*8;
        if (gm>=M) continue;
        long long base = (long long)gm*ldc;
#pragma unroll
        for (int nt=0;nt<4;nt++){
          int gn = col0 + wn0 + nt*8 + tq*2;
          if (gn>=N) continue;
          float v0 = alpha*acc[mt][nt][h*2+0];
          float v1 = alpha*acc[mt][nt][h*2+1];
          if (bias){ v0 += bias[gn]; if (gn+1<N) v1 += bias[gn+1]; }
          if (Cr)  { v0 += Cr[base+gn]; if (gn+1<N) v1 += Cr[base+gn+1]; }
          if (gn+1<N){
            float2 st; st.x=v0; st.y=v1; *(float2*)&C[base+gn]=st;
            if (Ch){
              uint32_t hh, ll; cvt2(v0, v1, hh, ll);
              *(uint32_t*)&Ch[base+gn] = hh;
              *(uint32_t*)&Cl[base+gn] = ll;
            }
          } else {
            C[base+gn]=v0;
            if (Ch){ __nv_bfloat16 hh, ll; cvt1(v0, hh, ll); Ch[base+gn]=hh; Cl[base+gn]=ll; }
          }
        }
      }
}

#define P_NONE  (1<<30), 0LL, 1, 0LL, 0LL
#define P_PLAIN(s) (1<<30), 0LL, 1, (long long)(s), 0LL
#define P_LOW8(s)  (1<<30), 0LL, 8, 0LL, (long long)(s)     // idx = z%8

static void run_hgemm(const __nv_bfloat16* Ah, const __nv_bfloat16* Al,
                      const __nv_bfloat16* Bh, const __nv_bfloat16* Bl,
                      const float* bias, const float* Cin, float* C,
                      __nv_bfloat16* Ch, __nv_bfloat16* Cl,
                      int M, int N, int K, int lda, int ldb, int ldc,
                      int aD1, long long aS1, int aD2, long long aS2, long long aS3,
                      int bD1, long long bS1, int bD2, long long bS2, long long bS3,
                      long long sCin, long long sC, int batch, float alpha, int addC)
{
    long long b128 = (long long)((N+127)/128)*((M+127)/128)*batch;
    if (M >= 96 && b128 >= 90) {
        constexpr int SM = 2*(2*128+256)*40*2;   // 81920 B
        cudaFuncSetAttribute(hgemm2<128>, cudaFuncAttributeMaxDynamicSharedMemorySize, SM);
        dim3 grid((N+127)/128, (M+127)/128, batch);
        hgemm2<128><<<grid, 256, SM>>>(Ah,Al,Bh,Bl,bias,Cin,C,Ch,Cl,M,N,K,lda,ldb,ldc,
            aD1,aS1,aD2,aS2,aS3,bD1,bS1,bD2,bS2,bS3,sCin,sC,alpha,addC);
    } else {
        constexpr int SM = 2*(2*64+256)*40*2;    // 61440 B
        cudaFuncSetAttribute(hgemm2<64>, cudaFuncAttributeMaxDynamicSharedMemorySize, SM);
        dim3 grid((N+127)/128, (M+63)/64, batch);
        hgemm2<64><<<grid, 128, SM>>>(Ah,Al,Bh,Bl,bias,Cin,C,Ch,Cl,M,N,K,lda,ldb,ldc,
            aD1,aS1,aD2,aS2,aS3,bD1,bS1,bD2,bS2,bS3,sCin,sC,alpha,addC);
    }
}

// ================= transpose-convert: fp32 [K][N] -> bf16 hi/lo [N][Kp] =================
__global__ void tconv(const float* __restrict__ in, __nv_bfloat16* __restrict__ oh,
                      __nv_bfloat16* __restrict__ ol,
                      int K, int N, int Kp, long long sIn, long long sOut)
{
    __shared__ float t[32][33];
    int z = blockIdx.z;
    const float* I = in + (long long)z * sIn;
    __nv_bfloat16* OH = oh + (long long)z * sOut;
    __nv_bfloat16* OL = ol + (long long)z * sOut;
    int kb = blockIdx.y * 32, nb = blockIdx.x * 32;
    for (int i = threadIdx.y; i < 32; i += 8) {
        int k = kb + i, n = nb + threadIdx.x;
        t[i][threadIdx.x] = (k < K && n < N) ? I[(long long)k*N + n] : 0.f;
    }
    __syncthreads();
    for (int i = threadIdx.y; i < 32; i += 8) {
        int n = nb + i, k = kb + threadIdx.x;
        if (n < N && k < Kp) {
            __nv_bfloat16 h, l; cvt1(t[threadIdx.x][i], h, l);
            OH[(long long)n*Kp + k] = h;
            OL[(long long)n*Kp + k] = l;
        }
    }
}

// ---------------- fp32 fallback GEMM (final head, M=8) ----------------
__global__ __launch_bounds__(64)
void sgemm_s(const float* __restrict__ A, const float* __restrict__ B,
             const float* __restrict__ bias, float* __restrict__ C,
             int M, int N, int K, int lda, int ldb, int ldc)
{
    constexpr int BK = 16;
    __shared__ float As[BK][36];
    __shared__ float Bs[BK][36];
    int row0 = blockIdx.y*32, col0 = blockIdx.x*32;
    int tid = threadIdx.x;
    int tx = tid % 8, ty = tid / 8;
    float acc[4][4];
#pragma unroll
    for (int i=0;i<4;i++)
#pragma unroll
      for (int j=0;j<4;j++) acc[i][j]=0.f;
    for (int k0 = 0; k0 < K; k0 += BK) {
        for (int e = tid; e < 32*BK/4; e += 64) {
            int mm = e >> 2, c4 = e & 3;
            int gm = row0+mm, gk = k0+c4*4;
            float4 v = make_float4(0.f,0.f,0.f,0.f);
            if (gm < M && gk < K) v = *(const float4*)&A[(long long)gm*lda+gk];
            As[c4*4+0][mm]=v.x; As[c4*4+1][mm]=v.y; As[c4*4+2][mm]=v.z; As[c4*4+3][mm]=v.w;
        }
        for (int e = tid; e < BK*8; e += 64) {
            int kk = e / 8, n4 = e % 8;
            int gk = k0+kk, gn = col0+n4*4;
            float4 v = make_float4(0.f,0.f,0.f,0.f);
            if (gk < K) {
                if (gn+3 < N) v = *(const float4*)&B[(long long)gk*ldb+gn];
                else {
                    const float* p = &B[(long long)gk*ldb];
                    if (gn<N)v.x=p[gn]; if (gn+1<N)v.y=p[gn+1];
                    if (gn+2<N)v.z=p[gn+2]; if (gn+3<N)v.w=p[gn+3];
                }
            }
            Bs[kk][n4*4+0]=v.x; Bs[kk][n4*4+1]=v.y; Bs[kk][n4*4+2]=v.z; Bs[kk][n4*4+3]=v.w;
        }
        __syncthreads();
#pragma unroll
        for (int kk = 0; kk < BK; kk++) {
            float a[4], b[4];
#pragma unroll
            for (int i=0;i<4;i++) a[i]=As[kk][ty*4+i];
#pragma unroll
            for (int j=0;j<4;j++) b[j]=Bs[kk][tx*4+j];
#pragma unroll
            for (int i=0;i<4;i++)
#pragma unroll
              for (int j=0;j<4;j++) acc[i][j]+=a[i]*b[j];
        }
        __syncthreads();
    }
#pragma unroll
    for (int i=0;i<4;i++){
        int gm = row0+ty*4+i;
        if (gm >= M) continue;
#pragma unroll
        for (int j=0;j<4;j++){
            int gn = col0+tx*4+j;
            if (gn >= N) continue;
            float v = acc[i][j];
            if (bias) v += bias[gn];
            C[(long long)gm*ldc+gn] = v;
        }
    }
}

// ---------------- elementwise kernels ----------------
__global__ void patch_gather2(const float* __restrict__ img,
                              __nv_bfloat16* __restrict__ oh, __nv_bfloat16* __restrict__ ol) {
    int idx = blockIdx.x*blockDim.x + threadIdx.x;
    int total = BATCH*NPATCH*PK;
    if (idx >= total) return;
    int k = idx % PK;
    int p = (idx / PK) % NPATCH;
    int b = idx / (PK*NPATCH);
    int c  = k % 3;
    int pj = (k/3) % 16;
    int pi = k / 48;
    int i = p / 14, j = p % 14;
    float v = img[(((long long)b*3 + c)*224 + (i*16+pi))*224 + (j*16+pj)];
    __nv_bfloat16 h, l; cvt1(v, h, l);
    oh[idx] = h; ol[idx] = l;
}

__global__ void assemble_x_kernel(const float* __restrict__ xp, const float* __restrict__ cls,
                                  float* __restrict__ x) {
    int idx = blockIdx.x*blockDim.x + threadIdx.x;
    int total = BATCH*SEQ*DIM;
    if (idx >= total) return;
    int d = idx % DIM;
    int m = (idx / DIM) % SEQ;
    int b = idx / (DIM*SEQ);
    x[idx] = (m == 0) ? cls[d] : xp[((long long)b*NPATCH + (m-1))*DIM + d];
}

__global__ void rms_part_kernel(const float* __restrict__ x, float* __restrict__ red) {
    int b = blockIdx.y, ch = blockIdx.x;
    const int per_batch = SEQ*DIM;
    const int chunk = per_batch/32;
    const float4* p = (const float4*)(x + (long long)b*per_batch + ch*chunk);
    float s = 0.f;
    for (int i = threadIdx.x; i < chunk/4; i += 256) {
        float4 v = p[i];
        s += v.x*v.x + v.y*v.y + v.z*v.z + v.w*v.w;
    }
    __shared__ float sm[256];
    sm[threadIdx.x] = s; __syncthreads();
    for (int o = 128; o > 0; o >>= 1) { if (threadIdx.x < o) sm[threadIdx.x] += sm[threadIdx.x+o]; __syncthreads(); }
    if (threadIdx.x == 0) red[b*32 + ch] = sm[0];
}
__global__ void rms_fin_kernel(const float* __restrict__ red, float* __restrict__ fac) {
    int b = threadIdx.x / 32, lane = threadIdx.x % 32;
    float v = red[b*32 + lane];
    for (int o = 16; o; o >>= 1) v += __shfl_xor_sync(0xffffffffu, v, o);
    if (lane == 0) fac[b] = sqrtf((float)(SEQ*DIM) / v);
}
__global__ void rms_apply2(float* __restrict__ x, const float* __restrict__ fac,
                           const float* __restrict__ scale,
                           uint2* __restrict__ xh, uint2* __restrict__ xl) {
    int idx = blockIdx.x*blockDim.x + threadIdx.x;
    const int per4 = SEQ*DIM/4;
    int total = BATCH*per4;
    if (idx >= total) return;
    int b = idx / per4, s4 = idx % per4;
    float f = fac[b];
    float4 v = ((float4*)x)[idx];
    float4 sc = ((const float4*)scale)[s4];
    v.x *= f*sc.x; v.y *= f*sc.y; v.z *= f*sc.z; v.w *= f*sc.w;
    ((float4*)x)[idx] = v;
    uint2 h, l; cvt4(v, h, l);
    xh[idx] = h; xl[idx] = l;
}

__global__ void rope2(const float* __restrict__ q, const float* __restrict__ k,
                      __nv_bfloat16* __restrict__ qh, __nv_bfloat16* __restrict__ ql,
                      __nv_bfloat16* __restrict__ kh, __nv_bfloat16* __restrict__ kl,
                      int Z, int M, int D, float cc) {
    int half = D / 2;
    long long total = (long long)Z * M * half;
    long long idx = (long long)blockIdx.x*blockDim.x + threadIdx.x;
    if (idx >= total) return;
    int i = (int)(idx % half);
    int m = (int)((idx / half) % M);
    long long z = idx / ((long long)half * M);
    float theta = exp2f(cc * ((float)i - 1.f));
    float ang = (float)m * theta;
    float s, c;
    sincosf(ang, &s, &c);
    long long base = ((z*M) + m) * (long long)D + 2*i;
    float xe, xo, re, ro;
    uint32_t h, l;
    xe = q[base]; xo = q[base+1];
    re = xe*c + xo*s; ro = -xe*s + xo*c;
    cvt2(re, ro, h, l);
    *(uint32_t*)&qh[base] = h; *(uint32_t*)&ql[base] = l;
    xe = k[base]; xo = k[base+1];
    re = xe*c + xo*s; ro = -xe*s + xo*c;
    cvt2(re, ro, h, l);
    *(uint32_t*)&kh[base] = h; *(uint32_t*)&kl[base] = l;
}

__global__ void softmax2(float* __restrict__ s,
                         __nv_bfloat16* __restrict__ ph, __nv_bfloat16* __restrict__ pl,
                         int rows, int L, int ld) {
    int warp = (blockIdx.x*blockDim.x + threadIdx.x) / 32;
    int lane = threadIdx.x % 32;
    if (warp >= rows) return;
    long long ro = (long long)warp * ld;
    float* row = s + ro;
    float mx = -1e30f;
    for (int i = lane; i < L; i += 32) mx = fmaxf(mx, row[i]);
    for (int o = 16; o; o >>= 1) mx = fmaxf(mx, __shfl_xor_sync(0xffffffffu, mx, o));
    float sum = 0.f;
    for (int i = lane; i < L; i += 32) { float e = __expf(row[i]-mx); row[i] = e; sum += e; }
    for (int o = 16; o; o >>= 1) sum += __shfl_xor_sync(0xffffffffu, sum, o);
    float inv = 1.f / sum;
    for (int i = lane; i < ld; i += 32) {
        float v = (i < L) ? row[i]*inv : 0.f;
        __nv_bfloat16 h, l; cvt1(v, h, l);
        ph[ro + i] = h; pl[ro + i] = l;
    }
}

__global__ void attn_reduce_kernel(const float* __restrict__ part,
                                   const float* __restrict__ bias,
                                   float* __restrict__ x) {
    int idx = blockIdx.x*blockDim.x + threadIdx.x;
    const int D4 = DIM/4;
    int total = BATCH*SEQ*D4;
    if (idx >= total) return;
    int d4 = idx % D4;
    int m  = (idx / D4) % SEQ;
    int b  = idx / (D4*SEQ);
    float4 acc = ((float4*)x)[idx];
    float4 bb = ((const float4*)bias)[d4];
    acc.x += bb.x; acc.y += bb.y; acc.z += bb.z; acc.w += bb.w;
#pragma unroll
    for (int h = 0; h < HEADS; h++) {
        float4 p = ((const float4*)part)[((long long)(b*HEADS+h)*SEQ + m)*D4 + d4];
        acc.x += p.x; acc.y += p.y; acc.z += p.z; acc.w += p.w;
    }
    ((float4*)x)[idx] = acc;
}

__global__ void x_to_y2(const float* __restrict__ x, float* __restrict__ y,
                        __nv_bfloat16* __restrict__ yh, __nv_bfloat16* __restrict__ yl) {
    int idx = blockIdx.x*blockDim.x + threadIdx.x;
    int total = BATCH*CDIM*TDIM;
    if (idx >= total) return;
    int t = idx % TDIM;
    int c = (idx / TDIM) % CDIM;
    int b = idx / (TDIM*CDIM);
    int f = t / SEQ, mm = t % SEQ;
    float v = x[((long long)b*SEQ + mm)*DIM + c*8 + f];
    y[idx] = v;
    __nv_bfloat16 h, l; cvt1(v, h, l);
    yh[idx] = h; yl[idx] = l;
}

__global__ void y_to_x_kernel(const float* __restrict__ y, float* __restrict__ x) {
    int idx = blockIdx.x*blockDim.x + threadIdx.x;
    int total = BATCH*SEQ*DIM;
    if (idx >= total) return;
    int d  = idx % DIM;
    int mm = (idx / DIM) % SEQ;
    int b  = idx / (DIM*SEQ);
    int c = d >> 3, f = d & 7;
    x[idx] = y[((long long)b*CDIM + c)*TDIM + f*SEQ + mm];
}

__global__ void cls_ln_kernel(const float* __restrict__ x, const float* __restrict__ g,
                              const float* __restrict__ be, float* __restrict__ out) {
    int b = blockIdx.x, t = threadIdx.x;
    const float* row = x + (long long)b*SEQ*DIM;
    __shared__ float red[256];
    float s = 0.f;
    for (int i = t; i < DIM; i += 256) s += row[i];
    red[t] = s; __syncthreads();
    for (int o = 128; o > 0; o >>= 1) { if (t < o) red[t] += red[t+o]; __syncthreads(); }
    float mu = red[0] / DIM; __syncthreads();
    float v = 0.f;
    for (int i = t; i < DIM; i += 256) { float d = row[i]-mu; v += d*d; }
    red[t] = v; __syncthreads();
    for (int o = 128; o > 0; o >>= 1) { if (t < o) red[t] += red[t+o]; __syncthreads(); }
    float inv = rsqrtf(red[0]/DIM + 1e-5f);
    for (int i = t; i < DIM; i += 256) out[b*DIM + i] = (row[i]-mu)*inv*g[i] + be[i];
}

static inline int nblk(long long n, int t) { return (int)((n + t - 1) / t); }

extern "C" void kernel_launch(void* const* d_in, const int* in_sizes, int n_in,
                              void* d_out, int out_size) {
    const float* img       = (const float*)d_in[0];
    const float* patch_W   = (const float*)d_in[1];
    const float* patch_b   = (const float*)d_in[2];
    const float* cls_token = (const float*)d_in[3];
    const float* rms_scale = (const float*)d_in[4];
    const float* Wq        = (const float*)d_in[5];
    const float* Wk        = (const float*)d_in[6];
    const float* Wv        = (const float*)d_in[7];
    const float* attn_W    = (const float*)d_in[8];
    const float* attn_b    = (const float*)d_in[9];
    const float* tWq       = (const float*)d_in[10];
    const float* tWk       = (const float*)d_in[11];
    const float* tWv       = (const float*)d_in[12];
    const float* ln_g      = (const float*)d_in[13];
    const float* ln_b      = (const float*)d_in[14];
    const float* head_W    = (const float*)d_in[15];
    const float* head_b    = (const float*)d_in[16];
    float* out = (float*)d_out;

    float *pxp,*px,*pqkv,*ps,*po,*pot,*py,*ptqkv,*pts,*pf,*pred,*pcls;
    cudaGetSymbolAddress((void**)&pxp,  g_xp);
    cudaGetSymbolAddress((void**)&px,   g_x);
    cudaGetSymbolAddress((void**)&pqkv, g_qkv);
    cudaGetSymbolAddress((void**)&ps,   g_sc);
    cudaGetSymbolAddress((void**)&po,   g_o);
    cudaGetSymbolAddress((void**)&pot,  g_ot);
    cudaGetSymbolAddress((void**)&py,   g_y);
    cudaGetSymbolAddress((void**)&ptqkv,g_tqkv);
    cudaGetSymbolAddress((void**)&pts,  g_ts);
    cudaGetSymbolAddress((void**)&pf,   g_fac);
    cudaGetSymbolAddress((void**)&pred, g_red);
    cudaGetSymbolAddress((void**)&pcls, g_cls);

    __nv_bfloat16 *path_h,*path_l,*xh,*xl,*qh,*ql,*kh,*kl,*ph,*pl,*oh,*ol;
    __nv_bfloat16 *yh,*yl,*tqh,*tql,*tkh,*tkl,*tsh,*tsl;
    __nv_bfloat16 *pwh,*pwl,*wAh,*wAl,*awh,*awl,*twAh,*twAl,*vth,*vtl,*tvth,*tvtl;
    cudaGetSymbolAddress((void**)&path_h, g_path_h); cudaGetSymbolAddress((void**)&path_l, g_path_l);
    cudaGetSymbolAddress((void**)&xh,  g_xh);  cudaGetSymbolAddress((void**)&xl,  g_xl);
    cudaGetSymbolAddress((void**)&qh,  g_qh);  cudaGetSymbolAddress((void**)&ql,  g_ql);
    cudaGetSymbolAddress((void**)&kh,  g_kh);  cudaGetSymbolAddress((void**)&kl,  g_kl);
    cudaGetSymbolAddress((void**)&ph,  g_ph);  cudaGetSymbolAddress((void**)&pl,  g_pl);
    cudaGetSymbolAddress((void**)&oh,  g_oh);  cudaGetSymbolAddress((void**)&ol,  g_ol);
    cudaGetSymbolAddress((void**)&yh,  g_yh);  cudaGetSymbolAddress((void**)&yl,  g_yl);
    cudaGetSymbolAddress((void**)&tqh, g_tqh); cudaGetSymbolAddress((void**)&tql, g_tql);
    cudaGetSymbolAddress((void**)&tkh, g_tkh); cudaGetSymbolAddress((void**)&tkl, g_tkl);
    cudaGetSymbolAddress((void**)&tsh, g_tsh); cudaGetSymbolAddress((void**)&tsl, g_tsl);
    cudaGetSymbolAddress((void**)&pwh,  g_pwh);  cudaGetSymbolAddress((void**)&pwl,  g_pwl);
    cudaGetSymbolAddress((void**)&wAh,  g_wAh);  cudaGetSymbolAddress((void**)&wAl,  g_wAl);
    cudaGetSymbolAddress((void**)&awh,  g_awh);  cudaGetSymbolAddress((void**)&awl,  g_awl);
    cudaGetSymbolAddress((void**)&twAh, g_twAh); cudaGetSymbolAddress((void**)&twAl, g_twAl);
    cudaGetSymbolAddress((void**)&vth,  g_vth);  cudaGetSymbolAddress((void**)&vtl,  g_vtl);
    cudaGetSymbolAddress((void**)&tvth, g_tvth); cudaGetSymbolAddress((void**)&tvtl, g_tvtl);

    const long long sXB  = (long long)SEQ*DIM;
    const long long sQH  = (long long)SEQ*DIM;
    const long long sSSp = (long long)SEQ*SEQP;
    const long long sY   = (long long)CDIM*TDIM;
    const long long sTS  = (long long)CDIM*CDIM;
    const long long sW   = (long long)DIM*DIM;
    const long long sVT  = (long long)DIM*SEQP;
    const long long sTVT = (long long)TDIM*CDIM;
    const long long sTW  = (long long)TDIM*TDIM;
    const float scale1 = (float)(1.0/sqrt(512.0));
    const float scale2 = (float)(1.0/sqrt(1576.0));
    const float cc1 = (float)(-2.0*log2(10000.0)/512.0);
    const float cc2 = (float)(-2.0*log2(10000.0)/1576.0);
    dim3 tcb(32, 8);

    // ---- weight pre-conversion into combined buffers ----
    tconv<<<dim3(DIM/32, PK/32, 1), tcb>>>(patch_W, pwh, pwl, PK, DIM, PK, 0, 0);
    for (int l = 0; l < 2; l++) {
        const float* srcs[3] = {Wq, Wk, Wv};
        for (int w = 0; w < 3; w++) {
            tconv<<<dim3(16, 16, 8), tcb>>>(srcs[w] + (long long)l*8*sW,
                                            wAh + ((long long)l*24 + w*8)*sW,
                                            wAl + ((long long)l*24 + w*8)*sW,
                                            DIM, DIM, DIM, sW, sW);
        }
        const float* tsrcs[3] = {tWq, tWk, tWv};
        for (int w = 0; w < 3; w++) {
            tconv<<<dim3(50, 50, 1), tcb>>>(tsrcs[w] + (long long)l*sTW,
                                            twAh + ((long long)l*3 + w)*sTW,
                                            twAl + ((long long)l*3 + w)*sTW,
                                            TDIM, TDIM, TDIM, 0, 0);
        }
    }
    tconv<<<dim3(16, 16, 16), tcb>>>(attn_W, awh, awl, DIM, DIM, DIM, sW, sW);

    // ---- patch embedding (BM=64 path: 100 blocks) ----
    patch_gather2<<<nblk((long long)BATCH*NPATCH*PK,256),256>>>(img, path_h, path_l);
    run_hgemm(path_h, path_l, pwh, pwl, patch_b, 0, pxp, 0, 0,
              BATCH*NPATCH, DIM, PK, PK, PK, DIM,
              P_NONE, P_NONE, 0, 0, 1, 1.f, 0);
    assemble_x_kernel<<<nblk((long long)BATCH*SEQ*DIM,256),256>>>(pxp, cls_token, px);

    for (int l = 0; l < 2; l++) {
        const float* scale_l = rms_scale + (long long)l*SEQ*DIM;

        // rmsnorm #1 (+split)
        rms_part_kernel<<<dim3(32,BATCH),256>>>(px, pred);
        rms_fin_kernel<<<1,256>>>(pred, pf);
        rms_apply2<<<nblk((long long)BATCH*SEQ*DIM/4,256),256>>>(px, pf, scale_l,
                                                                 (uint2*)xh, (uint2*)xl);

        // fused QKV: z = w*64 + b*8 + h  (192 batches, one launch)
        run_hgemm(xh, xl, wAh + (long long)l*24*sW, wAl + (long long)l*24*sW, 0, 0, pqkv, 0, 0,
                  SEQ, DIM, DIM, DIM, DIM, DIM,
                  64, 0LL, 8, sXB, 0LL,            // A: b = (z%64)/8
                  64, 8*sW, 8, 0LL, sW,            // B: w*8*sW + h*sW
                  0, sQH, 192, 1.f, 0);

        // v -> vT split [DIM][SEQP]
        tconv<<<dim3(16, 7, 64), tcb>>>(pqkv + 128*sQH, vth, vtl, SEQ, DIM, SEQP, sQH, sVT);

        // RoPE -> split q,k  (q at slices 0..63, k at 64..127)
        rope2<<<nblk((long long)64*SEQ*(DIM/2),256),256>>>(pqkv, pqkv + 64*sQH,
                                                           qh, ql, kh, kl, 64, SEQ, DIM, cc1);

        // scores
        run_hgemm(qh, ql, kh, kl, 0, 0, ps, 0, 0,
                  SEQ, SEQ, DIM, DIM, DIM, SEQP,
                  P_PLAIN(sQH), P_PLAIN(sQH), 0, sSSp, 64, scale1, 0);
        softmax2<<<nblk((long long)64*SEQ*32,256),256>>>(ps, ph, pl, 64*SEQ, SEQ, SEQP);

        // o = p @ v  (epilogue emits split oh/ol directly)
        run_hgemm(ph, pl, vth, vtl, 0, 0, po, oh, ol,
                  SEQ, DIM, SEQP, SEQP, SEQP, DIM,
                  P_PLAIN(sSSp), P_PLAIN(sVT), 0, sQH, 64, 1.f, 0);

        // per-head proj partials + reduce
        run_hgemm(oh, ol, awh + (long long)l*8*sW, awl + (long long)l*8*sW, 0, 0, pot, 0, 0,
                  SEQ, DIM, DIM, DIM, DIM, DIM,
                  P_PLAIN(sQH), P_LOW8(sW), 0, sQH, 64, 1.f, 0);
        attn_reduce_kernel<<<nblk((long long)BATCH*SEQ*DIM/4,256),256>>>(pot, attn_b + l*DIM, px);

        // rmsnorm #2 (+split)
        rms_part_kernel<<<dim3(32,BATCH),256>>>(px, pred);
        rms_fin_kernel<<<1,256>>>(pred, pf);
        rms_apply2<<<nblk((long long)BATCH*SEQ*DIM/4,256),256>>>(px, pf, scale_l,
                                                                 (uint2*)xh, (uint2*)xl);

        // token-mixing
        x_to_y2<<<nblk((long long)BATCH*CDIM*TDIM,256),256>>>(px, py, yh, yl);

        // fused token QKV: z = w*8 + b (24 batches, one launch, 312 blocks)
        run_hgemm(yh, yl, twAh + (long long)l*3*sTW, twAl + (long long)l*3*sTW, 0, 0, ptqkv, 0, 0,
                  CDIM, TDIM, TDIM, TDIM, TDIM, TDIM,
                  (1<<30), 0LL, 8, 0LL, sY,        // A: b = z%8
                  (1<<30), 0LL, 8, sTW, 0LL,       // B: w = z/8
                  0, sY, 24, 1.f, 0);

        // tv -> tvT split
        tconv<<<dim3(50, 2, 8), tcb>>>(ptqkv + 16*sY, tvth, tvtl, CDIM, TDIM, CDIM, sY, sTVT);

        // RoPE -> split tq,tk (tq slices 0..7, tk 8..15)
        rope2<<<nblk((long long)BATCH*CDIM*(TDIM/2),256),256>>>(ptqkv, ptqkv + 8*sY,
                                                                 tqh, tql, tkh, tkl,
                                                                 BATCH, CDIM, TDIM, cc2);

        // token scores
        run_hgemm(tqh, tql, tkh, tkl, 0, 0, pts, 0, 0,
                  CDIM, CDIM, TDIM, TDIM, TDIM, CDIM,
                  P_PLAIN(sY), P_PLAIN(sY), 0, sTS, BATCH, scale2, 0);
        softmax2<<<nblk((long long)BATCH*CDIM*32,256),256>>>(pts, tsh, tsl,
                                                             BATCH*CDIM, CDIM, CDIM);

        // y += p @ tv
        run_hgemm(tsh, tsl, tvth, tvtl, 0, py, py, 0, 0,
                  CDIM, TDIM, CDIM, CDIM, CDIM, TDIM,
                  P_PLAIN(sTS), P_PLAIN(sTVT), sY, sY, BATCH, 1.f, 1);

        y_to_x_kernel<<<nblk((long long)BATCH*SEQ*DIM,256),256>>>(py, px);
    }

    // ---- final: cls layernorm + head ----
    cls_ln_kernel<<<BATCH,256>>>(px, ln_g, ln_b, pcls);
    {
        dim3 grid((NCLS+31)/32, 1, 1);
        sgemm_s<<<grid, 64>>>(pcls, head_W, head_b, out, BATCH, NCLS, DIM, DIM, NCLS, NCLS);
    }
}

// round 12
// speedup vs baseline: 7.3943x; 1.1103x over previous
#include <cuda_runtime.h>
#include <cuda_bf16.h>
#include <math.h>
#include <stdint.h>

#define BATCH 8
#define HEADS 8
#define DIM 512
#define SEQ 197
#define SEQP 208
#define NPATCH 196
#define PK 768
#define CDIM 64
#define TDIM 1576
#define NCLS 1000

// ---------------- fp32 scratch ----------------
__device__ float g_xp[BATCH*NPATCH*DIM];
__device__ float g_x[BATCH*SEQ*DIM];
__device__ float g_qkv[192*SEQ*DIM];          // [w][h][b][SEQ][DIM]
__device__ float g_sc[BATCH*HEADS*SEQ*SEQP];
__device__ float g_o[BATCH*HEADS*SEQ*DIM];
__device__ float g_ot[BATCH*SEQ*HEADS*DIM];   // proj partials [h][b][SEQ][DIM]
__device__ float g_y[BATCH*CDIM*TDIM];
__device__ float g_tqkv[24*CDIM*TDIM];        // [w][b][CDIM][TDIM]
__device__ float g_ts[BATCH*CDIM*CDIM];
__device__ float g_fac[BATCH];
__device__ float g_red[BATCH*32];
__device__ float g_cls[BATCH*DIM];

// ---------------- bf16 hi/lo split operands (K-major) ----------------
__device__ __nv_bfloat16 g_path_h[BATCH*NPATCH*PK],  g_path_l[BATCH*NPATCH*PK];
__device__ __nv_bfloat16 g_xh[BATCH*SEQ*DIM],        g_xl[BATCH*SEQ*DIM];
__device__ __nv_bfloat16 g_qh[BATCH*HEADS*SEQ*DIM],  g_ql[BATCH*HEADS*SEQ*DIM];
__device__ __nv_bfloat16 g_kh[BATCH*HEADS*SEQ*DIM],  g_kl[BATCH*HEADS*SEQ*DIM];
__device__ __nv_bfloat16 g_ph[BATCH*HEADS*SEQ*SEQP], g_pl[BATCH*HEADS*SEQ*SEQP];
__device__ __nv_bfloat16 g_oh[BATCH*HEADS*SEQ*DIM],  g_ol[BATCH*HEADS*SEQ*DIM];
__device__ __nv_bfloat16 g_yh[BATCH*CDIM*TDIM],      g_yl[BATCH*CDIM*TDIM];
__device__ __nv_bfloat16 g_tqh[BATCH*CDIM*TDIM],     g_tql[BATCH*CDIM*TDIM];
__device__ __nv_bfloat16 g_tkh[BATCH*CDIM*TDIM],     g_tkl[BATCH*CDIM*TDIM];
__device__ __nv_bfloat16 g_tsh[BATCH*CDIM*CDIM],     g_tsl[BATCH*CDIM*CDIM];
// weights
__device__ __nv_bfloat16 g_pwh[DIM*PK],            g_pwl[DIM*PK];
__device__ __nv_bfloat16 g_wAh[2*3*8*DIM*DIM],     g_wAl[2*3*8*DIM*DIM];   // [l][w][h]
__device__ __nv_bfloat16 g_awh[16*DIM*DIM],        g_awl[16*DIM*DIM];
__device__ __nv_bfloat16 g_twAh[2*3*TDIM*TDIM],    g_twAl[2*3*TDIM*TDIM]; // [l][w]
__device__ __nv_bfloat16 g_vth[64*DIM*SEQP],       g_vtl[64*DIM*SEQP];
__device__ __nv_bfloat16 g_tvth[8*TDIM*CDIM],      g_tvtl[8*TDIM*CDIM];

// ---------------- helpers ----------------
__device__ __forceinline__ void cvt4(float4 v, uint2 &h, uint2 &l){
    __nv_bfloat16 ax=__float2bfloat16_rn(v.x), ay=__float2bfloat16_rn(v.y);
    __nv_bfloat16 az=__float2bfloat16_rn(v.z), aw=__float2bfloat16_rn(v.w);
    __nv_bfloat162 h0; h0.x=ax; h0.y=ay;
    __nv_bfloat162 h1; h1.x=az; h1.y=aw;
    h.x=*(unsigned*)&h0; h.y=*(unsigned*)&h1;
    __nv_bfloat162 l0; l0.x=__float2bfloat16_rn(v.x-__bfloat162float(ax));
                       l0.y=__float2bfloat16_rn(v.y-__bfloat162float(ay));
    __nv_bfloat162 l1; l1.x=__float2bfloat16_rn(v.z-__bfloat162float(az));
                       l1.y=__float2bfloat16_rn(v.w-__bfloat162float(aw));
    l.x=*(unsigned*)&l0; l.y=*(unsigned*)&l1;
}
__device__ __forceinline__ void cvt2(float a, float b, uint32_t &h, uint32_t &l){
    __nv_bfloat16 ha=__float2bfloat16_rn(a), hb=__float2bfloat16_rn(b);
    __nv_bfloat162 H; H.x=ha; H.y=hb; h=*(uint32_t*)&H;
    __nv_bfloat162 L; L.x=__float2bfloat16_rn(a-__bfloat162float(ha));
                      L.y=__float2bfloat16_rn(b-__bfloat162float(hb)); l=*(uint32_t*)&L;
}
__device__ __forceinline__ void cvt1(float a, __nv_bfloat16 &h, __nv_bfloat16 &l){
    h=__float2bfloat16_rn(a);
    l=__float2bfloat16_rn(a-__bfloat162float(h));
}
__device__ __forceinline__ void ldsm4(unsigned r[4], const __nv_bfloat16* p) {
    unsigned a = (unsigned)__cvta_generic_to_shared(p);
    asm volatile("ldmatrix.sync.aligned.m8n8.x4.shared.b16 {%0,%1,%2,%3}, [%4];"
                 : "=r"(r[0]), "=r"(r[1]), "=r"(r[2]), "=r"(r[3]) : "r"(a));
}
__device__ __forceinline__ void mma16816(float c[4], const unsigned a[4],
                                         unsigned b0, unsigned b1) {
    asm volatile("mma.sync.aligned.m16n8k16.row.col.f32.bf16.bf16.f32 "
                 "{%0,%1,%2,%3}, {%4,%5,%6,%7}, {%8,%9}, {%0,%1,%2,%3};"
                 : "+f"(c[0]), "+f"(c[1]), "+f"(c[2]), "+f"(c[3])
                 : "r"(a[0]), "r"(a[1]), "r"(a[2]), "r"(a[3]), "r"(b0), "r"(b1));
}
__device__ __forceinline__ void cp16(uint32_t dst, const void* src, bool valid){
    uint64_t g;
    asm("cvta.to.global.u64 %0, %1;" : "=l"(g) : "l"(src));
    int sz = valid ? 16 : 0;
    asm volatile("cp.async.cg.shared.global [%0], [%1], 16, %2;"
                 :: "r"(dst), "l"(g), "r"(sz) : "memory");
}
#define CP_COMMIT() asm volatile("cp.async.commit_group;" ::: "memory")

// ================= bf16 split GEMM: cp.async 3-stage pipeline, generic batching =============
// off(z) = (z/D1)*S1 + ((z%D1)/D2)*S2 + (z%D2)*S3  for A and B independently.
template<int BM>
__global__ __launch_bounds__(BM*2)
void hgemm3(const __nv_bfloat16* __restrict__ Ah, const __nv_bfloat16* __restrict__ Al,
            const __nv_bfloat16* __restrict__ Bh, const __nv_bfloat16* __restrict__ Bl,
            const float* __restrict__ bias, const float* __restrict__ Cin,
            float* __restrict__ C,
            __nv_bfloat16* __restrict__ Ch, __nv_bfloat16* __restrict__ Cl,
            int M, int N, int K, int lda, int ldb, int ldc,
            int aD1, long long aS1, int aD2, long long aS2, long long aS3,
            int bD1, long long bS1, int bD2, long long bS2, long long bS3,
            long long sCin, long long sC, float alpha, int addC)
{
    constexpr int WARPS_M = BM/64;
    constexpr int THREADS = BM*2;
    constexpr int A_CH = BM*4/THREADS;       // 16B chunks per thread (A hi)
    constexpr int B_CH = 512/THREADS;        // 16B chunks per thread (B hi)
    constexpr int SH = (2*BM + 256)*40;      // halves per stage
    const int OFF_AL = BM*40, OFF_BH = 2*BM*40;
    extern __shared__ __align__(16) __nv_bfloat16 sm[];
    uint32_t smem_base = (uint32_t)__cvta_generic_to_shared(sm);

    int z = blockIdx.z;
    long long ao = (long long)(z / aD1)*aS1 + (long long)((z % aD1) / aD2)*aS2
                 + (long long)(z % aD2)*aS3;
    long long bo = (long long)(z / bD1)*bS1 + (long long)((z % bD1) / bD2)*bS2
                 + (long long)(z % bD2)*bS3;
    Ah += ao; Al += ao; Bh += bo; Bl += bo;
    long long co = (long long)z * sC;
    C += co;
    if (Ch){ Ch += co; Cl += co; }
    const float* Cr = addC ? Cin + (long long)z * sCin : (const float*)0;

    int row0 = blockIdx.y*BM, col0 = blockIdx.x*128;
    int tid = threadIdx.x, lane = tid & 31, warp = tid >> 5;
    int wm0 = (warp % WARPS_M)*64;
    int wn0 = (warp / WARPS_M)*32;

    float acc[4][4][4];
#pragma unroll
    for (int i=0;i<4;i++)
#pragma unroll
      for (int j=0;j<4;j++)
#pragma unroll
        for (int t=0;t<4;t++) acc[i][j][t]=0.f;

    auto issue = [&](int kt){
        int st = kt % 3;
        uint32_t sb = smem_base + st*SH*2;
        int k0 = kt*32;
#pragma unroll
        for (int t = 0; t < A_CH; t++){
            int idx = tid + t*THREADS;
            int row = idx >> 2, k8 = idx & 3;
            int gm = row0 + row, gk = k0 + k8*8;
            bool v = (gm < M) && (gk < K);
            long long go = (long long)gm*lda + gk;
            uint32_t d = sb + (uint32_t)(row*40 + k8*8)*2;
            cp16(d, v ? Ah+go : Ah, v);
            cp16(d + OFF_AL*2, v ? Al+go : Al, v);
        }
#pragma unroll
        for (int t = 0; t < B_CH; t++){
            int idx = tid + t*THREADS;
            int row = idx >> 2, k8 = idx & 3;
            int gn = col0 + row, gk = k0 + k8*8;
            bool v = (gn < N) && (gk < K);
            long long go = (long long)gn*ldb + gk;
            uint32_t d = sb + (uint32_t)(OFF_BH + row*40 + k8*8)*2;
            cp16(d, v ? Bh+go : Bh, v);
            cp16(d + 128*40*2, v ? Bl+go : Bl, v);
        }
    };

    int r8 = lane&7, s1 = (lane>>3)&1, s2 = lane>>4;
    auto compute = [&](int st, int kk){
        const __nv_bfloat16* base = sm + st*SH;
        unsigned ah[4][4], al[4][4], bh[2][4], bl[2][4];
#pragma unroll
        for (int mt=0;mt<4;mt++){
            int row = wm0 + mt*16 + r8 + s1*8;
            int col = kk + s2*8;
            ldsm4(ah[mt], base + row*40 + col);
            ldsm4(al[mt], base + OFF_AL + row*40 + col);
        }
#pragma unroll
        for (int np=0;np<2;np++){
            int row = wn0 + np*16 + r8 + s2*8;
            int col = kk + s1*8;
            ldsm4(bh[np], base + OFF_BH + row*40 + col);
            ldsm4(bl[np], base + OFF_BH + 128*40 + row*40 + col);
        }
#pragma unroll
        for (int mt=0;mt<4;mt++)
#pragma unroll
            for (int nt=0;nt<4;nt++){
                unsigned b0h = bh[nt>>1][(nt&1)*2], b1h = bh[nt>>1][(nt&1)*2+1];
                unsigned b0l = bl[nt>>1][(nt&1)*2], b1l = bl[nt>>1][(nt&1)*2+1];
                mma16816(acc[mt][nt], ah[mt], b0h, b1h);
                mma16816(acc[mt][nt], al[mt], b0h, b1h);
                mma16816(acc[mt][nt], ah[mt], b0l, b1l);
            }
    };

    int nk = (K + 31) / 32;
    issue(0); CP_COMMIT();
    if (nk > 1){ issue(1); CP_COMMIT(); }
    for (int kt = 0; kt < nk; kt++){
        if (kt + 1 < nk) { asm volatile("cp.async.wait_group 1;" ::: "memory"); }
        else             { asm volatile("cp.async.wait_group 0;" ::: "memory"); }
        __syncthreads();
        int st = kt % 3;
        compute(st, 0);
        compute(st, 16);
        if (kt + 2 < nk){ issue(kt+2); CP_COMMIT(); }
    }

    // epilogue
    int gid = lane>>2, tq = lane&3;
#pragma unroll
    for (int mt=0;mt<4;mt++)
#pragma unroll
      for (int h=0;h<2;h++){
        int gm = row0 + wm0 + mt*16 + gid + h*8;
        if (gm>=M) continue;
        long long base = (long long)gm*ldc;
#pragma unroll
        for (int nt=0;nt<4;nt++){
          int gn = col0 + wn0 + nt*8 + tq*2;
          if (gn>=N) continue;
          float v0 = alpha*acc[mt][nt][h*2+0];
          float v1 = alpha*acc[mt][nt][h*2+1];
          if (bias){ v0 += bias[gn]; if (gn+1<N) v1 += bias[gn+1]; }
          if (Cr)  { v0 += Cr[base+gn]; if (gn+1<N) v1 += Cr[base+gn+1]; }
          if (gn+1<N){
            float2 st2; st2.x=v0; st2.y=v1; *(float2*)&C[base+gn]=st2;
            if (Ch){
              uint32_t hh, ll; cvt2(v0, v1, hh, ll);
              *(uint32_t*)&Ch[base+gn] = hh;
              *(uint32_t*)&Cl[base+gn] = ll;
            }
          } else {
            C[base+gn]=v0;
            if (Ch){ __nv_bfloat16 hh, ll; cvt1(v0, hh, ll); Ch[base+gn]=hh; Cl[base+gn]=ll; }
          }
        }
      }
}

#define P_NONE  (1<<30), 0LL, 1, 0LL, 0LL
#define P_PLAIN(s) (1<<30), 0LL, 1, (long long)(s), 0LL

static void run_hgemm(const __nv_bfloat16* Ah, const __nv_bfloat16* Al,
                      const __nv_bfloat16* Bh, const __nv_bfloat16* Bl,
                      const float* bias, const float* Cin, float* C,
                      __nv_bfloat16* Ch, __nv_bfloat16* Cl,
                      int M, int N, int K, int lda, int ldb, int ldc,
                      int aD1, long long aS1, int aD2, long long aS2, long long aS3,
                      int bD1, long long bS1, int bD2, long long bS2, long long bS3,
                      long long sCin, long long sC, int batch, float alpha, int addC)
{
    long long b128 = (long long)((N+127)/128)*((M+127)/128)*batch;
    if (M >= 96 && b128 >= 90) {
        constexpr int SM = 3*(2*128+256)*40*2;   // 122880 B
        cudaFuncSetAttribute(hgemm3<128>, cudaFuncAttributeMaxDynamicSharedMemorySize, SM);
        dim3 grid((N+127)/128, (M+127)/128, batch);
        hgemm3<128><<<grid, 256, SM>>>(Ah,Al,Bh,Bl,bias,Cin,C,Ch,Cl,M,N,K,lda,ldb,ldc,
            aD1,aS1,aD2,aS2,aS3,bD1,bS1,bD2,bS2,bS3,sCin,sC,alpha,addC);
    } else {
        constexpr int SM = 3*(2*64+256)*40*2;    // 92160 B
        cudaFuncSetAttribute(hgemm3<64>, cudaFuncAttributeMaxDynamicSharedMemorySize, SM);
        dim3 grid((N+127)/128, (M+63)/64, batch);
        hgemm3<64><<<grid, 128, SM>>>(Ah,Al,Bh,Bl,bias,Cin,C,Ch,Cl,M,N,K,lda,ldb,ldc,
            aD1,aS1,aD2,aS2,aS3,bD1,bS1,bD2,bS2,bS3,sCin,sC,alpha,addC);
    }
}

// ================= transpose-convert: fp32 [K][N] -> bf16 hi/lo [N][Kp] =================
__global__ void tconv(const float* __restrict__ in, __nv_bfloat16* __restrict__ oh,
                      __nv_bfloat16* __restrict__ ol,
                      int K, int N, int Kp, long long sIn, long long sOut)
{
    __shared__ float t[32][33];
    int z = blockIdx.z;
    const float* I = in + (long long)z * sIn;
    __nv_bfloat16* OH = oh + (long long)z * sOut;
    __nv_bfloat16* OL = ol + (long long)z * sOut;
    int kb = blockIdx.y * 32, nb = blockIdx.x * 32;
    for (int i = threadIdx.y; i < 32; i += 8) {
        int k = kb + i, n = nb + threadIdx.x;
        t[i][threadIdx.x] = (k < K && n < N) ? I[(long long)k*N + n] : 0.f;
    }
    __syncthreads();
    for (int i = threadIdx.y; i < 32; i += 8) {
        int n = nb + i, k = kb + threadIdx.x;
        if (n < N && k < Kp) {
            __nv_bfloat16 h, l; cvt1(t[threadIdx.x][i], h, l);
            OH[(long long)n*Kp + k] = h;
            OL[(long long)n*Kp + k] = l;
        }
    }
}

// ---------------- fp32 fallback GEMM (final head, M=8) ----------------
__global__ __launch_bounds__(64)
void sgemm_s(const float* __restrict__ A, const float* __restrict__ B,
             const float* __restrict__ bias, float* __restrict__ C,
             int M, int N, int K, int lda, int ldb, int ldc)
{
    constexpr int BK = 16;
    __shared__ float As[BK][36];
    __shared__ float Bs[BK][36];
    int row0 = blockIdx.y*32, col0 = blockIdx.x*32;
    int tid = threadIdx.x;
    int tx = tid % 8, ty = tid / 8;
    float acc[4][4];
#pragma unroll
    for (int i=0;i<4;i++)
#pragma unroll
      for (int j=0;j<4;j++) acc[i][j]=0.f;
    for (int k0 = 0; k0 < K; k0 += BK) {
        for (int e = tid; e < 32*BK/4; e += 64) {
            int mm = e >> 2, c4 = e & 3;
            int gm = row0+mm, gk = k0+c4*4;
            float4 v = make_float4(0.f,0.f,0.f,0.f);
            if (gm < M && gk < K) v = *(const float4*)&A[(long long)gm*lda+gk];
            As[c4*4+0][mm]=v.x; As[c4*4+1][mm]=v.y; As[c4*4+2][mm]=v.z; As[c4*4+3][mm]=v.w;
        }
        for (int e = tid; e < BK*8; e += 64) {
            int kk = e / 8, n4 = e % 8;
            int gk = k0+kk, gn = col0+n4*4;
            float4 v = make_float4(0.f,0.f,0.f,0.f);
            if (gk < K) {
                if (gn+3 < N) v = *(const float4*)&B[(long long)gk*ldb+gn];
                else {
                    const float* p = &B[(long long)gk*ldb];
                    if (gn<N)v.x=p[gn]; if (gn+1<N)v.y=p[gn+1];
                    if (gn+2<N)v.z=p[gn+2]; if (gn+3<N)v.w=p[gn+3];
                }
            }
            Bs[kk][n4*4+0]=v.x; Bs[kk][n4*4+1]=v.y; Bs[kk][n4*4+2]=v.z; Bs[kk][n4*4+3]=v.w;
        }
        __syncthreads();
#pragma unroll
        for (int kk = 0; kk < BK; kk++) {
            float a[4], b[4];
#pragma unroll
            for (int i=0;i<4;i++) a[i]=As[kk][ty*4+i];
#pragma unroll
            for (int j=0;j<4;j++) b[j]=Bs[kk][tx*4+j];
#pragma unroll
            for (int i=0;i<4;i++)
#pragma unroll
              for (int j=0;j<4;j++) acc[i][j]+=a[i]*b[j];
        }
        __syncthreads();
    }
#pragma unroll
    for (int i=0;i<4;i++){
        int gm = row0+ty*4+i;
        if (gm >= M) continue;
#pragma unroll
        for (int j=0;j<4;j++){
            int gn = col0+tx*4+j;
            if (gn >= N) continue;
            float v = acc[i][j];
            if (bias) v += bias[gn];
            C[(long long)gm*ldc+gn] = v;
        }
    }
}

// ---------------- elementwise kernels ----------------
__global__ void patch_gather2(const float* __restrict__ img,
                              __nv_bfloat16* __restrict__ oh, __nv_bfloat16* __restrict__ ol) {
    int idx = blockIdx.x*blockDim.x + threadIdx.x;
    int total = BATCH*NPATCH*PK;
    if (idx >= total) return;
    int k = idx % PK;
    int p = (idx / PK) % NPATCH;
    int b = idx / (PK*NPATCH);
    int c  = k % 3;
    int pj = (k/3) % 16;
    int pi = k / 48;
    int i = p / 14, j = p % 14;
    float v = img[(((long long)b*3 + c)*224 + (i*16+pi))*224 + (j*16+pj)];
    __nv_bfloat16 h, l; cvt1(v, h, l);
    oh[idx] = h; ol[idx] = l;
}

__global__ void assemble_x_kernel(const float* __restrict__ xp, const float* __restrict__ cls,
                                  float* __restrict__ x) {
    int idx = blockIdx.x*blockDim.x + threadIdx.x;
    int total = BATCH*SEQ*DIM;
    if (idx >= total) return;
    int d = idx % DIM;
    int m = (idx / DIM) % SEQ;
    int b = idx / (DIM*SEQ);
    x[idx] = (m == 0) ? cls[d] : xp[((long long)b*NPATCH + (m-1))*DIM + d];
}

__global__ void rms_part_kernel(const float* __restrict__ x, float* __restrict__ red) {
    int b = blockIdx.y, ch = blockIdx.x;
    const int per_batch = SEQ*DIM;
    const int chunk = per_batch/32;
    const float4* p = (const float4*)(x + (long long)b*per_batch + ch*chunk);
    float s = 0.f;
    for (int i = threadIdx.x; i < chunk/4; i += 256) {
        float4 v = p[i];
        s += v.x*v.x + v.y*v.y + v.z*v.z + v.w*v.w;
    }
    __shared__ float sm[256];
    sm[threadIdx.x] = s; __syncthreads();
    for (int o = 128; o > 0; o >>= 1) { if (threadIdx.x < o) sm[threadIdx.x] += sm[threadIdx.x+o]; __syncthreads(); }
    if (threadIdx.x == 0) red[b*32 + ch] = sm[0];
}
__global__ void rms_fin_kernel(const float* __restrict__ red, float* __restrict__ fac) {
    int b = threadIdx.x / 32, lane = threadIdx.x % 32;
    float v = red[b*32 + lane];
    for (int o = 16; o; o >>= 1) v += __shfl_xor_sync(0xffffffffu, v, o);
    if (lane == 0) fac[b] = sqrtf((float)(SEQ*DIM) / v);
}
__global__ void rms_apply2(float* __restrict__ x, const float* __restrict__ fac,
                           const float* __restrict__ scale,
                           uint2* __restrict__ xh, uint2* __restrict__ xl) {
    int idx = blockIdx.x*blockDim.x + threadIdx.x;
    const int per4 = SEQ*DIM/4;
    int total = BATCH*per4;
    if (idx >= total) return;
    int b = idx / per4, s4 = idx % per4;
    float f = fac[b];
    float4 v = ((float4*)x)[idx];
    float4 sc = ((const float4*)scale)[s4];
    v.x *= f*sc.x; v.y *= f*sc.y; v.z *= f*sc.z; v.w *= f*sc.w;
    ((float4*)x)[idx] = v;
    uint2 h, l; cvt4(v, h, l);
    xh[idx] = h; xl[idx] = l;
}

__global__ void rope2(const float* __restrict__ q, const float* __restrict__ k,
                      __nv_bfloat16* __restrict__ qh, __nv_bfloat16* __restrict__ ql,
                      __nv_bfloat16* __restrict__ kh, __nv_bfloat16* __restrict__ kl,
                      int Z, int M, int D, float cc) {
    int half = D / 2;
    long long total = (long long)Z * M * half;
    long long idx = (long long)blockIdx.x*blockDim.x + threadIdx.x;
    if (idx >= total) return;
    int i = (int)(idx % half);
    int m = (int)((idx / half) % M);
    long long z = idx / ((long long)half * M);
    float theta = exp2f(cc * ((float)i - 1.f));
    float ang = (float)m * theta;
    float s, c;
    sincosf(ang, &s, &c);
    long long base = ((z*M) + m) * (long long)D + 2*i;
    float xe, xo, re, ro;
    uint32_t h, l;
    xe = q[base]; xo = q[base+1];
    re = xe*c + xo*s; ro = -xe*s + xo*c;
    cvt2(re, ro, h, l);
    *(uint32_t*)&qh[base] = h; *(uint32_t*)&ql[base] = l;
    xe = k[base]; xo = k[base+1];
    re = xe*c + xo*s; ro = -xe*s + xo*c;
    cvt2(re, ro, h, l);
    *(uint32_t*)&kh[base] = h; *(uint32_t*)&kl[base] = l;
}

__global__ void softmax2(float* __restrict__ s,
                         __nv_bfloat16* __restrict__ ph, __nv_bfloat16* __restrict__ pl,
                         int rows, int L, int ld) {
    int warp = (blockIdx.x*blockDim.x + threadIdx.x) / 32;
    int lane = threadIdx.x % 32;
    if (warp >= rows) return;
    long long ro = (long long)warp * ld;
    float* row = s + ro;
    float mx = -1e30f;
    for (int i = lane; i < L; i += 32) mx = fmaxf(mx, row[i]);
    for (int o = 16; o; o >>= 1) mx = fmaxf(mx, __shfl_xor_sync(0xffffffffu, mx, o));
    float sum = 0.f;
    for (int i = lane; i < L; i += 32) { float e = __expf(row[i]-mx); row[i] = e; sum += e; }
    for (int o = 16; o; o >>= 1) sum += __shfl_xor_sync(0xffffffffu, sum, o);
    float inv = 1.f / sum;
    for (int i = lane; i < ld; i += 32) {
        float v = (i < L) ? row[i]*inv : 0.f;
        __nv_bfloat16 h, l; cvt1(v, h, l);
        ph[ro + i] = h; pl[ro + i] = l;
    }
}

// x[b][m][:] += bias + sum_h part[(h*8+b)][m][:]   ([h][b] slice order)
__global__ void attn_reduce_kernel(const float* __restrict__ part,
                                   const float* __restrict__ bias,
                                   float* __restrict__ x) {
    int idx = blockIdx.x*blockDim.x + threadIdx.x;
    const int D4 = DIM/4;
    int total = BATCH*SEQ*D4;
    if (idx >= total) return;
    int d4 = idx % D4;
    int m  = (idx / D4) % SEQ;
    int b  = idx / (D4*SEQ);
    float4 acc = ((float4*)x)[idx];
    float4 bb = ((const float4*)bias)[d4];
    acc.x += bb.x; acc.y += bb.y; acc.z += bb.z; acc.w += bb.w;
#pragma unroll
    for (int h = 0; h < HEADS; h++) {
        float4 p = ((const float4*)part)[((long long)(h*BATCH+b)*SEQ + m)*D4 + d4];
        acc.x += p.x; acc.y += p.y; acc.z += p.z; acc.w += p.w;
    }
    ((float4*)x)[idx] = acc;
}

__global__ void x_to_y2(const float* __restrict__ x, float* __restrict__ y,
                        __nv_bfloat16* __restrict__ yh, __nv_bfloat16* __restrict__ yl) {
    int idx = blockIdx.x*blockDim.x + threadIdx.x;
    int total = BATCH*CDIM*TDIM;
    if (idx >= total) return;
    int t = idx % TDIM;
    int c = (idx / TDIM) % CDIM;
    int b = idx / (TDIM*CDIM);
    int f = t / SEQ, mm = t % SEQ;
    float v = x[((long long)b*SEQ + mm)*DIM + c*8 + f];
    y[idx] = v;
    __nv_bfloat16 h, l; cvt1(v, h, l);
    yh[idx] = h; yl[idx] = l;
}

__global__ void y_to_x_kernel(const float* __restrict__ y, float* __restrict__ x) {
    int idx = blockIdx.x*blockDim.x + threadIdx.x;
    int total = BATCH*SEQ*DIM;
    if (idx >= total) return;
    int d  = idx % DIM;
    int mm = (idx / DIM) % SEQ;
    int b  = idx / (DIM*SEQ);
    int c = d >> 3, f = d & 7;
    x[idx] = y[((long long)b*CDIM + c)*TDIM + f*SEQ + mm];
}

__global__ void cls_ln_kernel(const float* __restrict__ x, const float* __restrict__ g,
                              const float* __restrict__ be, float* __restrict__ out) {
    int b = blockIdx.x, t = threadIdx.x;
    const float* row = x + (long long)b*SEQ*DIM;
    __shared__ float red[256];
    float s = 0.f;
    for (int i = t; i < DIM; i += 256) s += row[i];
    red[t] = s; __syncthreads();
    for (int o = 128; o > 0; o >>= 1) { if (t < o) red[t] += red[t+o]; __syncthreads(); }
    float mu = red[0] / DIM; __syncthreads();
    float v = 0.f;
    for (int i = t; i < DIM; i += 256) { float d = row[i]-mu; v += d*d; }
    red[t] = v; __syncthreads();
    for (int o = 128; o > 0; o >>= 1) { if (t < o) red[t] += red[t+o]; __syncthreads(); }
    float inv = rsqrtf(red[0]/DIM + 1e-5f);
    for (int i = t; i < DIM; i += 256) out[b*DIM + i] = (row[i]-mu)*inv*g[i] + be[i];
}

static inline int nblk(long long n, int t) { return (int)((n + t - 1) / t); }

extern "C" void kernel_launch(void* const* d_in, const int* in_sizes, int n_in,
                              void* d_out, int out_size) {
    const float* img       = (const float*)d_in[0];
    const float* patch_W   = (const float*)d_in[1];
    const float* patch_b   = (const float*)d_in[2];
    const float* cls_token = (const float*)d_in[3];
    const float* rms_scale = (const float*)d_in[4];
    const float* Wq        = (const float*)d_in[5];
    const float* Wk        = (const float*)d_in[6];
    const float* Wv        = (const float*)d_in[7];
    const float* attn_W    = (const float*)d_in[8];
    const float* attn_b    = (const float*)d_in[9];
    const float* tWq       = (const float*)d_in[10];
    const float* tWk       = (const float*)d_in[11];
    const float* tWv       = (const float*)d_in[12];
    const float* ln_g      = (const float*)d_in[13];
    const float* ln_b      = (const float*)d_in[14];
    const float* head_W    = (const float*)d_in[15];
    const float* head_b    = (const float*)d_in[16];
    float* out = (float*)d_out;

    float *pxp,*px,*pqkv,*ps,*po,*pot,*py,*ptqkv,*pts,*pf,*pred,*pcls;
    cudaGetSymbolAddress((void**)&pxp,  g_xp);
    cudaGetSymbolAddress((void**)&px,   g_x);
    cudaGetSymbolAddress((void**)&pqkv, g_qkv);
    cudaGetSymbolAddress((void**)&ps,   g_sc);
    cudaGetSymbolAddress((void**)&po,   g_o);
    cudaGetSymbolAddress((void**)&pot,  g_ot);
    cudaGetSymbolAddress((void**)&py,   g_y);
    cudaGetSymbolAddress((void**)&ptqkv,g_tqkv);
    cudaGetSymbolAddress((void**)&pts,  g_ts);
    cudaGetSymbolAddress((void**)&pf,   g_fac);
    cudaGetSymbolAddress((void**)&pred, g_red);
    cudaGetSymbolAddress((void**)&pcls, g_cls);

    __nv_bfloat16 *path_h,*path_l,*xh,*xl,*qh,*ql,*kh,*kl,*ph,*pl,*oh,*ol;
    __nv_bfloat16 *yh,*yl,*tqh,*tql,*tkh,*tkl,*tsh,*tsl;
    __nv_bfloat16 *pwh,*pwl,*wAh,*wAl,*awh,*awl,*twAh,*twAl,*vth,*vtl,*tvth,*tvtl;
    cudaGetSymbolAddress((void**)&path_h, g_path_h); cudaGetSymbolAddress((void**)&path_l, g_path_l);
    cudaGetSymbolAddress((void**)&xh,  g_xh);  cudaGetSymbolAddress((void**)&xl,  g_xl);
    cudaGetSymbolAddress((void**)&qh,  g_qh);  cudaGetSymbolAddress((void**)&ql,  g_ql);
    cudaGetSymbolAddress((void**)&kh,  g_kh);  cudaGetSymbolAddress((void**)&kl,  g_kl);
    cudaGetSymbolAddress((void**)&ph,  g_ph);  cudaGetSymbolAddress((void**)&pl,  g_pl);
    cudaGetSymbolAddress((void**)&oh,  g_oh);  cudaGetSymbolAddress((void**)&ol,  g_ol);
    cudaGetSymbolAddress((void**)&yh,  g_yh);  cudaGetSymbolAddress((void**)&yl,  g_yl);
    cudaGetSymbolAddress((void**)&tqh, g_tqh); cudaGetSymbolAddress((void**)&tql, g_tql);
    cudaGetSymbolAddress((void**)&tkh, g_tkh); cudaGetSymbolAddress((void**)&tkl, g_tkl);
    cudaGetSymbolAddress((void**)&tsh, g_tsh); cudaGetSymbolAddress((void**)&tsl, g_tsl);
    cudaGetSymbolAddress((void**)&pwh,  g_pwh);  cudaGetSymbolAddress((void**)&pwl,  g_pwl);
    cudaGetSymbolAddress((void**)&wAh,  g_wAh);  cudaGetSymbolAddress((void**)&wAl,  g_wAl);
    cudaGetSymbolAddress((void**)&awh,  g_awh);  cudaGetSymbolAddress((void**)&awl,  g_awl);
    cudaGetSymbolAddress((void**)&twAh, g_twAh); cudaGetSymbolAddress((void**)&twAl, g_twAl);
    cudaGetSymbolAddress((void**)&vth,  g_vth);  cudaGetSymbolAddress((void**)&vtl,  g_vtl);
    cudaGetSymbolAddress((void**)&tvth, g_tvth); cudaGetSymbolAddress((void**)&tvtl, g_tvtl);

    const long long sQH  = (long long)SEQ*DIM;
    const long long sSSp = (long long)SEQ*SEQP;
    const long long sY   = (long long)CDIM*TDIM;
    const long long sTS  = (long long)CDIM*CDIM;
    const long long sW   = (long long)DIM*DIM;
    const long long sVT  = (long long)DIM*SEQP;
    const long long sTVT = (long long)TDIM*CDIM;
    const long long sTW  = (long long)TDIM*TDIM;
    const float scale1 = (float)(1.0/sqrt(512.0));
    const float scale2 = (float)(1.0/sqrt(1576.0));
    const float cc1 = (float)(-2.0*log2(10000.0)/512.0);
    const float cc2 = (float)(-2.0*log2(10000.0)/1576.0);
    dim3 tcb(32, 8);

    // ---- weight pre-conversion into combined buffers ----
    tconv<<<dim3(DIM/32, PK/32, 1), tcb>>>(patch_W, pwh, pwl, PK, DIM, PK, 0, 0);
    for (int l = 0; l < 2; l++) {
        const float* srcs[3] = {Wq, Wk, Wv};
        for (int w = 0; w < 3; w++) {
            tconv<<<dim3(16, 16, 8), tcb>>>(srcs[w] + (long long)l*8*sW,
                                            wAh + ((long long)l*24 + w*8)*sW,
                                            wAl + ((long long)l*24 + w*8)*sW,
                                            DIM, DIM, DIM, sW, sW);
        }
        const float* tsrcs[3] = {tWq, tWk, tWv};
        for (int w = 0; w < 3; w++) {
            tconv<<<dim3(50, 50, 1), tcb>>>(tsrcs[w] + (long long)l*sTW,
                                            twAh + ((long long)l*3 + w)*sTW,
                                            twAl + ((long long)l*3 + w)*sTW,
                                            TDIM, TDIM, TDIM, 0, 0);
        }
    }
    tconv<<<dim3(16, 16, 16), tcb>>>(attn_W, awh, awl, DIM, DIM, DIM, sW, sW);

    // ---- patch embedding ----
    patch_gather2<<<nblk((long long)BATCH*NPATCH*PK,256),256>>>(img, path_h, path_l);
    run_hgemm(path_h, path_l, pwh, pwl, patch_b, 0, pxp, 0, 0,
              BATCH*NPATCH, DIM, PK, PK, PK, DIM,
              P_NONE, P_NONE, 0, 0, 1, 1.f, 0);
    assemble_x_kernel<<<nblk((long long)BATCH*SEQ*DIM,256),256>>>(pxp, cls_token, px);

    for (int l = 0; l < 2; l++) {
        const float* scale_l = rms_scale + (long long)l*SEQ*DIM;

        // rmsnorm #1 (+split)
        rms_part_kernel<<<dim3(32,BATCH),256>>>(px, pred);
        rms_fin_kernel<<<1,256>>>(pred, pf);
        rms_apply2<<<nblk((long long)BATCH*SEQ*DIM/4,256),256>>>(px, pf, scale_l,
                                                                 (uint2*)xh, (uint2*)xl);

        // fused QKV, batch folded into M: M=1576, z = w*8+h (24 batches)
        // C layout [w][h][b][SEQ][DIM]
        run_hgemm(xh, xl, wAh + (long long)l*24*sW, wAl + (long long)l*24*sW, 0, 0, pqkv, 0, 0,
                  BATCH*SEQ, DIM, DIM, DIM, DIM, DIM,
                  P_NONE,
                  8, 8*sW, 8, 0LL, sW,            // B: (z/8)*8sW + (z%8)*sW
                  0, 8*sQH, 24, 1.f, 0);

        // v -> vT split [DIM][SEQP]  (v block at 128*sQH, 64 slices [h][b])
        tconv<<<dim3(16, 7, 64), tcb>>>(pqkv + 128*sQH, vth, vtl, SEQ, DIM, SEQP, sQH, sVT);

        // RoPE -> split q,k (q slices 0..63, k slices 64..127; order [h][b], per-slice identical)
        rope2<<<nblk((long long)64*SEQ*(DIM/2),256),256>>>(pqkv, pqkv + 64*sQH,
                                                           qh, ql, kh, kl, 64, SEQ, DIM, cc1);

        // scores (per-slice)
        run_hgemm(qh, ql, kh, kl, 0, 0, ps, 0, 0,
                  SEQ, SEQ, DIM, DIM, DIM, SEQP,
                  P_PLAIN(sQH), P_PLAIN(sQH), 0, sSSp, 64, scale1, 0);
        softmax2<<<nblk((long long)64*SEQ*32,256),256>>>(ps, ph, pl, 64*SEQ, SEQ, SEQP);

        // o = p @ v (epilogue emits split oh/ol)
        run_hgemm(ph, pl, vth, vtl, 0, 0, po, oh, ol,
                  SEQ, DIM, SEQP, SEQP, SEQP, DIM,
                  P_PLAIN(sSSp), P_PLAIN(sVT), 0, sQH, 64, 1.f, 0);

        // proj partials, batch folded into M: M=1576, z=h (8 batches)
        run_hgemm(oh, ol, awh + (long long)l*8*sW, awl + (long long)l*8*sW, 0, 0, pot, 0, 0,
                  BATCH*SEQ, DIM, DIM, DIM, DIM, DIM,
                  P_PLAIN(8*sQH), P_PLAIN(sW), 0, 8*sQH, 8, 1.f, 0);
        attn_reduce_kernel<<<nblk((long long)BATCH*SEQ*DIM/4,256),256>>>(pot, attn_b + l*DIM, px);

        // rmsnorm #2 (+split)
        rms_part_kernel<<<dim3(32,BATCH),256>>>(px, pred);
        rms_fin_kernel<<<1,256>>>(pred, pf);
        rms_apply2<<<nblk((long long)BATCH*SEQ*DIM/4,256),256>>>(px, pf, scale_l,
                                                                 (uint2*)xh, (uint2*)xl);

        // token-mixing
        x_to_y2<<<nblk((long long)BATCH*CDIM*TDIM,256),256>>>(px, py, yh, yl);

        // fused token QKV, batch folded into M: M=512, z=w (3 batches), C [w][b][64][1576]
        run_hgemm(yh, yl, twAh + (long long)l*3*sTW, twAl + (long long)l*3*sTW, 0, 0, ptqkv, 0, 0,
                  BATCH*CDIM, TDIM, TDIM, TDIM, TDIM, TDIM,
                  P_NONE, P_PLAIN(sTW), 0, 8*sY, 3, 1.f, 0);

        // tv -> tvT split
        tconv<<<dim3(50, 2, 8), tcb>>>(ptqkv + 16*sY, tvth, tvtl, CDIM, TDIM, CDIM, sY, sTVT);

        // RoPE -> split tq,tk
        rope2<<<nblk((long long)BATCH*CDIM*(TDIM/2),256),256>>>(ptqkv, ptqkv + 8*sY,
                                                                 tqh, tql, tkh, tkl,
                                                                 BATCH, CDIM, TDIM, cc2);

        // token scores
        run_hgemm(tqh, tql, tkh, tkl, 0, 0, pts, 0, 0,
                  CDIM, CDIM, TDIM, TDIM, TDIM, CDIM,
                  P_PLAIN(sY), P_PLAIN(sY), 0, sTS, BATCH, scale2, 0);
        softmax2<<<nblk((long long)BATCH*CDIM*32,256),256>>>(pts, tsh, tsl,
                                                             BATCH*CDIM, CDIM, CDIM);

        // y += p @ tv
        run_hgemm(tsh, tsl, tvth, tvtl, 0, py, py, 0, 0,
                  CDIM, TDIM, CDIM, CDIM, CDIM, TDIM,
                  P_PLAIN(sTS), P_PLAIN(sTVT), sY, sY, BATCH, 1.f, 1);

        y_to_x_kernel<<<nblk((long long)BATCH*SEQ*DIM,256),256>>>(py, px);
    }

    // ---- final: cls layernorm + head ----
    cls_ln_kernel<<<BATCH,256>>>(px, ln_g, ln_b, pcls);
    {
        dim3 grid((NCLS+31)/32, 1, 1);
        sgemm_s<<<grid, 64>>>(pcls, head_W, head_b, out, BATCH, NCLS, DIM, DIM, NCLS, NCLS);
    }
}